// round 9
// baseline (speedup 1.0000x reference)
#include <cuda_runtime.h>

#define NDIM   2048
#define TILE   128
#define NTH    256

// ---------------------------------------------------------------------------
// fast activations (accuracy ~1e-6 rel, far inside the 1e-3 tolerance)
// ---------------------------------------------------------------------------
__device__ __forceinline__ float sigmoid_f(float v) {
    float e = __expf(-v);                 // +inf for very negative v -> result 0 (correct limit)
    return __fdividef(1.0f, 1.0f + e);
}
__device__ __forceinline__ float tanh_f(float v) {
    v = fminf(fmaxf(v, -20.0f), 20.0f);   // keep __expf finite
    float e = __expf(-2.0f * v);
    return __fdividef(1.0f - e, 1.0f + e);
}

// ---------------------------------------------------------------------------
// Fused kernel: feature build -> LSTM gates (i,g,o) -> MLP head -> updates
// one CTA handles TILE=128 consecutive rows; grid = 262144/128 = 2048
// ---------------------------------------------------------------------------
__global__ __launch_bounds__(NTH, 1)
void ps_lstm_kernel(
    const float* __restrict__ x,   const float* __restrict__ x1,  const float* __restrict__ x2,
    const float* __restrict__ z1,  const float* __restrict__ z2,
    const float* __restrict__ x1E, const float* __restrict__ x2E,
    const float* __restrict__ z1E, const float* __restrict__ z2E,
    const float* __restrict__ muB, const float* __restrict__ lb,  const float* __restrict__ ub,
    const float* __restrict__ W_ih, const float* __restrict__ b_ih, const float* __restrict__ b_hh,
    const float* __restrict__ W1,  const float* __restrict__ b1,
    const float* __restrict__ W2,  const float* __restrict__ b2,
    float* __restrict__ out)
{
    extern __shared__ float sm[];
    float* sWih  = sm;                    // [16][384]  transposed i/g/o rows of W_ih (k-padded)
    float* sBias = sWih  + 16 * 384;      // [384]      b_ih + b_hh for i/g/o rows
    float* sW1   = sBias + 384;           // [128][128] sW1[j*128+k] = W1[k*128+j] (W1^T)
    float* sb1   = sW1   + 128 * 128;     // [128]
    float* sW2   = sb1   + 128;           // [128]
    float* sH    = sW2   + 128;           // [TILE][128] hidden states
    float* sP    = sH    + 128 * 128;     // [TILE] step sizes

    const int tid = threadIdx.x;

    // ---- load weights into shared -----------------------------------------
    // gate index jj in [0,384): jj<128 -> i-gate row jj; else g/o rows jj+128
    for (int jj = tid; jj < 384; jj += NTH) {
        int row = (jj < 128) ? jj : jj + 128;
        sBias[jj] = b_ih[row] + b_hh[row];
        #pragma unroll
        for (int k = 0; k < 15; ++k)
            sWih[k * 384 + jj] = W_ih[row * 15 + k];
        sWih[15 * 384 + jj] = 0.0f;
    }
    for (int i = tid; i < 128 * 128; i += NTH) {
        int k = i >> 7, j = i & 127;
        sW1[j * 128 + k] = W1[i];          // coalesced gmem read, conflict-free smem write
    }
    if (tid < 128) { sb1[tid] = b1[tid]; sW2[tid] = W2[tid]; }
    __syncthreads();

    const int warp = tid >> 5, lane = tid & 31;
    const int rowbase = blockIdx.x * TILE;

    // ---- Stage A: features + gate GEMM + activations -> sH ----------------
    // each warp: 16 rows, 2 rows per pass. lane computes gates j = lane+32q.
    for (int pass = 0; pass < 8; ++pass) {
        const int lr0 = warp * 16 + pass * 2;
        float f[2][15];
        #pragma unroll
        for (int r = 0; r < 2; ++r) {
            int row = rowbase + lr0 + r;
            float mu  = muB[row >> 11];
            float xv  = x[row],  x1v = x1[row], x2v = x2[row];
            float z1v = z1[row], z2v = z2[row];
            float z1m = (z1v + mu <= 0.0f) ? 0.0f : z1v;
            float z2m = (z2v + mu <= 0.0f) ? 0.0f : z2v;
            float iD1 = fminf(fmaxf(__fdividef(z1m + mu, x1v + mu + 1e-12f), 0.0f), 100.0f);
            float iD2 = fminf(fmaxf(__fdividef(z2m + mu, x2v + mu + 1e-12f), 0.0f), 100.0f);
            f[r][0] = xv;  f[r][1] = x1v; f[r][2] = x2v; f[r][3] = z1m; f[r][4] = z2m;
            f[r][5] = xv;  f[r][6] = z1m; f[r][7] = z2m;            // grads
            f[r][8] = x1E[row]; f[r][9]  = x2E[row];
            f[r][10] = z1E[row]; f[r][11] = z2E[row];
            f[r][12] = mu; f[r][13] = iD1; f[r][14] = iD2;
        }

        float acc0[12], acc1[12];
        #pragma unroll
        for (int m = 0; m < 12; ++m) {
            float bb = sBias[lane + 32 * m];
            acc0[m] = bb; acc1[m] = bb;
        }
        #pragma unroll
        for (int k = 0; k < 15; ++k) {
            #pragma unroll
            for (int m = 0; m < 12; ++m) {
                float w = sWih[k * 384 + lane + 32 * m];    // conflict-free
                acc0[m] = fmaf(w, f[0][k], acc0[m]);
                acc1[m] = fmaf(w, f[1][k], acc1[m]);
            }
        }
        // m 0..3: i-gate, 4..7: g-gate, 8..11: o-gate  (same j = lane+32q)
        #pragma unroll
        for (int q = 0; q < 4; ++q) {
            float c0 = sigmoid_f(acc0[q]) * tanh_f(acc0[q + 4]);
            sH[lr0 * 128 + lane + 32 * q]       = sigmoid_f(acc0[q + 8]) * tanh_f(c0);
            float c1 = sigmoid_f(acc1[q]) * tanh_f(acc1[q + 4]);
            sH[(lr0 + 1) * 128 + lane + 32 * q] = sigmoid_f(acc1[q + 8]) * tanh_f(c1);
        }
    }
    __syncthreads();

    // ---- Stage B: a = relu(W1 h + b1); p = |a . W2 + b2| -> sP ------------
    // lane owns output channels k = 4*lane..4*lane+3; 8 rows per pass.
    {
        const float  b2v = b2[0];
        const float4 bv  = *(const float4*)(sb1 + 4 * lane);
        const float4 w2v = *(const float4*)(sW2 + 4 * lane);
        for (int pass = 0; pass < 2; ++pass) {
            const int rbase = warp * 16 + pass * 8;
            float acc[8][4];
            #pragma unroll
            for (int r = 0; r < 8; ++r) {
                acc[r][0] = bv.x; acc[r][1] = bv.y; acc[r][2] = bv.z; acc[r][3] = bv.w;
            }
            for (int j4 = 0; j4 < 32; ++j4) {
                const float4 wv0 = *(const float4*)(sW1 + (4 * j4 + 0) * 128 + 4 * lane);
                const float4 wv1 = *(const float4*)(sW1 + (4 * j4 + 1) * 128 + 4 * lane);
                const float4 wv2 = *(const float4*)(sW1 + (4 * j4 + 2) * 128 + 4 * lane);
                const float4 wv3 = *(const float4*)(sW1 + (4 * j4 + 3) * 128 + 4 * lane);
                #pragma unroll
                for (int r = 0; r < 8; ++r) {
                    const float4 hv = *(const float4*)(sH + (rbase + r) * 128 + 4 * j4); // broadcast
                    acc[r][0] = fmaf(wv0.x, hv.x, fmaf(wv1.x, hv.y, fmaf(wv2.x, hv.z, fmaf(wv3.x, hv.w, acc[r][0]))));
                    acc[r][1] = fmaf(wv0.y, hv.x, fmaf(wv1.y, hv.y, fmaf(wv2.y, hv.z, fmaf(wv3.y, hv.w, acc[r][1]))));
                    acc[r][2] = fmaf(wv0.z, hv.x, fmaf(wv1.z, hv.y, fmaf(wv2.z, hv.z, fmaf(wv3.z, hv.w, acc[r][2]))));
                    acc[r][3] = fmaf(wv0.w, hv.x, fmaf(wv1.w, hv.y, fmaf(wv2.w, hv.z, fmaf(wv3.w, hv.w, acc[r][3]))));
                }
            }
            #pragma unroll
            for (int r = 0; r < 8; ++r) {
                float s = fmaxf(acc[r][0], 0.0f) * w2v.x + fmaxf(acc[r][1], 0.0f) * w2v.y
                        + fmaxf(acc[r][2], 0.0f) * w2v.z + fmaxf(acc[r][3], 0.0f) * w2v.w;
                #pragma unroll
                for (int off = 16; off; off >>= 1)
                    s += __shfl_xor_sync(0xffffffffu, s, off);
                if (lane == 0) sP[rbase + r] = fabsf(s + b2v);
            }
        }
    }
    __syncthreads();

    // ---- Stage C: elementwise updates + output ----------------------------
    if (tid < TILE) {
        const int row = rowbase + tid;
        const int b = row >> 11, n = row & (NDIM - 1);
        float mu  = muB[b];
        float xv  = x[row],  x1v = x1[row], x2v = x2[row];
        float z1v = z1[row], z2v = z2[row];
        float z1m = (z1v + mu <= 0.0f) ? 0.0f : z1v;
        float z2m = (z2v + mu <= 0.0f) ? 0.0f : z2v;
        float iD1 = fminf(fmaxf(__fdividef(z1m + mu, x1v + mu + 1e-12f), 0.0f), 100.0f);
        float iD2 = fminf(fmaxf(__fdividef(z2m + mu, x2v + mu + 1e-12f), 0.0f), 100.0f);
        float p  = sP[tid];
        float d  = -p * xv;                       // d_x = -p_x * grad_x
        float xn = xv + d;
        float z1o = z1m - iD1 * (d + z1m);        // z1 - invD1*(-p*x + z1)
        float z2o = z2m - iD2 * (-d + z2m);       // z2 - invD2*( p*x + z2)
        float x1o = xn - lb[row];                 // has_lb is all-true by construction
        float x2o = ub[row] - xn;                 // has_ub is all-true by construction
        size_t ob = (size_t)b * (5 * NDIM) + n;
        out[ob]            = xn;
        out[ob +     NDIM] = x1o;
        out[ob + 2 * NDIM] = x2o;
        out[ob + 3 * NDIM] = z1o;
        out[ob + 4 * NDIM] = z2o;
    }
}

// ---------------------------------------------------------------------------
// metadata order:
//  0 x  1 x1  2 x2  3 z1  4 z2  5 x1E  6 x2E  7 z1E  8 z2E  9 muB  10 lb 11 ub
// 12 has_lb 13 has_ub 14 W_ih 15 W_hh(unused) 16 b_ih 17 b_hh 18 W1 19 b1 20 W2 21 b2
// ---------------------------------------------------------------------------
extern "C" void kernel_launch(void* const* d_in, const int* in_sizes, int n_in,
                              void* d_out, int out_size) {
    (void)in_sizes; (void)n_in; (void)out_size;
    const float* x    = (const float*)d_in[0];
    const float* x1   = (const float*)d_in[1];
    const float* x2   = (const float*)d_in[2];
    const float* z1   = (const float*)d_in[3];
    const float* z2   = (const float*)d_in[4];
    const float* x1E  = (const float*)d_in[5];
    const float* x2E  = (const float*)d_in[6];
    const float* z1E  = (const float*)d_in[7];
    const float* z2E  = (const float*)d_in[8];
    const float* muB  = (const float*)d_in[9];
    const float* lb   = (const float*)d_in[10];
    const float* ub   = (const float*)d_in[11];
    const float* W_ih = (const float*)d_in[14];
    const float* b_ih = (const float*)d_in[16];
    const float* b_hh = (const float*)d_in[17];
    const float* W1   = (const float*)d_in[18];
    const float* b1   = (const float*)d_in[19];
    const float* W2   = (const float*)d_in[20];
    const float* b2   = (const float*)d_in[21];

    const size_t smem = (size_t)(16*384 + 384 + 128*128 + 128 + 128 + 128*128 + 128) * sizeof(float);
    cudaFuncSetAttribute(ps_lstm_kernel, cudaFuncAttributeMaxDynamicSharedMemorySize, (int)smem);

    const int rows  = 128 * NDIM;          // 262144
    const int grid  = rows / TILE;         // 2048
    ps_lstm_kernel<<<grid, NTH, smem>>>(
        x, x1, x2, z1, z2, x1E, x2E, z1E, z2E, muB, lb, ub,
        W_ih, b_ih, b_hh, W1, b1, W2, b2, (float*)d_out);
}

// round 11
// speedup vs baseline: 2.2172x; 2.2172x over previous
#include <cuda_runtime.h>
#include <cstdint>

#define NDIM   2048
#define TILE   128
#define NTH    256

// ---------------------------------------------------------------------------
// tcgen05 is an architecture-SPECIFIC ('a') feature set. The harness also
// compiles a plain compute_103 PTX pass where these instructions don't exist,
// so every tcgen05 usage is gated on the arch-specific feature macros and a
// plain-FMA fallback is provided for the PTX pass. The sm_103a cubin (what
// actually runs on GB300) takes the tcgen05 path.
// ---------------------------------------------------------------------------
#if defined(__CUDA_ARCH__) && (defined(__CUDA_ARCH_FEAT_SM103_ALL) || \
    defined(__CUDA_ARCH_FEAT_SM100_ALL) || defined(__CUDA_ARCH_SPECIFIC__))
#define USE_TCGEN05 1
#else
#define USE_TCGEN05 0
#endif

// ---------------------------------------------------------------------------
// PTX helpers
// ---------------------------------------------------------------------------
__device__ __forceinline__ uint32_t elect_one_pred() {
    uint32_t pred;
    asm volatile("{\n\t.reg .pred p;\n\telect.sync _|p, 0xFFFFFFFF;\n\tselp.b32 %0, 1, 0, p;\n\t}"
                 : "=r"(pred));
    return pred;
}
__device__ __forceinline__ uint32_t smem_u32(const void* p) {
    uint32_t a;
    asm("{ .reg .u64 t; cvta.to.shared.u64 t, %1; cvt.u32.u64 %0, t; }" : "=r"(a) : "l"(p));
    return a;
}

#define MBARRIER_INIT(mbar, count) \
    asm volatile("mbarrier.init.shared.b64 [%0], %1;" \
                 :: "r"((uint32_t)(mbar)), "r"((uint32_t)(count)) : "memory")
#define MBARRIER_INVAL(mbar) \
    asm volatile("mbarrier.inval.shared.b64 [%0];" :: "r"((uint32_t)(mbar)) : "memory")
#define MBARRIER_WAIT_PARITY(mbar, parity) do { \
    uint32_t _m = (uint32_t)(mbar); uint32_t _p = (uint32_t)(parity); uint32_t _d; \
    asm volatile("{\n\t.reg .pred p;\n\t" \
        "mbarrier.try_wait.parity.acquire.cta.shared::cta.b64 p, [%1], %2;\n\t" \
        "selp.b32 %0, 1, 0, p;\n\t}" : "=r"(_d) : "r"(_m), "r"(_p) : "memory"); \
    if (!_d) { \
        asm volatile("{\n\t.reg .pred P1;\n\t" \
            "WL_%=:\n\t" \
            "mbarrier.try_wait.parity.acquire.cta.shared::cta.b64 P1, [%0], %1, 0x989680;\n\t" \
            "@P1 bra.uni WD_%=;\n\t" \
            "bra.uni WL_%=;\n\t" \
            "WD_%=:\n\t}" :: "r"(_m), "r"(_p) : "memory"); \
    } } while (0)

#define FENCE_PROXY_ASYNC()    asm volatile("fence.proxy.async.shared::cta;" ::: "memory")

#if USE_TCGEN05
#define TCGEN05_ALLOC(smem_result_addr, nCols) \
    asm volatile("tcgen05.alloc.cta_group::1.sync.aligned.shared::cta.b32 [%0], %1;" \
                 :: "r"((uint32_t)(smem_result_addr)), "r"((uint32_t)(nCols)) : "memory")
#define TCGEN05_DEALLOC(tmem_addr, nCols) \
    asm volatile("tcgen05.dealloc.cta_group::1.sync.aligned.b32 %0, %1;" \
                 :: "r"(tmem_addr), "r"((uint32_t)(nCols)))
#define TCGEN05_RELINQ() \
    asm volatile("tcgen05.relinquish_alloc_permit.cta_group::1.sync.aligned;")
#define TCGEN05_COMMIT(mbar) \
    asm volatile("tcgen05.commit.cta_group::1.mbarrier::arrive::one.shared::cluster.b64 [%0];" \
                 :: "r"((uint32_t)(mbar)) : "memory")
#define TCGEN05_FENCE_AFTER()  asm volatile("tcgen05.fence::after_thread_sync;" ::: "memory")
#define TCGEN05_FENCE_BEFORE() asm volatile("tcgen05.fence::before_thread_sync;" ::: "memory")
#define TCGEN05_WAIT_LD()      asm volatile("tcgen05.wait::ld.sync.aligned;" ::: "memory")

#define TCGEN05_LD_32X32B_X32(r, tmem_addr) \
    asm volatile("tcgen05.ld.sync.aligned.32x32b.x32.b32 " \
        "{%0, %1, %2, %3, %4, %5, %6, %7, %8, %9, %10, %11, %12, %13, %14, %15, " \
        " %16, %17, %18, %19, %20, %21, %22, %23, %24, %25, %26, %27, %28, %29, %30, %31}, [%32];" \
        : "=r"((r)[0]),  "=r"((r)[1]),  "=r"((r)[2]),  "=r"((r)[3]), \
          "=r"((r)[4]),  "=r"((r)[5]),  "=r"((r)[6]),  "=r"((r)[7]), \
          "=r"((r)[8]),  "=r"((r)[9]),  "=r"((r)[10]), "=r"((r)[11]), \
          "=r"((r)[12]), "=r"((r)[13]), "=r"((r)[14]), "=r"((r)[15]), \
          "=r"((r)[16]), "=r"((r)[17]), "=r"((r)[18]), "=r"((r)[19]), \
          "=r"((r)[20]), "=r"((r)[21]), "=r"((r)[22]), "=r"((r)[23]), \
          "=r"((r)[24]), "=r"((r)[25]), "=r"((r)[26]), "=r"((r)[27]), \
          "=r"((r)[28]), "=r"((r)[29]), "=r"((r)[30]), "=r"((r)[31]) \
        : "r"(tmem_addr))

// SS-form tf32 MMA, cta_group::1. fp32 data in SMEM; HW rounds to tf32.
__device__ __forceinline__ void mma_tf32_ss(uint32_t d_tmem, uint64_t a_desc, uint64_t b_desc,
                                            uint32_t idesc, bool accum) {
    uint32_t en = accum ? 1u : 0u;
    asm volatile("{\n\t.reg .pred p;\n\tsetp.ne.u32 p, %5, 0;\n\t"
                 "tcgen05.mma.cta_group::1.kind::tf32 [%0], %1, %2, %3, {%4, %4, %4, %4}, p;\n\t}"
                 :: "r"(d_tmem), "l"(a_desc), "l"(b_desc), "r"(idesc), "r"(0u), "r"(en)
                 : "memory");
}
#endif // USE_TCGEN05

// SW128 K-major SMEM descriptor base: layout=SW128(2), version=1, SBO=64, LBO=1
static constexpr uint64_t DESC_BASE_SW128 =
    (uint64_t(2) << 61) | (uint64_t(1) << 46) | (uint64_t(64) << 32) | (uint64_t(1) << 16);

// idesc: D=F32, A=TF32, B=TF32, N=128, M=128, K-major both
#define IDESC_TF32 0x8200910u

// ---------------------------------------------------------------------------
// fast activations: tanh.approx.f32 (single MUFU), sigmoid via tanh identity
// ---------------------------------------------------------------------------
__device__ __forceinline__ float tanh_fast(float v) {
    float r;
    asm("tanh.approx.f32 %0, %1;" : "=f"(r) : "f"(v));
    return r;
}
__device__ __forceinline__ float sigmoid_fast(float v) {
    return fmaf(tanh_fast(0.5f * v), 0.5f, 0.5f);
}

// byte offset (incl. SW128 swizzle) for K-major blocked-atom layout:
// 128 rows x 128 fp32; atom = 8 rows x 32 fp32 (1024B); 16 atom-rows x 4 atom-cols
__device__ __forceinline__ uint32_t kmaj_off(int row, int col) {
    uint32_t b = (uint32_t)((row >> 3) + (col >> 5) * 16) * 1024u
               + (uint32_t)(row & 7) * 128u + (uint32_t)(col & 31) * 4u;
    return b ^ ((b >> 3) & 0x70);
}

// ---- shared memory layout (bytes, from 1024-aligned base) -----------------
#define OFF_TMEMPTR 0
#define OFF_MBAR    8
#define OFF_BIAS    16                       // 384 f
#define OFF_B1      (OFF_BIAS + 384*4)       // 128 f
#define OFF_W2      (OFF_B1 + 128*4)         // 128 f
#define OFF_PART    (OFF_W2 + 128*4)         // 256 f
#define OFF_WIH     (OFF_PART + 256*4)       // 16*384 f -> ends 28176
#define OFF_W1      28672                    // 64 KB (1024-aligned)
#define OFF_H       94208                    // 64 KB (1024-aligned)
#define SMEM_BYTES  (159744 + 1024)          // + alignment slack

__global__ __launch_bounds__(NTH, 1)
void ps_lstm_kernel(
    const float* __restrict__ x,   const float* __restrict__ x1,  const float* __restrict__ x2,
    const float* __restrict__ z1,  const float* __restrict__ z2,
    const float* __restrict__ x1E, const float* __restrict__ x2E,
    const float* __restrict__ z1E, const float* __restrict__ z2E,
    const float* __restrict__ muB, const float* __restrict__ lb,  const float* __restrict__ ub,
    const float* __restrict__ W_ih, const float* __restrict__ b_ih, const float* __restrict__ b_hh,
    const float* __restrict__ W1,  const float* __restrict__ b1,
    const float* __restrict__ W2,  const float* __restrict__ b2,
    float* __restrict__ out)
{
    extern __shared__ unsigned char smraw[];
    const uint32_t rawa = smem_u32(smraw);
    const uint32_t base = (rawa + 1023u) & ~1023u;
    unsigned char* smb = smraw + (base - rawa);

    float* sBias = (float*)(smb + OFF_BIAS);
    float* sb1   = (float*)(smb + OFF_B1);
    float* sW2   = (float*)(smb + OFF_W2);
    float* sPart = (float*)(smb + OFF_PART);
    float* sWih  = (float*)(smb + OFF_WIH);

    const int tid  = threadIdx.x;
    const int warp = tid >> 5, lane = tid & 31;

    // ---- load weights -----------------------------------------------------
    for (int jj = tid; jj < 384; jj += NTH) {
        int row = (jj < 128) ? jj : jj + 128;      // i-gate rows, then g/o rows
        sBias[jj] = b_ih[row] + b_hh[row];
        #pragma unroll
        for (int k = 0; k < 15; ++k)
            sWih[k * 384 + jj] = W_ih[row * 15 + k];
        sWih[15 * 384 + jj] = 0.0f;
    }
    // W1 -> swizzled K-major blocked layout (row = out channel = N, col = K)
    for (int i = tid; i < 128 * 128; i += NTH) {
        int r = i >> 7, c = i & 127;
        *(float*)(smb + OFF_W1 + kmaj_off(r, c)) = W1[i];
    }
    if (tid < 128) { sb1[tid] = b1[tid]; sW2[tid] = W2[tid]; }

#if USE_TCGEN05
    if (warp == 0) { TCGEN05_ALLOC(base + OFF_TMEMPTR, 128); TCGEN05_RELINQ(); }
    if (tid == 0)  { MBARRIER_INIT(base + OFF_MBAR, 1); }
#endif
    __syncthreads();

#if USE_TCGEN05
    uint32_t tmem;
    asm volatile("ld.shared.b32 %0, [%1];" : "=r"(tmem) : "r"(base + OFF_TMEMPTR));
#endif

    const int rowbase = blockIdx.x * TILE;

    // ---- Stage A: features + gate GEMM + activations -> swizzled sH -------
    for (int pass = 0; pass < 8; ++pass) {
        const int lr0 = warp * 16 + pass * 2;
        float f[2][15];
        #pragma unroll
        for (int r = 0; r < 2; ++r) {
            int row = rowbase + lr0 + r;
            float mu  = muB[row >> 11];
            float xv  = x[row],  x1v = x1[row], x2v = x2[row];
            float z1v = z1[row], z2v = z2[row];
            float z1m = (z1v + mu <= 0.0f) ? 0.0f : z1v;
            float z2m = (z2v + mu <= 0.0f) ? 0.0f : z2v;
            float iD1 = fminf(fmaxf(__fdividef(z1m + mu, x1v + mu + 1e-12f), 0.0f), 100.0f);
            float iD2 = fminf(fmaxf(__fdividef(z2m + mu, x2v + mu + 1e-12f), 0.0f), 100.0f);
            f[r][0] = xv;  f[r][1] = x1v; f[r][2] = x2v; f[r][3] = z1m; f[r][4] = z2m;
            f[r][5] = xv;  f[r][6] = z1m; f[r][7] = z2m;
            f[r][8] = x1E[row]; f[r][9]  = x2E[row];
            f[r][10] = z1E[row]; f[r][11] = z2E[row];
            f[r][12] = mu; f[r][13] = iD1; f[r][14] = iD2;
        }

        float acc0[12], acc1[12];
        #pragma unroll
        for (int m = 0; m < 12; ++m) {
            float bb = sBias[lane + 32 * m];
            acc0[m] = bb; acc1[m] = bb;
        }
        #pragma unroll
        for (int k = 0; k < 15; ++k) {
            #pragma unroll
            for (int m = 0; m < 12; ++m) {
                float w = sWih[k * 384 + lane + 32 * m];
                acc0[m] = fmaf(w, f[0][k], acc0[m]);
                acc1[m] = fmaf(w, f[1][k], acc1[m]);
            }
        }
        // m 0..3: i-gate, 4..7: g-gate, 8..11: o-gate (channel j = lane+32q)
        const uint32_t rp0 = (uint32_t)((lr0 >> 3)) * 1024u + (uint32_t)(lr0 & 7) * 128u;
        const uint32_t rp1 = (uint32_t)(((lr0 + 1) >> 3)) * 1024u + (uint32_t)((lr0 + 1) & 7) * 128u;
        #pragma unroll
        for (int q = 0; q < 4; ++q) {
            float c0 = sigmoid_fast(acc0[q]) * tanh_fast(acc0[q + 4]);
            float h0 = sigmoid_fast(acc0[q + 8]) * tanh_fast(c0);
            float c1 = sigmoid_fast(acc1[q]) * tanh_fast(acc1[q + 4]);
            float h1 = sigmoid_fast(acc1[q + 8]) * tanh_fast(c1);
            uint32_t cp = (uint32_t)q * 16384u + (uint32_t)lane * 4u;
            uint32_t b0 = rp0 + cp; b0 ^= (b0 >> 3) & 0x70;
            uint32_t b1o = rp1 + cp; b1o ^= (b1o >> 3) & 0x70;
            *(float*)(smb + OFF_H + b0)  = h0;
            *(float*)(smb + OFF_H + b1o) = h1;
        }
    }

    FENCE_PROXY_ASYNC();           // order generic SMEM writes before async-proxy MMA reads
    __syncthreads();

#if USE_TCGEN05
    // ---- Stage B: tcgen05 tf32 SS MMA  D[128,128] = H @ W1^T --------------
    if (warp == 0) {
        const uint64_t ad = DESC_BASE_SW128 | ((uint64_t)((base + OFF_H)  >> 4) & 0x3FFF);
        const uint64_t bd = DESC_BASE_SW128 | ((uint64_t)((base + OFF_W1) >> 4) & 0x3FFF);
        if (elect_one_pred()) {
            #pragma unroll
            for (int s = 0; s < 16; ++s) {
                uint32_t off = (uint32_t)(s >> 2) * 1024u + (uint32_t)(s & 3) * 2u;
                mma_tf32_ss(tmem, ad + off, bd + off, IDESC_TF32, s > 0);
            }
            TCGEN05_COMMIT(base + OFF_MBAR);
        }
    }

    MBARRIER_WAIT_PARITY(base + OFF_MBAR, 0);
    TCGEN05_FENCE_AFTER();

    // ---- Epilogue: relu(D + b1) . W2, per-row partial sums ----------------
    {
        const int sp = warp & 3;          // implicit TMEM subpartition (rows sp*32..+31)
        const int ch = warp >> 2;         // column half
        const int cb = ch * 64;
        uint32_t d0[32], d1[32];
        TCGEN05_LD_32X32B_X32(d0, tmem + cb);
        TCGEN05_LD_32X32B_X32(d1, tmem + cb + 32);
        TCGEN05_WAIT_LD();
        float s = 0.0f;
        #pragma unroll
        for (int r = 0; r < 32; ++r) {
            s = fmaf(fmaxf(__uint_as_float(d0[r]) + sb1[cb + r], 0.0f), sW2[cb + r], s);
            s = fmaf(fmaxf(__uint_as_float(d1[r]) + sb1[cb + 32 + r], 0.0f), sW2[cb + 32 + r], s);
        }
        TCGEN05_FENCE_BEFORE();
        sPart[ch * 128 + sp * 32 + lane] = s;
    }
    __syncthreads();
#else
    // ---- Stage B fallback (compute_103 PTX pass only): plain FMA ----------
    // thread t: row r = t>>1, channel half hf = t&1 (64 channels), swizzled LDS.
    {
        const int r  = tid >> 1;
        const int hf = tid & 1;
        float s = 0.0f;
        for (int j = hf * 64; j < hf * 64 + 64; ++j) {
            float acc = sb1[j];
            #pragma unroll 8
            for (int k4 = 0; k4 < 32; ++k4) {
                const float4 hv = *(const float4*)(smb + OFF_H  + kmaj_off(r, 4 * k4));
                const float4 wv = *(const float4*)(smb + OFF_W1 + kmaj_off(j, 4 * k4));
                acc = fmaf(hv.x, wv.x, fmaf(hv.y, wv.y, fmaf(hv.z, wv.z, fmaf(hv.w, wv.w, acc))));
            }
            s = fmaf(fmaxf(acc, 0.0f), sW2[j], s);
        }
        sPart[hf * 128 + r] = s;
    }
    __syncthreads();
#endif

    // ---- Stage C: elementwise updates + output ----------------------------
    if (tid < TILE) {
        const int row = rowbase + tid;
        const int b = row >> 11, n = row & (NDIM - 1);
        float mu  = muB[b];
        float xv  = x[row],  x1v = x1[row], x2v = x2[row];
        float z1v = z1[row], z2v = z2[row];
        float z1m = (z1v + mu <= 0.0f) ? 0.0f : z1v;
        float z2m = (z2v + mu <= 0.0f) ? 0.0f : z2v;
        float iD1 = fminf(fmaxf(__fdividef(z1m + mu, x1v + mu + 1e-12f), 0.0f), 100.0f);
        float iD2 = fminf(fmaxf(__fdividef(z2m + mu, x2v + mu + 1e-12f), 0.0f), 100.0f);
        float p  = fabsf(sPart[tid] + sPart[128 + tid] + b2[0]);
        float d  = -p * xv;
        float xn = xv + d;
        float z1o = z1m - iD1 * (d + z1m);
        float z2o = z2m - iD2 * (-d + z2m);
        float x1o = xn - lb[row];
        float x2o = ub[row] - xn;
        size_t ob = (size_t)b * (5 * NDIM) + n;
        out[ob]            = xn;
        out[ob +     NDIM] = x1o;
        out[ob + 2 * NDIM] = x2o;
        out[ob + 3 * NDIM] = z1o;
        out[ob + 4 * NDIM] = z2o;
    }

#if USE_TCGEN05
    if (tid == 0) MBARRIER_INVAL(base + OFF_MBAR);
    if (warp == 0) TCGEN05_DEALLOC(tmem, 128);
#endif
}

// ---------------------------------------------------------------------------
// metadata order:
//  0 x  1 x1  2 x2  3 z1  4 z2  5 x1E  6 x2E  7 z1E  8 z2E  9 muB  10 lb 11 ub
// 12 has_lb 13 has_ub 14 W_ih 15 W_hh(unused) 16 b_ih 17 b_hh 18 W1 19 b1 20 W2 21 b2
// ---------------------------------------------------------------------------
extern "C" void kernel_launch(void* const* d_in, const int* in_sizes, int n_in,
                              void* d_out, int out_size) {
    (void)in_sizes; (void)n_in; (void)out_size;
    const float* x    = (const float*)d_in[0];
    const float* x1   = (const float*)d_in[1];
    const float* x2   = (const float*)d_in[2];
    const float* z1   = (const float*)d_in[3];
    const float* z2   = (const float*)d_in[4];
    const float* x1E  = (const float*)d_in[5];
    const float* x2E  = (const float*)d_in[6];
    const float* z1E  = (const float*)d_in[7];
    const float* z2E  = (const float*)d_in[8];
    const float* muB  = (const float*)d_in[9];
    const float* lb   = (const float*)d_in[10];
    const float* ub   = (const float*)d_in[11];
    const float* W_ih = (const float*)d_in[14];
    const float* b_ih = (const float*)d_in[16];
    const float* b_hh = (const float*)d_in[17];
    const float* W1   = (const float*)d_in[18];
    const float* b1   = (const float*)d_in[19];
    const float* W2   = (const float*)d_in[20];
    const float* b2   = (const float*)d_in[21];

    cudaFuncSetAttribute(ps_lstm_kernel, cudaFuncAttributeMaxDynamicSharedMemorySize, SMEM_BYTES);

    const int rows = 128 * NDIM;           // 262144
    const int grid = rows / TILE;          // 2048
    ps_lstm_kernel<<<grid, NTH, SMEM_BYTES>>>(
        x, x1, x2, z1, z2, x1E, x2E, z1E, z2E, muB, lb, ub,
        W_ih, b_ih, b_hh, W1, b1, W2, b2, (float*)d_out);
}

// round 12
// speedup vs baseline: 2.8102x; 1.2674x over previous
#include <cuda_runtime.h>
#include <cstdint>

#define NDIM   2048
#define TILE   256
#define NTH    256

// ---------------------------------------------------------------------------
// tcgen05 is an architecture-SPECIFIC ('a') feature. The harness also compiles
// a plain compute_103 PTX pass where these instructions don't exist, so every
// tcgen05 usage is gated and a plain-FMA fallback covers the PTX pass.
// ---------------------------------------------------------------------------
#if defined(__CUDA_ARCH__) && (defined(__CUDA_ARCH_FEAT_SM103_ALL) || \
    defined(__CUDA_ARCH_FEAT_SM100_ALL) || defined(__CUDA_ARCH_SPECIFIC__))
#define USE_TCGEN05 1
#else
#define USE_TCGEN05 0
#endif

// ---------------------------------------------------------------------------
// PTX helpers
// ---------------------------------------------------------------------------
__device__ __forceinline__ uint32_t elect_one_pred() {
    uint32_t pred;
    asm volatile("{\n\t.reg .pred p;\n\telect.sync _|p, 0xFFFFFFFF;\n\tselp.b32 %0, 1, 0, p;\n\t}"
                 : "=r"(pred));
    return pred;
}
__device__ __forceinline__ uint32_t smem_u32(const void* p) {
    uint32_t a;
    asm("{ .reg .u64 t; cvta.to.shared.u64 t, %1; cvt.u32.u64 %0, t; }" : "=r"(a) : "l"(p));
    return a;
}

#define MBARRIER_INIT(mbar, count) \
    asm volatile("mbarrier.init.shared.b64 [%0], %1;" \
                 :: "r"((uint32_t)(mbar)), "r"((uint32_t)(count)) : "memory")
#define MBARRIER_INVAL(mbar) \
    asm volatile("mbarrier.inval.shared.b64 [%0];" :: "r"((uint32_t)(mbar)) : "memory")
#define MBARRIER_WAIT_PARITY(mbar, parity) do { \
    uint32_t _m = (uint32_t)(mbar); uint32_t _p = (uint32_t)(parity); uint32_t _d; \
    asm volatile("{\n\t.reg .pred p;\n\t" \
        "mbarrier.try_wait.parity.acquire.cta.shared::cta.b64 p, [%1], %2;\n\t" \
        "selp.b32 %0, 1, 0, p;\n\t}" : "=r"(_d) : "r"(_m), "r"(_p) : "memory"); \
    if (!_d) { \
        asm volatile("{\n\t.reg .pred P1;\n\t" \
            "WL_%=:\n\t" \
            "mbarrier.try_wait.parity.acquire.cta.shared::cta.b64 P1, [%0], %1, 0x989680;\n\t" \
            "@P1 bra.uni WD_%=;\n\t" \
            "bra.uni WL_%=;\n\t" \
            "WD_%=:\n\t}" :: "r"(_m), "r"(_p) : "memory"); \
    } } while (0)

#define FENCE_PROXY_ASYNC()    asm volatile("fence.proxy.async.shared::cta;" ::: "memory")

#if USE_TCGEN05
#define TCGEN05_ALLOC(smem_result_addr, nCols) \
    asm volatile("tcgen05.alloc.cta_group::1.sync.aligned.shared::cta.b32 [%0], %1;" \
                 :: "r"((uint32_t)(smem_result_addr)), "r"((uint32_t)(nCols)) : "memory")
#define TCGEN05_DEALLOC(tmem_addr, nCols) \
    asm volatile("tcgen05.dealloc.cta_group::1.sync.aligned.b32 %0, %1;" \
                 :: "r"(tmem_addr), "r"((uint32_t)(nCols)))
#define TCGEN05_RELINQ() \
    asm volatile("tcgen05.relinquish_alloc_permit.cta_group::1.sync.aligned;")
#define TCGEN05_COMMIT(mbar) \
    asm volatile("tcgen05.commit.cta_group::1.mbarrier::arrive::one.shared::cluster.b64 [%0];" \
                 :: "r"((uint32_t)(mbar)) : "memory")
#define TCGEN05_FENCE_AFTER()  asm volatile("tcgen05.fence::after_thread_sync;" ::: "memory")
#define TCGEN05_FENCE_BEFORE() asm volatile("tcgen05.fence::before_thread_sync;" ::: "memory")
#define TCGEN05_WAIT_LD()      asm volatile("tcgen05.wait::ld.sync.aligned;" ::: "memory")

#define TCGEN05_LD_32X32B_X32(r, tmem_addr) \
    asm volatile("tcgen05.ld.sync.aligned.32x32b.x32.b32 " \
        "{%0, %1, %2, %3, %4, %5, %6, %7, %8, %9, %10, %11, %12, %13, %14, %15, " \
        " %16, %17, %18, %19, %20, %21, %22, %23, %24, %25, %26, %27, %28, %29, %30, %31}, [%32];" \
        : "=r"((r)[0]),  "=r"((r)[1]),  "=r"((r)[2]),  "=r"((r)[3]), \
          "=r"((r)[4]),  "=r"((r)[5]),  "=r"((r)[6]),  "=r"((r)[7]), \
          "=r"((r)[8]),  "=r"((r)[9]),  "=r"((r)[10]), "=r"((r)[11]), \
          "=r"((r)[12]), "=r"((r)[13]), "=r"((r)[14]), "=r"((r)[15]), \
          "=r"((r)[16]), "=r"((r)[17]), "=r"((r)[18]), "=r"((r)[19]), \
          "=r"((r)[20]), "=r"((r)[21]), "=r"((r)[22]), "=r"((r)[23]), \
          "=r"((r)[24]), "=r"((r)[25]), "=r"((r)[26]), "=r"((r)[27]), \
          "=r"((r)[28]), "=r"((r)[29]), "=r"((r)[30]), "=r"((r)[31]) \
        : "r"(tmem_addr))

// SS-form tf32 MMA, cta_group::1. fp32 data in SMEM; HW rounds to tf32.
__device__ __forceinline__ void mma_tf32_ss(uint32_t d_tmem, uint64_t a_desc, uint64_t b_desc,
                                            uint32_t idesc, bool accum) {
    uint32_t en = accum ? 1u : 0u;
    asm volatile("{\n\t.reg .pred p;\n\tsetp.ne.u32 p, %5, 0;\n\t"
                 "tcgen05.mma.cta_group::1.kind::tf32 [%0], %1, %2, %3, {%4, %4, %4, %4}, p;\n\t}"
                 :: "r"(d_tmem), "l"(a_desc), "l"(b_desc), "r"(idesc), "r"(0u), "r"(en)
                 : "memory");
}
#endif // USE_TCGEN05

// SW128 K-major SMEM descriptor base: layout=SW128(2), version=1, SBO=64, LBO=1
static constexpr uint64_t DESC_BASE_SW128 =
    (uint64_t(2) << 61) | (uint64_t(1) << 46) | (uint64_t(64) << 32) | (uint64_t(1) << 16);

// idesc: D=F32, A=TF32, B=TF32, N=128, M=128, K-major both
#define IDESC_TF32 0x8200910u

// ---------------------------------------------------------------------------
// fast activations: tanh.approx.f32 (single MUFU), sigmoid via tanh identity
// ---------------------------------------------------------------------------
__device__ __forceinline__ float tanh_fast(float v) {
    float r;
    asm("tanh.approx.f32 %0, %1;" : "=f"(r) : "f"(v));
    return r;
}
__device__ __forceinline__ float sigmoid_fast(float v) {
    return fmaf(tanh_fast(0.5f * v), 0.5f, 0.5f);
}

// byte offset (incl. SW128 swizzle) for K-major blocked-atom layout, one
// 128x128 fp32 block: atom = 8 rows x 32 fp32 (1024B); 16 atom-rows x 4 atom-cols
__device__ __forceinline__ uint32_t kmaj_off(int row, int col) {
    uint32_t b = (uint32_t)((row >> 3) + (col >> 5) * 16) * 1024u
               + (uint32_t)(row & 7) * 128u + (uint32_t)(col & 31) * 4u;
    return b ^ ((b >> 3) & 0x70);
}

// ---- shared memory layout (bytes, from 1024-aligned base) -----------------
#define OFF_TMEMPTR 0
#define OFF_MBAR    8
#define OFF_BIAS    16                        // 384 f  -> 1552
#define OFF_B1      1552                      // 128 f  -> 2064
#define OFF_W2      2064                      // 128 f  -> 2576
#define OFF_PART    2576                      // 512 f  -> 4624
#define OFF_WIH     4624                      // 12*384 f -> 23056
#define OFF_W1      23552                     // 64 KB (1024-aligned) -> 89088
#define OFF_H       89088                     // 2 x 64 KB blocks -> 220160
#define SMEM_BYTES  (220160 + 1024)

__global__ __launch_bounds__(NTH, 1)
void ps_lstm_kernel(
    const float* __restrict__ x,   const float* __restrict__ x1,  const float* __restrict__ x2,
    const float* __restrict__ z1,  const float* __restrict__ z2,
    const float* __restrict__ x1E, const float* __restrict__ x2E,
    const float* __restrict__ z1E, const float* __restrict__ z2E,
    const float* __restrict__ muB, const float* __restrict__ lb,  const float* __restrict__ ub,
    const float* __restrict__ W_ih, const float* __restrict__ b_ih, const float* __restrict__ b_hh,
    const float* __restrict__ W1,  const float* __restrict__ b1,
    const float* __restrict__ W2,  const float* __restrict__ b2,
    float* __restrict__ out)
{
    extern __shared__ unsigned char smraw[];
    const uint32_t rawa = smem_u32(smraw);
    const uint32_t base = (rawa + 1023u) & ~1023u;
    unsigned char* smb = smraw + (base - rawa);

    float* sBias = (float*)(smb + OFF_BIAS);
    float* sb1   = (float*)(smb + OFF_B1);
    float* sW2   = (float*)(smb + OFF_W2);
    float* sPart = (float*)(smb + OFF_PART);
    float* sWih  = (float*)(smb + OFF_WIH);

    const int tid  = threadIdx.x;
    const int warp = tid >> 5, lane = tid & 31;

    // ---- load weights -----------------------------------------------------
    // W_ih: merge duplicate features (grad_x=x, grad_z1=z1, grad_z2=z2):
    // 12 effective feature slots: {0+5, 1, 2, 3+6, 4+7, 8..14}
    for (int jj = tid; jj < 384; jj += NTH) {
        int row = (jj < 128) ? jj : jj + 128;      // i-gate rows, then g/o rows
        const float* wr = W_ih + row * 15;
        sBias[jj] = b_ih[row] + b_hh[row];
        sWih[0 * 384 + jj] = wr[0] + wr[5];
        sWih[1 * 384 + jj] = wr[1];
        sWih[2 * 384 + jj] = wr[2];
        sWih[3 * 384 + jj] = wr[3] + wr[6];
        sWih[4 * 384 + jj] = wr[4] + wr[7];
        #pragma unroll
        for (int k = 5; k < 12; ++k)
            sWih[k * 384 + jj] = wr[k + 3];
    }
    // W1 -> swizzled K-major blocked layout, float4 (swizzle is 16B-granular)
    for (int i = tid; i < 4096; i += NTH) {
        int r = i >> 5, c4 = (i & 31) * 4;
        float4 v = *(const float4*)(W1 + r * 128 + c4);
        *(float4*)(smb + OFF_W1 + kmaj_off(r, c4)) = v;
    }
    if (tid < 128) { sb1[tid] = b1[tid]; sW2[tid] = W2[tid]; }

#if USE_TCGEN05
    if (warp == 0) { TCGEN05_ALLOC(base + OFF_TMEMPTR, 256); TCGEN05_RELINQ(); }
    if (tid == 0)  { MBARRIER_INIT(base + OFF_MBAR, 1); }
#endif
    __syncthreads();

#if USE_TCGEN05
    uint32_t tmem;
    asm volatile("ld.shared.b32 %0, [%1];" : "=r"(tmem) : "r"(base + OFF_TMEMPTR));
#endif

    const int rowbase = blockIdx.x * TILE;

    // ---- Stage A: features + gate GEMM + activations -> swizzled sH -------
    // each warp: 32 rows, 4 rows per pass, 8 passes
    for (int pass = 0; pass < 8; ++pass) {
        const int lr0 = warp * 32 + pass * 4;
        float g[4][12];
        #pragma unroll
        for (int r = 0; r < 4; ++r) {
            int row = rowbase + lr0 + r;
            float mu  = muB[row >> 11];
            float xv  = x[row],  x1v = x1[row], x2v = x2[row];
            float z1v = z1[row], z2v = z2[row];
            float z1m = (z1v + mu <= 0.0f) ? 0.0f : z1v;
            float z2m = (z2v + mu <= 0.0f) ? 0.0f : z2v;
            float iD1 = fminf(fmaxf(__fdividef(z1m + mu, x1v + mu + 1e-12f), 0.0f), 100.0f);
            float iD2 = fminf(fmaxf(__fdividef(z2m + mu, x2v + mu + 1e-12f), 0.0f), 100.0f);
            g[r][0] = xv;  g[r][1] = x1v; g[r][2] = x2v; g[r][3] = z1m; g[r][4] = z2m;
            g[r][5] = x1E[row]; g[r][6] = x2E[row];
            g[r][7] = z1E[row]; g[r][8] = z2E[row];
            g[r][9] = mu; g[r][10] = iD1; g[r][11] = iD2;
        }

        float acc[4][12];
        #pragma unroll
        for (int m = 0; m < 12; ++m) {
            float bb = sBias[lane + 32 * m];
            acc[0][m] = bb; acc[1][m] = bb; acc[2][m] = bb; acc[3][m] = bb;
        }
        #pragma unroll
        for (int k = 0; k < 12; ++k) {
            #pragma unroll
            for (int m = 0; m < 12; ++m) {
                float w = sWih[k * 384 + lane + 32 * m];
                acc[0][m] = fmaf(w, g[0][k], acc[0][m]);
                acc[1][m] = fmaf(w, g[1][k], acc[1][m]);
                acc[2][m] = fmaf(w, g[2][k], acc[2][m]);
                acc[3][m] = fmaf(w, g[3][k], acc[3][m]);
            }
        }
        // m 0..3: i-gate, 4..7: g-gate, 8..11: o-gate (channel j = lane+32q)
        #pragma unroll
        for (int r = 0; r < 4; ++r) {
            const int lr = lr0 + r;
            const uint32_t blk = (uint32_t)(lr >> 7) * 65536u;
            const uint32_t rp  = (uint32_t)((lr & 127) >> 3) * 1024u
                               + (uint32_t)(lr & 7) * 128u;
            #pragma unroll
            for (int q = 0; q < 4; ++q) {
                float c = sigmoid_fast(acc[r][q]) * tanh_fast(acc[r][q + 4]);
                float h = sigmoid_fast(acc[r][q + 8]) * tanh_fast(c);
                uint32_t b = rp + (uint32_t)q * 16384u + (uint32_t)lane * 4u;
                b ^= (b >> 3) & 0x70;
                *(float*)(smb + OFF_H + blk + b) = h;
            }
        }
    }

    FENCE_PROXY_ASYNC();           // order generic SMEM writes before async-proxy MMA reads
    __syncthreads();

#if USE_TCGEN05
    // ---- Stage B: 2x tcgen05 tf32 SS MMA  D[t][128,128] = H[t] @ W1^T -----
    if (warp == 0) {
        const uint64_t ad = DESC_BASE_SW128 | ((uint64_t)((base + OFF_H)  >> 4) & 0x3FFF);
        const uint64_t bd = DESC_BASE_SW128 | ((uint64_t)((base + OFF_W1) >> 4) & 0x3FFF);
        if (elect_one_pred()) {
            #pragma unroll
            for (int t = 0; t < 2; ++t) {
                #pragma unroll
                for (int s = 0; s < 16; ++s) {
                    uint32_t off = (uint32_t)(s >> 2) * 1024u + (uint32_t)(s & 3) * 2u;
                    mma_tf32_ss(tmem + t * 128, ad + t * 4096u + off, bd + off,
                                IDESC_TF32, s > 0);
                }
            }
            TCGEN05_COMMIT(base + OFF_MBAR);
        }
    }

    MBARRIER_WAIT_PARITY(base + OFF_MBAR, 0);
    TCGEN05_FENCE_AFTER();

    // ---- Epilogue: relu(D + b1) . W2, per-row partial sums ----------------
    {
        const int sp = warp & 3;          // implicit TMEM subpartition (rows sp*32..+31)
        const int ch = warp >> 2;         // column half
        const int cb = ch * 64;
        #pragma unroll
        for (int t = 0; t < 2; ++t) {
            uint32_t d0[32], d1[32];
            TCGEN05_LD_32X32B_X32(d0, tmem + t * 128 + cb);
            TCGEN05_LD_32X32B_X32(d1, tmem + t * 128 + cb + 32);
            TCGEN05_WAIT_LD();
            float s = 0.0f;
            #pragma unroll
            for (int r = 0; r < 32; ++r) {
                s = fmaf(fmaxf(__uint_as_float(d0[r]) + sb1[cb + r], 0.0f), sW2[cb + r], s);
                s = fmaf(fmaxf(__uint_as_float(d1[r]) + sb1[cb + 32 + r], 0.0f), sW2[cb + 32 + r], s);
            }
            sPart[ch * 256 + t * 128 + sp * 32 + lane] = s;
        }
        TCGEN05_FENCE_BEFORE();
    }
    __syncthreads();
#else
    // ---- Stage B fallback (compute_103 PTX pass only): plain FMA ----------
    {
        const int r = tid;                 // one row per thread (256 rows)
        const uint32_t blk = (uint32_t)(r >> 7) * 65536u;
        float s = 0.0f;
        for (int j = 0; j < 128; ++j) {
            float acc = sb1[j];
            #pragma unroll 8
            for (int k4 = 0; k4 < 32; ++k4) {
                uint32_t ho = kmaj_off(r & 127, 4 * k4);
                const float4 hv = *(const float4*)(smb + OFF_H + blk + ho);
                const float4 wv = *(const float4*)(smb + OFF_W1 + kmaj_off(j, 4 * k4));
                acc = fmaf(hv.x, wv.x, fmaf(hv.y, wv.y, fmaf(hv.z, wv.z, fmaf(hv.w, wv.w, acc))));
            }
            s = fmaf(fmaxf(acc, 0.0f), sW2[j], s);
        }
        sPart[tid] = s;
        sPart[256 + tid] = 0.0f;
    }
    __syncthreads();
#endif

    // ---- Stage C: elementwise updates + output ----------------------------
    {
        const int row = rowbase + tid;
        const int b = row >> 11, n = row & (NDIM - 1);
        float mu  = muB[b];
        float xv  = x[row],  x1v = x1[row], x2v = x2[row];
        float z1v = z1[row], z2v = z2[row];
        float z1m = (z1v + mu <= 0.0f) ? 0.0f : z1v;
        float z2m = (z2v + mu <= 0.0f) ? 0.0f : z2v;
        float iD1 = fminf(fmaxf(__fdividef(z1m + mu, x1v + mu + 1e-12f), 0.0f), 100.0f);
        float iD2 = fminf(fmaxf(__fdividef(z2m + mu, x2v + mu + 1e-12f), 0.0f), 100.0f);
        float p  = fabsf(sPart[tid] + sPart[256 + tid] + b2[0]);
        float d  = -p * xv;
        float xn = xv + d;
        float z1o = z1m - iD1 * (d + z1m);
        float z2o = z2m - iD2 * (-d + z2m);
        float x1o = xn - lb[row];
        float x2o = ub[row] - xn;
        size_t ob = (size_t)b * (5 * NDIM) + n;
        out[ob]            = xn;
        out[ob +     NDIM] = x1o;
        out[ob + 2 * NDIM] = x2o;
        out[ob + 3 * NDIM] = z1o;
        out[ob + 4 * NDIM] = z2o;
    }

#if USE_TCGEN05
    if (tid == 0) MBARRIER_INVAL(base + OFF_MBAR);
    if (warp == 0) TCGEN05_DEALLOC(tmem, 256);
#endif
}

// ---------------------------------------------------------------------------
// metadata order:
//  0 x  1 x1  2 x2  3 z1  4 z2  5 x1E  6 x2E  7 z1E  8 z2E  9 muB  10 lb 11 ub
// 12 has_lb 13 has_ub 14 W_ih 15 W_hh(unused) 16 b_ih 17 b_hh 18 W1 19 b1 20 W2 21 b2
// ---------------------------------------------------------------------------
extern "C" void kernel_launch(void* const* d_in, const int* in_sizes, int n_in,
                              void* d_out, int out_size) {
    (void)in_sizes; (void)n_in; (void)out_size;
    const float* x    = (const float*)d_in[0];
    const float* x1   = (const float*)d_in[1];
    const float* x2   = (const float*)d_in[2];
    const float* z1   = (const float*)d_in[3];
    const float* z2   = (const float*)d_in[4];
    const float* x1E  = (const float*)d_in[5];
    const float* x2E  = (const float*)d_in[6];
    const float* z1E  = (const float*)d_in[7];
    const float* z2E  = (const float*)d_in[8];
    const float* muB  = (const float*)d_in[9];
    const float* lb   = (const float*)d_in[10];
    const float* ub   = (const float*)d_in[11];
    const float* W_ih = (const float*)d_in[14];
    const float* b_ih = (const float*)d_in[16];
    const float* b_hh = (const float*)d_in[17];
    const float* W1   = (const float*)d_in[18];
    const float* b1   = (const float*)d_in[19];
    const float* W2   = (const float*)d_in[20];
    const float* b2   = (const float*)d_in[21];

    cudaFuncSetAttribute(ps_lstm_kernel, cudaFuncAttributeMaxDynamicSharedMemorySize, SMEM_BYTES);

    const int rows = 128 * NDIM;           // 262144
    const int grid = rows / TILE;          // 1024
    ps_lstm_kernel<<<grid, NTH, SMEM_BYTES>>>(
        x, x1, x2, z1, z2, x1E, x2E, z1E, z2E, muB, lb, ub,
        W_ih, b_ih, b_hh, W1, b1, W2, b2, (float*)d_out);
}

// round 13
// speedup vs baseline: 3.4309x; 1.2209x over previous
#include <cuda_runtime.h>
#include <cstdint>

#define NDIM   2048
#define TILE   128
#define NTH    256

// ---------------------------------------------------------------------------
// tcgen05 is an architecture-SPECIFIC ('a') feature. The harness also compiles
// a plain compute_103 PTX pass where these instructions don't exist, so every
// tcgen05 usage is gated and a plain-FMA fallback covers the PTX pass.
// ---------------------------------------------------------------------------
#if defined(__CUDA_ARCH__) && (defined(__CUDA_ARCH_FEAT_SM103_ALL) || \
    defined(__CUDA_ARCH_FEAT_SM100_ALL) || defined(__CUDA_ARCH_SPECIFIC__))
#define USE_TCGEN05 1
#else
#define USE_TCGEN05 0
#endif

// ---------------------------------------------------------------------------
// PTX helpers
// ---------------------------------------------------------------------------
__device__ __forceinline__ uint32_t elect_one_pred() {
    uint32_t pred;
    asm volatile("{\n\t.reg .pred p;\n\telect.sync _|p, 0xFFFFFFFF;\n\tselp.b32 %0, 1, 0, p;\n\t}"
                 : "=r"(pred));
    return pred;
}
__device__ __forceinline__ uint32_t smem_u32(const void* p) {
    uint32_t a;
    asm("{ .reg .u64 t; cvta.to.shared.u64 t, %1; cvt.u32.u64 %0, t; }" : "=r"(a) : "l"(p));
    return a;
}

#define MBARRIER_INIT(mbar, count) \
    asm volatile("mbarrier.init.shared.b64 [%0], %1;" \
                 :: "r"((uint32_t)(mbar)), "r"((uint32_t)(count)) : "memory")
#define MBARRIER_INVAL(mbar) \
    asm volatile("mbarrier.inval.shared.b64 [%0];" :: "r"((uint32_t)(mbar)) : "memory")
#define MBARRIER_WAIT_PARITY(mbar, parity) do { \
    uint32_t _m = (uint32_t)(mbar); uint32_t _p = (uint32_t)(parity); uint32_t _d; \
    asm volatile("{\n\t.reg .pred p;\n\t" \
        "mbarrier.try_wait.parity.acquire.cta.shared::cta.b64 p, [%1], %2;\n\t" \
        "selp.b32 %0, 1, 0, p;\n\t}" : "=r"(_d) : "r"(_m), "r"(_p) : "memory"); \
    if (!_d) { \
        asm volatile("{\n\t.reg .pred P1;\n\t" \
            "WL_%=:\n\t" \
            "mbarrier.try_wait.parity.acquire.cta.shared::cta.b64 P1, [%0], %1, 0x989680;\n\t" \
            "@P1 bra.uni WD_%=;\n\t" \
            "bra.uni WL_%=;\n\t" \
            "WD_%=:\n\t}" :: "r"(_m), "r"(_p) : "memory"); \
    } } while (0)

#define FENCE_PROXY_ASYNC()    asm volatile("fence.proxy.async.shared::cta;" ::: "memory")

#if USE_TCGEN05
#define TCGEN05_ALLOC(smem_result_addr, nCols) \
    asm volatile("tcgen05.alloc.cta_group::1.sync.aligned.shared::cta.b32 [%0], %1;" \
                 :: "r"((uint32_t)(smem_result_addr)), "r"((uint32_t)(nCols)) : "memory")
#define TCGEN05_DEALLOC(tmem_addr, nCols) \
    asm volatile("tcgen05.dealloc.cta_group::1.sync.aligned.b32 %0, %1;" \
                 :: "r"(tmem_addr), "r"((uint32_t)(nCols)))
#define TCGEN05_RELINQ() \
    asm volatile("tcgen05.relinquish_alloc_permit.cta_group::1.sync.aligned;")
#define TCGEN05_COMMIT(mbar) \
    asm volatile("tcgen05.commit.cta_group::1.mbarrier::arrive::one.shared::cluster.b64 [%0];" \
                 :: "r"((uint32_t)(mbar)) : "memory")
#define TCGEN05_FENCE_AFTER()  asm volatile("tcgen05.fence::after_thread_sync;" ::: "memory")
#define TCGEN05_FENCE_BEFORE() asm volatile("tcgen05.fence::before_thread_sync;" ::: "memory")
#define TCGEN05_WAIT_LD()      asm volatile("tcgen05.wait::ld.sync.aligned;" ::: "memory")

#define TCGEN05_LD_32X32B_X32(r, tmem_addr) \
    asm volatile("tcgen05.ld.sync.aligned.32x32b.x32.b32 " \
        "{%0, %1, %2, %3, %4, %5, %6, %7, %8, %9, %10, %11, %12, %13, %14, %15, " \
        " %16, %17, %18, %19, %20, %21, %22, %23, %24, %25, %26, %27, %28, %29, %30, %31}, [%32];" \
        : "=r"((r)[0]),  "=r"((r)[1]),  "=r"((r)[2]),  "=r"((r)[3]), \
          "=r"((r)[4]),  "=r"((r)[5]),  "=r"((r)[6]),  "=r"((r)[7]), \
          "=r"((r)[8]),  "=r"((r)[9]),  "=r"((r)[10]), "=r"((r)[11]), \
          "=r"((r)[12]), "=r"((r)[13]), "=r"((r)[14]), "=r"((r)[15]), \
          "=r"((r)[16]), "=r"((r)[17]), "=r"((r)[18]), "=r"((r)[19]), \
          "=r"((r)[20]), "=r"((r)[21]), "=r"((r)[22]), "=r"((r)[23]), \
          "=r"((r)[24]), "=r"((r)[25]), "=r"((r)[26]), "=r"((r)[27]), \
          "=r"((r)[28]), "=r"((r)[29]), "=r"((r)[30]), "=r"((r)[31]) \
        : "r"(tmem_addr))

// SS-form tf32 MMA, cta_group::1. fp32 data in SMEM; HW rounds to tf32.
__device__ __forceinline__ void mma_tf32_ss(uint32_t d_tmem, uint64_t a_desc, uint64_t b_desc,
                                            uint32_t idesc, bool accum) {
    uint32_t en = accum ? 1u : 0u;
    asm volatile("{\n\t.reg .pred p;\n\tsetp.ne.u32 p, %5, 0;\n\t"
                 "tcgen05.mma.cta_group::1.kind::tf32 [%0], %1, %2, %3, {%4, %4, %4, %4}, p;\n\t}"
                 :: "r"(d_tmem), "l"(a_desc), "l"(b_desc), "r"(idesc), "r"(0u), "r"(en)
                 : "memory");
}
#endif // USE_TCGEN05

// SW128 K-major SMEM descriptor base: layout=SW128(2), version=1, SBO=64, LBO=1
static constexpr uint64_t DESC_BASE_SW128 =
    (uint64_t(2) << 61) | (uint64_t(1) << 46) | (uint64_t(64) << 32) | (uint64_t(1) << 16);

// idesc: D=F32, A=TF32, B=TF32, N=128, M=128, K-major both
#define IDESC_TF32 0x8200910u

// ---------------------------------------------------------------------------
// fast activations: tanh.approx.f32 (single MUFU), sigmoid via tanh identity
// ---------------------------------------------------------------------------
__device__ __forceinline__ float tanh_fast(float v) {
    float r;
    asm("tanh.approx.f32 %0, %1;" : "=f"(r) : "f"(v));
    return r;
}
__device__ __forceinline__ float sigmoid_fast(float v) {
    return fmaf(tanh_fast(0.5f * v), 0.5f, 0.5f);
}
__device__ __forceinline__ float lstm_h(float iv, float gv, float ov) {
    float c = sigmoid_fast(iv) * tanh_fast(gv);
    return sigmoid_fast(ov) * tanh_fast(c);
}

// byte offset (incl. SW128 swizzle) for K-major blocked-atom layout, one
// 128-row block of 128B rows: atom = 8 rows x 32 fp32; 16 atom-rows x atom-cols
__device__ __forceinline__ uint32_t kmaj_off(int row, int col) {
    uint32_t b = (uint32_t)((row >> 3) + (col >> 5) * 16) * 1024u
               + (uint32_t)(row & 7) * 128u + (uint32_t)(col & 31) * 4u;
    return b ^ ((b >> 3) & 0x70);
}

// ---- shared memory layout (bytes, from 1024-aligned base) -----------------
#define OFF_TMEMPTR 0
#define OFF_MBAR    8
#define OFF_B1      16                        // 128 f
#define OFF_W2      528                       // 128 f
#define OFF_PART    1040                      // 256 f -> 2064
#define OFF_F       2048                      // 128 rows x 128B  = 16 KB
#define OFF_WIHB    18432                     // 384 rows x 128B  = 48 KB (3 blocks)
#define OFF_W1      67584                     // 64 KB
#define OFF_H       133120                    // 64 KB -> 198656
#define SMEM_BYTES  (198656 + 1024)

__global__ __launch_bounds__(NTH, 1)
void ps_lstm_kernel(
    const float* __restrict__ x,   const float* __restrict__ x1,  const float* __restrict__ x2,
    const float* __restrict__ z1,  const float* __restrict__ z2,
    const float* __restrict__ x1E, const float* __restrict__ x2E,
    const float* __restrict__ z1E, const float* __restrict__ z2E,
    const float* __restrict__ muB, const float* __restrict__ lb,  const float* __restrict__ ub,
    const float* __restrict__ W_ih, const float* __restrict__ b_ih, const float* __restrict__ b_hh,
    const float* __restrict__ W1,  const float* __restrict__ b1,
    const float* __restrict__ W2,  const float* __restrict__ b2,
    float* __restrict__ out)
{
    extern __shared__ unsigned char smraw[];
    const uint32_t rawa = smem_u32(smraw);
    const uint32_t base = (rawa + 1023u) & ~1023u;
    unsigned char* smb = smraw + (base - rawa);

    float* sb1   = (float*)(smb + OFF_B1);
    float* sW2   = (float*)(smb + OFF_W2);
    float* sPart = (float*)(smb + OFF_PART);

    const int tid  = threadIdx.x;
    const int warp = tid >> 5, lane = tid & 31;
    const int rowbase = blockIdx.x * TILE;

    // ---- preload: W_ih^T (+bias feature) into K-major SW128 ---------------
    // channel j (0..383): j<128 -> i-gate row j; 128..255 -> g row j+128;
    // 256..383 -> o row j+128. Merged 12 features + col12 = bias, 13..15 = 0.
    for (int j = tid; j < 384; j += NTH) {
        int row = (j < 128) ? j : j + 128;
        const float* wr = W_ih + row * 15;
        uint32_t blk = (uint32_t)(j >> 7) * 16384u + (uint32_t)OFF_WIHB;
        int jr = j & 127;
        float w0 = wr[0] + wr[5], w3 = wr[3] + wr[6], w4 = wr[4] + wr[7];
        *(float*)(smb + blk + kmaj_off(jr, 0))  = w0;
        *(float*)(smb + blk + kmaj_off(jr, 1))  = wr[1];
        *(float*)(smb + blk + kmaj_off(jr, 2))  = wr[2];
        *(float*)(smb + blk + kmaj_off(jr, 3))  = w3;
        *(float*)(smb + blk + kmaj_off(jr, 4))  = w4;
        #pragma unroll
        for (int k = 5; k < 12; ++k)
            *(float*)(smb + blk + kmaj_off(jr, k)) = wr[k + 3];
        *(float*)(smb + blk + kmaj_off(jr, 12)) = b_ih[row] + b_hh[row];
        *(float*)(smb + blk + kmaj_off(jr, 13)) = 0.0f;
        *(float*)(smb + blk + kmaj_off(jr, 14)) = 0.0f;
        *(float*)(smb + blk + kmaj_off(jr, 15)) = 0.0f;
    }
    // W1 -> swizzled K-major blocked layout, float4 (swizzle is 16B-granular)
    for (int i = tid; i < 4096; i += NTH) {
        int r = i >> 5, c4 = (i & 31) * 4;
        float4 v = *(const float4*)(W1 + r * 128 + c4);
        *(float4*)(smb + OFF_W1 + kmaj_off(r, c4)) = v;
    }
    if (tid < 128) { sb1[tid] = b1[tid]; sW2[tid] = W2[tid]; }

    // ---- feature build: F[128 rows, 16 K] (col12 = 1 bias, 13..15 = 0) ----
    {
        const int r    = tid & 127;
        const int half = tid >> 7;
        const int row  = rowbase + r;
        float mu  = muB[row >> 11];
        float x1v = x1[row], x2v = x2[row];
        float z1v = z1[row], z2v = z2[row];
        float z1m = (z1v + mu <= 0.0f) ? 0.0f : z1v;
        float z2m = (z2v + mu <= 0.0f) ? 0.0f : z2v;
        if (half == 0) {
            float xv = x[row];
            float4 a = make_float4(xv, x1v, x2v, z1m);
            float4 b = make_float4(z2m, x1E[row], x2E[row], z1E[row]);
            *(float4*)(smb + OFF_F + kmaj_off(r, 0)) = a;
            *(float4*)(smb + OFF_F + kmaj_off(r, 4)) = b;
        } else {
            float iD1 = fminf(fmaxf(__fdividef(z1m + mu, x1v + mu + 1e-12f), 0.0f), 100.0f);
            float iD2 = fminf(fmaxf(__fdividef(z2m + mu, x2v + mu + 1e-12f), 0.0f), 100.0f);
            float4 a = make_float4(z2E[row], mu, iD1, iD2);
            float4 b = make_float4(1.0f, 0.0f, 0.0f, 0.0f);
            *(float4*)(smb + OFF_F + kmaj_off(r, 8))  = a;
            *(float4*)(smb + OFF_F + kmaj_off(r, 12)) = b;
        }
    }

#if USE_TCGEN05
    if (warp == 0) { TCGEN05_ALLOC(base + OFF_TMEMPTR, 512); TCGEN05_RELINQ(); }
    if (tid == 0)  { MBARRIER_INIT(base + OFF_MBAR, 1); }
#endif
    FENCE_PROXY_ASYNC();
    __syncthreads();

#if USE_TCGEN05
    uint32_t tmem;
    asm volatile("ld.shared.b32 %0, [%1];" : "=r"(tmem) : "r"(base + OFF_TMEMPTR));

    // ---- MMA1: gates[128,384] = F @ WihB^T, 3 x (N=128, K=16) -------------
    if (warp == 0) {
        const uint64_t fd = DESC_BASE_SW128 | ((uint64_t)((base + OFF_F)    >> 4) & 0x3FFF);
        const uint64_t wd = DESC_BASE_SW128 | ((uint64_t)((base + OFF_WIHB) >> 4) & 0x3FFF);
        if (elect_one_pred()) {
            #pragma unroll
            for (int nb = 0; nb < 3; ++nb) {
                #pragma unroll
                for (int s = 0; s < 2; ++s)
                    mma_tf32_ss(tmem + nb * 128, fd + s * 2, wd + nb * 1024u + s * 2,
                                IDESC_TF32, s > 0);
            }
            TCGEN05_COMMIT(base + OFF_MBAR);
        }
    }
    MBARRIER_WAIT_PARITY(base + OFF_MBAR, 0);
    TCGEN05_FENCE_AFTER();

    // ---- gate epilogue: activations -> H (swizzled K-major) ---------------
    // warp sp = warp&3 owns TMEM lanes (rows) sp*32..+31; ch = warp>>2 owns
    // column half [ch*64, ch*64+64) in chunks of 32.
    {
        const int sp = warp & 3, ch = warp >> 2;
        const int row = sp * 32 + lane;
        #pragma unroll
        for (int cc = 0; cc < 2; ++cc) {
            const int c = ch * 64 + cc * 32;
            uint32_t vi[32], vg[32], vo[32];
            TCGEN05_LD_32X32B_X32(vi, tmem + c);
            TCGEN05_LD_32X32B_X32(vg, tmem + 128 + c);
            TCGEN05_LD_32X32B_X32(vo, tmem + 256 + c);
            TCGEN05_WAIT_LD();
            #pragma unroll
            for (int u = 0; u < 8; ++u) {
                float4 hv;
                hv.x = lstm_h(__uint_as_float(vi[4*u+0]), __uint_as_float(vg[4*u+0]), __uint_as_float(vo[4*u+0]));
                hv.y = lstm_h(__uint_as_float(vi[4*u+1]), __uint_as_float(vg[4*u+1]), __uint_as_float(vo[4*u+1]));
                hv.z = lstm_h(__uint_as_float(vi[4*u+2]), __uint_as_float(vg[4*u+2]), __uint_as_float(vo[4*u+2]));
                hv.w = lstm_h(__uint_as_float(vi[4*u+3]), __uint_as_float(vg[4*u+3]), __uint_as_float(vo[4*u+3]));
                *(float4*)(smb + OFF_H + kmaj_off(row, c + 4 * u)) = hv;
            }
        }
    }
    TCGEN05_FENCE_BEFORE();
    FENCE_PROXY_ASYNC();
    __syncthreads();

    // ---- MMA2: D2[128,128] = H @ W1^T -> TMEM cols [384,512) --------------
    if (warp == 0) {
        const uint64_t ad = DESC_BASE_SW128 | ((uint64_t)((base + OFF_H)  >> 4) & 0x3FFF);
        const uint64_t bd = DESC_BASE_SW128 | ((uint64_t)((base + OFF_W1) >> 4) & 0x3FFF);
        if (elect_one_pred()) {
            #pragma unroll
            for (int s = 0; s < 16; ++s) {
                uint32_t off = (uint32_t)(s >> 2) * 1024u + (uint32_t)(s & 3) * 2u;
                mma_tf32_ss(tmem + 384, ad + off, bd + off, IDESC_TF32, s > 0);
            }
            TCGEN05_COMMIT(base + OFF_MBAR);
        }
    }
    MBARRIER_WAIT_PARITY(base + OFF_MBAR, 1);
    TCGEN05_FENCE_AFTER();

    // ---- head epilogue: relu(D2 + b1) . W2, per-row partial sums ----------
    {
        const int sp = warp & 3, ch = warp >> 2;
        const int cb = ch * 64;
        uint32_t d0[32], d1[32];
        TCGEN05_LD_32X32B_X32(d0, tmem + 384 + cb);
        TCGEN05_LD_32X32B_X32(d1, tmem + 384 + cb + 32);
        TCGEN05_WAIT_LD();
        float s = 0.0f;
        #pragma unroll
        for (int r = 0; r < 32; ++r) {
            s = fmaf(fmaxf(__uint_as_float(d0[r]) + sb1[cb + r], 0.0f), sW2[cb + r], s);
            s = fmaf(fmaxf(__uint_as_float(d1[r]) + sb1[cb + 32 + r], 0.0f), sW2[cb + 32 + r], s);
        }
        TCGEN05_FENCE_BEFORE();
        sPart[ch * 128 + sp * 32 + lane] = s;
    }
    __syncthreads();
#else
    // ---- PTX-pass fallback: scalar gates + head (compiles, never runs) ----
    if (tid < 128) {
        const int r = tid;
        float f[13];
        #pragma unroll
        for (int k = 0; k < 13; ++k)
            f[k] = *(const float*)(smb + OFF_F + kmaj_off(r, k));
        for (int j = 0; j < 128; ++j) {
            float a[3];
            #pragma unroll
            for (int gidx = 0; gidx < 3; ++gidx) {
                int jj = j + gidx * 128;
                uint32_t blk = (uint32_t)(jj >> 7) * 16384u + (uint32_t)OFF_WIHB;
                float acc = 0.0f;
                #pragma unroll
                for (int k = 0; k < 13; ++k)
                    acc = fmaf(f[k], *(const float*)(smb + blk + kmaj_off(jj & 127, k)), acc);
                a[gidx] = acc;
            }
            *(float*)(smb + OFF_H + kmaj_off(r, j)) = lstm_h(a[0], a[1], a[2]);
        }
    }
    __syncthreads();
    if (tid < 128) {
        const int r = tid;
        float s = 0.0f;
        for (int j = 0; j < 128; ++j) {
            float acc = sb1[j];
            #pragma unroll 8
            for (int k4 = 0; k4 < 32; ++k4) {
                const float4 hv = *(const float4*)(smb + OFF_H  + kmaj_off(r, 4 * k4));
                const float4 wv = *(const float4*)(smb + OFF_W1 + kmaj_off(j, 4 * k4));
                acc = fmaf(hv.x, wv.x, fmaf(hv.y, wv.y, fmaf(hv.z, wv.z, fmaf(hv.w, wv.w, acc))));
            }
            s = fmaf(fmaxf(acc, 0.0f), sW2[j], s);
        }
        sPart[tid] = s;
        sPart[128 + tid] = 0.0f;
    }
    __syncthreads();
#endif

    // ---- Stage C: elementwise updates + output ----------------------------
    if (tid < TILE) {
        const int row = rowbase + tid;
        const int b = row >> 11, n = row & (NDIM - 1);
        float mu  = muB[b];
        float xv  = x[row],  x1v = x1[row], x2v = x2[row];
        float z1v = z1[row], z2v = z2[row];
        float z1m = (z1v + mu <= 0.0f) ? 0.0f : z1v;
        float z2m = (z2v + mu <= 0.0f) ? 0.0f : z2v;
        float iD1 = fminf(fmaxf(__fdividef(z1m + mu, x1v + mu + 1e-12f), 0.0f), 100.0f);
        float iD2 = fminf(fmaxf(__fdividef(z2m + mu, x2v + mu + 1e-12f), 0.0f), 100.0f);
        float p  = fabsf(sPart[tid] + sPart[128 + tid] + b2[0]);
        float d  = -p * xv;
        float xn = xv + d;
        float z1o = z1m - iD1 * (d + z1m);
        float z2o = z2m - iD2 * (-d + z2m);
        float x1o = xn - lb[row];
        float x2o = ub[row] - xn;
        size_t ob = (size_t)b * (5 * NDIM) + n;
        out[ob]            = xn;
        out[ob +     NDIM] = x1o;
        out[ob + 2 * NDIM] = x2o;
        out[ob + 3 * NDIM] = z1o;
        out[ob + 4 * NDIM] = z2o;
    }

#if USE_TCGEN05
    if (tid == 0) MBARRIER_INVAL(base + OFF_MBAR);
    if (warp == 0) TCGEN05_DEALLOC(tmem, 512);
#endif
}

// ---------------------------------------------------------------------------
// metadata order:
//  0 x  1 x1  2 x2  3 z1  4 z2  5 x1E  6 x2E  7 z1E  8 z2E  9 muB  10 lb 11 ub
// 12 has_lb 13 has_ub 14 W_ih 15 W_hh(unused) 16 b_ih 17 b_hh 18 W1 19 b1 20 W2 21 b2
// ---------------------------------------------------------------------------
extern "C" void kernel_launch(void* const* d_in, const int* in_sizes, int n_in,
                              void* d_out, int out_size) {
    (void)in_sizes; (void)n_in; (void)out_size;
    const float* x    = (const float*)d_in[0];
    const float* x1   = (const float*)d_in[1];
    const float* x2   = (const float*)d_in[2];
    const float* z1   = (const float*)d_in[3];
    const float* z2   = (const float*)d_in[4];
    const float* x1E  = (const float*)d_in[5];
    const float* x2E  = (const float*)d_in[6];
    const float* z1E  = (const float*)d_in[7];
    const float* z2E  = (const float*)d_in[8];
    const float* muB  = (const float*)d_in[9];
    const float* lb   = (const float*)d_in[10];
    const float* ub   = (const float*)d_in[11];
    const float* W_ih = (const float*)d_in[14];
    const float* b_ih = (const float*)d_in[16];
    const float* b_hh = (const float*)d_in[17];
    const float* W1   = (const float*)d_in[18];
    const float* b1   = (const float*)d_in[19];
    const float* W2   = (const float*)d_in[20];
    const float* b2   = (const float*)d_in[21];

    cudaFuncSetAttribute(ps_lstm_kernel, cudaFuncAttributeMaxDynamicSharedMemorySize, SMEM_BYTES);

    const int rows = 128 * NDIM;           // 262144
    const int grid = rows / TILE;          // 2048
    ps_lstm_kernel<<<grid, NTH, SMEM_BYTES>>>(
        x, x1, x2, z1, z2, x1E, x2E, z1E, z2E, muB, lb, ub,
        W_ih, b_ih, b_hh, W1, b1, W2, b2, (float*)d_out);
}

// round 14
// speedup vs baseline: 5.1317x; 1.4957x over previous
#include <cuda_runtime.h>
#include <cstdint>

#define NDIM   2048
#define TILE   256
#define NTH    512

// ---------------------------------------------------------------------------
// tcgen05 is an architecture-SPECIFIC ('a') feature. The harness also compiles
// a plain compute_103 PTX pass where these instructions don't exist, so every
// tcgen05 usage is gated and a plain-FMA fallback covers the PTX pass.
// ---------------------------------------------------------------------------
#if defined(__CUDA_ARCH__) && (defined(__CUDA_ARCH_FEAT_SM103_ALL) || \
    defined(__CUDA_ARCH_FEAT_SM100_ALL) || defined(__CUDA_ARCH_SPECIFIC__))
#define USE_TCGEN05 1
#else
#define USE_TCGEN05 0
#endif

// ---------------------------------------------------------------------------
// PTX helpers
// ---------------------------------------------------------------------------
__device__ __forceinline__ uint32_t elect_one_pred() {
    uint32_t pred;
    asm volatile("{\n\t.reg .pred p;\n\telect.sync _|p, 0xFFFFFFFF;\n\tselp.b32 %0, 1, 0, p;\n\t}"
                 : "=r"(pred));
    return pred;
}
__device__ __forceinline__ uint32_t smem_u32(const void* p) {
    uint32_t a;
    asm("{ .reg .u64 t; cvta.to.shared.u64 t, %1; cvt.u32.u64 %0, t; }" : "=r"(a) : "l"(p));
    return a;
}

#define MBARRIER_INIT(mbar, count) \
    asm volatile("mbarrier.init.shared.b64 [%0], %1;" \
                 :: "r"((uint32_t)(mbar)), "r"((uint32_t)(count)) : "memory")
#define MBARRIER_INVAL(mbar) \
    asm volatile("mbarrier.inval.shared.b64 [%0];" :: "r"((uint32_t)(mbar)) : "memory")
#define MBARRIER_WAIT_PARITY(mbar, parity) do { \
    uint32_t _m = (uint32_t)(mbar); uint32_t _p = (uint32_t)(parity); uint32_t _d; \
    asm volatile("{\n\t.reg .pred p;\n\t" \
        "mbarrier.try_wait.parity.acquire.cta.shared::cta.b64 p, [%1], %2;\n\t" \
        "selp.b32 %0, 1, 0, p;\n\t}" : "=r"(_d) : "r"(_m), "r"(_p) : "memory"); \
    if (!_d) { \
        asm volatile("{\n\t.reg .pred P1;\n\t" \
            "WL_%=:\n\t" \
            "mbarrier.try_wait.parity.acquire.cta.shared::cta.b64 P1, [%0], %1, 0x989680;\n\t" \
            "@P1 bra.uni WD_%=;\n\t" \
            "bra.uni WL_%=;\n\t" \
            "WD_%=:\n\t}" :: "r"(_m), "r"(_p) : "memory"); \
    } } while (0)

#define FENCE_PROXY_ASYNC()    asm volatile("fence.proxy.async.shared::cta;" ::: "memory")

#if USE_TCGEN05
#define TCGEN05_ALLOC(smem_result_addr, nCols) \
    asm volatile("tcgen05.alloc.cta_group::1.sync.aligned.shared::cta.b32 [%0], %1;" \
                 :: "r"((uint32_t)(smem_result_addr)), "r"((uint32_t)(nCols)) : "memory")
#define TCGEN05_DEALLOC(tmem_addr, nCols) \
    asm volatile("tcgen05.dealloc.cta_group::1.sync.aligned.b32 %0, %1;" \
                 :: "r"(tmem_addr), "r"((uint32_t)(nCols)))
#define TCGEN05_RELINQ() \
    asm volatile("tcgen05.relinquish_alloc_permit.cta_group::1.sync.aligned;")
#define TCGEN05_COMMIT(mbar) \
    asm volatile("tcgen05.commit.cta_group::1.mbarrier::arrive::one.shared::cluster.b64 [%0];" \
                 :: "r"((uint32_t)(mbar)) : "memory")
#define TCGEN05_FENCE_AFTER()  asm volatile("tcgen05.fence::after_thread_sync;" ::: "memory")
#define TCGEN05_FENCE_BEFORE() asm volatile("tcgen05.fence::before_thread_sync;" ::: "memory")
#define TCGEN05_WAIT_LD()      asm volatile("tcgen05.wait::ld.sync.aligned;" ::: "memory")

#define TCGEN05_LD_32X32B_X16(r, tmem_addr) \
    asm volatile("tcgen05.ld.sync.aligned.32x32b.x16.b32 " \
        "{%0, %1, %2, %3, %4, %5, %6, %7, %8, %9, %10, %11, %12, %13, %14, %15}, [%16];" \
        : "=r"((r)[0]),  "=r"((r)[1]),  "=r"((r)[2]),  "=r"((r)[3]), \
          "=r"((r)[4]),  "=r"((r)[5]),  "=r"((r)[6]),  "=r"((r)[7]), \
          "=r"((r)[8]),  "=r"((r)[9]),  "=r"((r)[10]), "=r"((r)[11]), \
          "=r"((r)[12]), "=r"((r)[13]), "=r"((r)[14]), "=r"((r)[15]) \
        : "r"(tmem_addr))

#define TCGEN05_LD_32X32B_X32(r, tmem_addr) \
    asm volatile("tcgen05.ld.sync.aligned.32x32b.x32.b32 " \
        "{%0, %1, %2, %3, %4, %5, %6, %7, %8, %9, %10, %11, %12, %13, %14, %15, " \
        " %16, %17, %18, %19, %20, %21, %22, %23, %24, %25, %26, %27, %28, %29, %30, %31}, [%32];" \
        : "=r"((r)[0]),  "=r"((r)[1]),  "=r"((r)[2]),  "=r"((r)[3]), \
          "=r"((r)[4]),  "=r"((r)[5]),  "=r"((r)[6]),  "=r"((r)[7]), \
          "=r"((r)[8]),  "=r"((r)[9]),  "=r"((r)[10]), "=r"((r)[11]), \
          "=r"((r)[12]), "=r"((r)[13]), "=r"((r)[14]), "=r"((r)[15]), \
          "=r"((r)[16]), "=r"((r)[17]), "=r"((r)[18]), "=r"((r)[19]), \
          "=r"((r)[20]), "=r"((r)[21]), "=r"((r)[22]), "=r"((r)[23]), \
          "=r"((r)[24]), "=r"((r)[25]), "=r"((r)[26]), "=r"((r)[27]), \
          "=r"((r)[28]), "=r"((r)[29]), "=r"((r)[30]), "=r"((r)[31]) \
        : "r"(tmem_addr))

// SS-form tf32 MMA, cta_group::1. fp32 data in SMEM; HW rounds to tf32.
__device__ __forceinline__ void mma_tf32_ss(uint32_t d_tmem, uint64_t a_desc, uint64_t b_desc,
                                            uint32_t idesc, bool accum) {
    uint32_t en = accum ? 1u : 0u;
    asm volatile("{\n\t.reg .pred p;\n\tsetp.ne.u32 p, %5, 0;\n\t"
                 "tcgen05.mma.cta_group::1.kind::tf32 [%0], %1, %2, %3, {%4, %4, %4, %4}, p;\n\t}"
                 :: "r"(d_tmem), "l"(a_desc), "l"(b_desc), "r"(idesc), "r"(0u), "r"(en)
                 : "memory");
}
#endif // USE_TCGEN05

// SW128 K-major SMEM descriptor base: layout=SW128(2), version=1, SBO=64, LBO=1
static constexpr uint64_t DESC_BASE_SW128 =
    (uint64_t(2) << 61) | (uint64_t(1) << 46) | (uint64_t(64) << 32) | (uint64_t(1) << 16);

// idesc: D=F32, A=TF32, B=TF32, N=128, M=128, K-major both
#define IDESC_TF32 0x8200910u

// ---------------------------------------------------------------------------
// fast activations: tanh.approx.f32 (single MUFU), sigmoid via tanh identity
// ---------------------------------------------------------------------------
__device__ __forceinline__ float tanh_fast(float v) {
    float r;
    asm("tanh.approx.f32 %0, %1;" : "=f"(r) : "f"(v));
    return r;
}
__device__ __forceinline__ float sigmoid_fast(float v) {
    return fmaf(tanh_fast(0.5f * v), 0.5f, 0.5f);
}
__device__ __forceinline__ float lstm_h(float iv, float gv, float ov) {
    float c = sigmoid_fast(iv) * tanh_fast(gv);
    return sigmoid_fast(ov) * tanh_fast(c);
}

// byte offset (incl. SW128 swizzle) for K-major blocked-atom layout, one
// 128-row block of 128B rows: atom = 8 rows x 32 fp32; 16 atom-rows x atom-cols
__device__ __forceinline__ uint32_t kmaj_off(int row, int col) {
    uint32_t b = (uint32_t)((row >> 3) + (col >> 5) * 16) * 1024u
               + (uint32_t)(row & 7) * 128u + (uint32_t)(col & 31) * 4u;
    return b ^ ((b >> 3) & 0x70);
}

// ---- shared memory layout (bytes, from 1024-aligned base) -----------------
#define OFF_TMEMPTR 0
#define OFF_MBAR    8
#define OFF_B1      16                        // 128 f
#define OFF_W2      528                       // 128 f
#define OFF_PART    1040                      // 1024 f (2 blk x 4 q x 128) -> 5136
#define OFF_F       6144                      // 2 x 16 KB = 32 KB
#define OFF_WIHB    38912                     // 3 x 16 KB = 48 KB
#define OFF_W1      88064                     // 64 KB
#define OFF_H       153600                    // 64 KB -> 219136
#define SMEM_BYTES  (219136 + 1024)

__global__ __launch_bounds__(NTH, 1)
void ps_lstm_kernel(
    const float* __restrict__ x,   const float* __restrict__ x1,  const float* __restrict__ x2,
    const float* __restrict__ z1,  const float* __restrict__ z2,
    const float* __restrict__ x1E, const float* __restrict__ x2E,
    const float* __restrict__ z1E, const float* __restrict__ z2E,
    const float* __restrict__ muB, const float* __restrict__ lb,  const float* __restrict__ ub,
    const float* __restrict__ W_ih, const float* __restrict__ b_ih, const float* __restrict__ b_hh,
    const float* __restrict__ W1,  const float* __restrict__ b1,
    const float* __restrict__ W2,  const float* __restrict__ b2,
    float* __restrict__ out)
{
    extern __shared__ unsigned char smraw[];
    const uint32_t rawa = smem_u32(smraw);
    const uint32_t base = (rawa + 1023u) & ~1023u;
    unsigned char* smb = smraw + (base - rawa);

    float* sb1   = (float*)(smb + OFF_B1);
    float* sW2   = (float*)(smb + OFF_W2);
    float* sPart = (float*)(smb + OFF_PART);

    const int tid  = threadIdx.x;
    const int warp = tid >> 5, lane = tid & 31;
    const int rowbase = blockIdx.x * TILE;

    // ---- preload: W_ih^T (+bias as feature col 12) into K-major SW128 -----
    // channel j (0..383): j<128 -> i-gate row j; 128..255 -> g row j+128;
    // 256..383 -> o row j+128. Merged features {0+5,1,2,3+6,4+7,8..14}.
    for (int j = tid; j < 384; j += NTH) {
        int row = (j < 128) ? j : j + 128;
        const float* wr = W_ih + row * 15;
        uint32_t blk = (uint32_t)(j >> 7) * 16384u + (uint32_t)OFF_WIHB;
        int jr = j & 127;
        *(float*)(smb + blk + kmaj_off(jr, 0))  = wr[0] + wr[5];
        *(float*)(smb + blk + kmaj_off(jr, 1))  = wr[1];
        *(float*)(smb + blk + kmaj_off(jr, 2))  = wr[2];
        *(float*)(smb + blk + kmaj_off(jr, 3))  = wr[3] + wr[6];
        *(float*)(smb + blk + kmaj_off(jr, 4))  = wr[4] + wr[7];
        #pragma unroll
        for (int k = 5; k < 12; ++k)
            *(float*)(smb + blk + kmaj_off(jr, k)) = wr[k + 3];
        *(float*)(smb + blk + kmaj_off(jr, 12)) = b_ih[row] + b_hh[row];
        *(float*)(smb + blk + kmaj_off(jr, 13)) = 0.0f;
        *(float*)(smb + blk + kmaj_off(jr, 14)) = 0.0f;
        *(float*)(smb + blk + kmaj_off(jr, 15)) = 0.0f;
    }
    // W1 -> swizzled K-major blocked layout, float4 (swizzle is 16B-granular)
    for (int i = tid; i < 4096; i += NTH) {
        int r = i >> 5, c4 = (i & 31) * 4;
        float4 v = *(const float4*)(W1 + r * 128 + c4);
        *(float4*)(smb + OFF_W1 + kmaj_off(r, c4)) = v;
    }
    if (tid < 128) { sb1[tid] = b1[tid]; sW2[tid] = W2[tid]; }

    // ---- feature build: F[2 blocks][128 rows, 16 K], col12 = 1 (bias) -----
    {
        const int r256 = tid & 255;
        const int half = tid >> 8;
        const int row  = rowbase + r256;
        const int rr   = r256 & 127;
        const uint32_t fb = (uint32_t)OFF_F + (uint32_t)(r256 >> 7) * 16384u;
        float mu  = muB[row >> 11];
        float x1v = x1[row], x2v = x2[row];
        float z1v = z1[row], z2v = z2[row];
        float z1m = (z1v + mu <= 0.0f) ? 0.0f : z1v;
        float z2m = (z2v + mu <= 0.0f) ? 0.0f : z2v;
        if (half == 0) {
            float xv = x[row];
            *(float4*)(smb + fb + kmaj_off(rr, 0)) = make_float4(xv, x1v, x2v, z1m);
            *(float4*)(smb + fb + kmaj_off(rr, 4)) = make_float4(z2m, x1E[row], x2E[row], z1E[row]);
        } else {
            float iD1 = fminf(fmaxf(__fdividef(z1m + mu, x1v + mu + 1e-12f), 0.0f), 100.0f);
            float iD2 = fminf(fmaxf(__fdividef(z2m + mu, x2v + mu + 1e-12f), 0.0f), 100.0f);
            *(float4*)(smb + fb + kmaj_off(rr, 8))  = make_float4(z2E[row], mu, iD1, iD2);
            *(float4*)(smb + fb + kmaj_off(rr, 12)) = make_float4(1.0f, 0.0f, 0.0f, 0.0f);
        }
    }

#if USE_TCGEN05
    if (warp == 0) { TCGEN05_ALLOC(base + OFF_TMEMPTR, 512); TCGEN05_RELINQ(); }
    if (tid == 0)  { MBARRIER_INIT(base + OFF_MBAR, 1); }
#endif
    FENCE_PROXY_ASYNC();
    __syncthreads();

#if USE_TCGEN05
    uint32_t tmem;
    asm volatile("ld.shared.b32 %0, [%1];" : "=r"(tmem) : "r"(base + OFF_TMEMPTR));

    const uint64_t fdA = DESC_BASE_SW128 | ((uint64_t)((base + OFF_F)           >> 4) & 0x3FFF);
    const uint64_t fdB = DESC_BASE_SW128 | ((uint64_t)((base + OFF_F + 16384u)  >> 4) & 0x3FFF);
    const uint64_t wd  = DESC_BASE_SW128 | ((uint64_t)((base + OFF_WIHB)        >> 4) & 0x3FFF);
    const uint64_t hd  = DESC_BASE_SW128 | ((uint64_t)((base + OFF_H)           >> 4) & 0x3FFF);
    const uint64_t w1d = DESC_BASE_SW128 | ((uint64_t)((base + OFF_W1)          >> 4) & 0x3FFF);

    const int sp = warp & 3;           // TMEM subpartition (rows sp*32..+31)
    const int qu = warp >> 2;          // col quarter 0..3
    const int trow = sp * 32 + lane;

    // ---- commit#1: MMA1(A)  gates_A -> cols 0..383 ------------------------
    if (warp == 0 && elect_one_pred()) {
        #pragma unroll
        for (int nb = 0; nb < 3; ++nb)
            #pragma unroll
            for (int s = 0; s < 2; ++s)
                mma_tf32_ss(tmem + nb * 128, fdA + s * 2, wd + nb * 1024u + s * 2,
                            IDESC_TF32, s > 0);
        TCGEN05_COMMIT(base + OFF_MBAR);
    }
    MBARRIER_WAIT_PARITY(base + OFF_MBAR, 0);
    TCGEN05_FENCE_AFTER();

    // ---- gate-epi(A): 16 units (sp x quarter), 2 x 16-col chunks ---------
    #pragma unroll
    for (int hh = 0; hh < 2; ++hh) {
        const int c = qu * 32 + hh * 16;
        uint32_t vi[16], vg[16], vo[16];
        TCGEN05_LD_32X32B_X16(vi, tmem + c);
        TCGEN05_LD_32X32B_X16(vg, tmem + 128 + c);
        TCGEN05_LD_32X32B_X16(vo, tmem + 256 + c);
        TCGEN05_WAIT_LD();
        #pragma unroll
        for (int u = 0; u < 4; ++u) {
            float4 hv;
            hv.x = lstm_h(__uint_as_float(vi[4*u+0]), __uint_as_float(vg[4*u+0]), __uint_as_float(vo[4*u+0]));
            hv.y = lstm_h(__uint_as_float(vi[4*u+1]), __uint_as_float(vg[4*u+1]), __uint_as_float(vo[4*u+1]));
            hv.z = lstm_h(__uint_as_float(vi[4*u+2]), __uint_as_float(vg[4*u+2]), __uint_as_float(vo[4*u+2]));
            hv.w = lstm_h(__uint_as_float(vi[4*u+3]), __uint_as_float(vg[4*u+3]), __uint_as_float(vo[4*u+3]));
            *(float4*)(smb + OFF_H + kmaj_off(trow, c + 4 * u)) = hv;
        }
    }
    TCGEN05_FENCE_BEFORE();
    FENCE_PROXY_ASYNC();
    __syncthreads();

    // ---- commit#2: MMA2(A) -> cols 384..511  +  MMA1(B) -> cols 0..383 ----
    if (warp == 0 && elect_one_pred()) {
        #pragma unroll
        for (int s = 0; s < 16; ++s) {
            uint32_t off = (uint32_t)(s >> 2) * 1024u + (uint32_t)(s & 3) * 2u;
            mma_tf32_ss(tmem + 384, hd + off, w1d + off, IDESC_TF32, s > 0);
        }
        #pragma unroll
        for (int nb = 0; nb < 3; ++nb)
            #pragma unroll
            for (int s = 0; s < 2; ++s)
                mma_tf32_ss(tmem + nb * 128, fdB + s * 2, wd + nb * 1024u + s * 2,
                            IDESC_TF32, s > 0);
        TCGEN05_COMMIT(base + OFF_MBAR);
    }
    MBARRIER_WAIT_PARITY(base + OFF_MBAR, 1);
    TCGEN05_FENCE_AFTER();

    // ---- gate-epi(B) -> H  (MMA2(A) done, H reusable) ---------------------
    #pragma unroll
    for (int hh = 0; hh < 2; ++hh) {
        const int c = qu * 32 + hh * 16;
        uint32_t vi[16], vg[16], vo[16];
        TCGEN05_LD_32X32B_X16(vi, tmem + c);
        TCGEN05_LD_32X32B_X16(vg, tmem + 128 + c);
        TCGEN05_LD_32X32B_X16(vo, tmem + 256 + c);
        TCGEN05_WAIT_LD();
        #pragma unroll
        for (int u = 0; u < 4; ++u) {
            float4 hv;
            hv.x = lstm_h(__uint_as_float(vi[4*u+0]), __uint_as_float(vg[4*u+0]), __uint_as_float(vo[4*u+0]));
            hv.y = lstm_h(__uint_as_float(vi[4*u+1]), __uint_as_float(vg[4*u+1]), __uint_as_float(vo[4*u+1]));
            hv.z = lstm_h(__uint_as_float(vi[4*u+2]), __uint_as_float(vg[4*u+2]), __uint_as_float(vo[4*u+2]));
            hv.w = lstm_h(__uint_as_float(vi[4*u+3]), __uint_as_float(vg[4*u+3]), __uint_as_float(vo[4*u+3]));
            *(float4*)(smb + OFF_H + kmaj_off(trow, c + 4 * u)) = hv;
        }
    }
    // ---- head-epi(A): relu(D2_A + b1) . W2 per quarter --------------------
    {
        const int cb = qu * 32;
        uint32_t d0[32];
        TCGEN05_LD_32X32B_X32(d0, tmem + 384 + cb);
        TCGEN05_WAIT_LD();
        float s = 0.0f;
        #pragma unroll
        for (int r = 0; r < 32; ++r)
            s = fmaf(fmaxf(__uint_as_float(d0[r]) + sb1[cb + r], 0.0f), sW2[cb + r], s);
        sPart[qu * 128 + trow] = s;
    }
    TCGEN05_FENCE_BEFORE();
    FENCE_PROXY_ASYNC();
    __syncthreads();

    // ---- commit#3: MMA2(B) -> cols 384..511 -------------------------------
    if (warp == 0 && elect_one_pred()) {
        #pragma unroll
        for (int s = 0; s < 16; ++s) {
            uint32_t off = (uint32_t)(s >> 2) * 1024u + (uint32_t)(s & 3) * 2u;
            mma_tf32_ss(tmem + 384, hd + off, w1d + off, IDESC_TF32, s > 0);
        }
        TCGEN05_COMMIT(base + OFF_MBAR);
    }
    MBARRIER_WAIT_PARITY(base + OFF_MBAR, 0);
    TCGEN05_FENCE_AFTER();

    // ---- head-epi(B) ------------------------------------------------------
    {
        const int cb = qu * 32;
        uint32_t d0[32];
        TCGEN05_LD_32X32B_X32(d0, tmem + 384 + cb);
        TCGEN05_WAIT_LD();
        float s = 0.0f;
        #pragma unroll
        for (int r = 0; r < 32; ++r)
            s = fmaf(fmaxf(__uint_as_float(d0[r]) + sb1[cb + r], 0.0f), sW2[cb + r], s);
        sPart[512 + qu * 128 + trow] = s;
        TCGEN05_FENCE_BEFORE();
    }
    __syncthreads();
#else
    // ---- PTX-pass fallback: scalar gates + head, block-sequential ---------
    for (int t = 0; t < 2; ++t) {
        if (tid < 128) {
            const int r = tid;
            const uint32_t fb = (uint32_t)OFF_F + (uint32_t)t * 16384u;
            float f[13];
            #pragma unroll
            for (int k = 0; k < 13; ++k)
                f[k] = *(const float*)(smb + fb + kmaj_off(r, k));
            for (int j = 0; j < 128; ++j) {
                float a[3];
                #pragma unroll
                for (int gidx = 0; gidx < 3; ++gidx) {
                    uint32_t blk = (uint32_t)gidx * 16384u + (uint32_t)OFF_WIHB;
                    float acc = 0.0f;
                    #pragma unroll
                    for (int k = 0; k < 13; ++k)
                        acc = fmaf(f[k], *(const float*)(smb + blk + kmaj_off(j, k)), acc);
                    a[gidx] = acc;
                }
                *(float*)(smb + OFF_H + kmaj_off(r, j)) = lstm_h(a[0], a[1], a[2]);
            }
        }
        __syncthreads();
        if (tid < 128) {
            const int r = tid;
            float s = 0.0f;
            for (int j = 0; j < 128; ++j) {
                float acc = sb1[j];
                #pragma unroll 8
                for (int k4 = 0; k4 < 32; ++k4) {
                    const float4 hv = *(const float4*)(smb + OFF_H  + kmaj_off(r, 4 * k4));
                    const float4 wv = *(const float4*)(smb + OFF_W1 + kmaj_off(j, 4 * k4));
                    acc = fmaf(hv.x, wv.x, fmaf(hv.y, wv.y, fmaf(hv.z, wv.z, fmaf(hv.w, wv.w, acc))));
                }
                s = fmaf(fmaxf(acc, 0.0f), sW2[j], s);
            }
            sPart[t * 512 + r]       = s;
            sPart[t * 512 + 128 + r] = 0.0f;
            sPart[t * 512 + 256 + r] = 0.0f;
            sPart[t * 512 + 384 + r] = 0.0f;
        }
        __syncthreads();
    }
#endif

    // ---- Stage C: elementwise updates + output ----------------------------
    if (tid < TILE) {
        const int row = rowbase + tid;
        const int t = tid >> 7, rb = tid & 127;
        const int b = row >> 11, n = row & (NDIM - 1);
        float mu  = muB[b];
        float xv  = x[row],  x1v = x1[row], x2v = x2[row];
        float z1v = z1[row], z2v = z2[row];
        float z1m = (z1v + mu <= 0.0f) ? 0.0f : z1v;
        float z2m = (z2v + mu <= 0.0f) ? 0.0f : z2v;
        float iD1 = fminf(fmaxf(__fdividef(z1m + mu, x1v + mu + 1e-12f), 0.0f), 100.0f);
        float iD2 = fminf(fmaxf(__fdividef(z2m + mu, x2v + mu + 1e-12f), 0.0f), 100.0f);
        float p  = fabsf(sPart[t * 512 + rb] + sPart[t * 512 + 128 + rb]
                       + sPart[t * 512 + 256 + rb] + sPart[t * 512 + 384 + rb] + b2[0]);
        float d  = -p * xv;
        float xn = xv + d;
        float z1o = z1m - iD1 * (d + z1m);
        float z2o = z2m - iD2 * (-d + z2m);
        float x1o = xn - lb[row];
        float x2o = ub[row] - xn;
        size_t ob = (size_t)b * (5 * NDIM) + n;
        out[ob]            = xn;
        out[ob +     NDIM] = x1o;
        out[ob + 2 * NDIM] = x2o;
        out[ob + 3 * NDIM] = z1o;
        out[ob + 4 * NDIM] = z2o;
    }

#if USE_TCGEN05
    if (tid == 0) MBARRIER_INVAL(base + OFF_MBAR);
    if (warp == 0) TCGEN05_DEALLOC(tmem, 512);
#endif
}

// ---------------------------------------------------------------------------
// metadata order:
//  0 x  1 x1  2 x2  3 z1  4 z2  5 x1E  6 x2E  7 z1E  8 z2E  9 muB  10 lb 11 ub
// 12 has_lb 13 has_ub 14 W_ih 15 W_hh(unused) 16 b_ih 17 b_hh 18 W1 19 b1 20 W2 21 b2
// ---------------------------------------------------------------------------
extern "C" void kernel_launch(void* const* d_in, const int* in_sizes, int n_in,
                              void* d_out, int out_size) {
    (void)in_sizes; (void)n_in; (void)out_size;
    const float* x    = (const float*)d_in[0];
    const float* x1   = (const float*)d_in[1];
    const float* x2   = (const float*)d_in[2];
    const float* z1   = (const float*)d_in[3];
    const float* z2   = (const float*)d_in[4];
    const float* x1E  = (const float*)d_in[5];
    const float* x2E  = (const float*)d_in[6];
    const float* z1E  = (const float*)d_in[7];
    const float* z2E  = (const float*)d_in[8];
    const float* muB  = (const float*)d_in[9];
    const float* lb   = (const float*)d_in[10];
    const float* ub   = (const float*)d_in[11];
    const float* W_ih = (const float*)d_in[14];
    const float* b_ih = (const float*)d_in[16];
    const float* b_hh = (const float*)d_in[17];
    const float* W1   = (const float*)d_in[18];
    const float* b1   = (const float*)d_in[19];
    const float* W2   = (const float*)d_in[20];
    const float* b2   = (const float*)d_in[21];

    cudaFuncSetAttribute(ps_lstm_kernel, cudaFuncAttributeMaxDynamicSharedMemorySize, SMEM_BYTES);

    const int rows = 128 * NDIM;           // 262144
    const int grid = rows / TILE;          // 1024
    ps_lstm_kernel<<<grid, NTH, SMEM_BYTES>>>(
        x, x1, x2, z1, z2, x1E, x2E, z1E, z2E, muB, lb, ub,
        W_ih, b_ih, b_hh, W1, b1, W2, b2, (float*)d_out);
}

// round 15
// speedup vs baseline: 6.7565x; 1.3166x over previous
#include <cuda_runtime.h>
#include <cstdint>

#define NDIM   2048
#define TILE   256
#define NTH    512
#define NTILES 1024

// ---------------------------------------------------------------------------
// tcgen05 is an architecture-SPECIFIC ('a') feature. The harness also compiles
// a plain compute_103 PTX pass where these instructions don't exist, so every
// tcgen05 usage is gated and a plain-FMA fallback covers the PTX pass.
// ---------------------------------------------------------------------------
#if defined(__CUDA_ARCH__) && (defined(__CUDA_ARCH_FEAT_SM103_ALL) || \
    defined(__CUDA_ARCH_FEAT_SM100_ALL) || defined(__CUDA_ARCH_SPECIFIC__))
#define USE_TCGEN05 1
#else
#define USE_TCGEN05 0
#endif

// ---------------------------------------------------------------------------
// PTX helpers
// ---------------------------------------------------------------------------
__device__ __forceinline__ uint32_t elect_one_pred() {
    uint32_t pred;
    asm volatile("{\n\t.reg .pred p;\n\telect.sync _|p, 0xFFFFFFFF;\n\tselp.b32 %0, 1, 0, p;\n\t}"
                 : "=r"(pred));
    return pred;
}
__device__ __forceinline__ uint32_t smem_u32(const void* p) {
    uint32_t a;
    asm("{ .reg .u64 t; cvta.to.shared.u64 t, %1; cvt.u32.u64 %0, t; }" : "=r"(a) : "l"(p));
    return a;
}

#define MBARRIER_INIT(mbar, count) \
    asm volatile("mbarrier.init.shared.b64 [%0], %1;" \
                 :: "r"((uint32_t)(mbar)), "r"((uint32_t)(count)) : "memory")
#define MBARRIER_INVAL(mbar) \
    asm volatile("mbarrier.inval.shared.b64 [%0];" :: "r"((uint32_t)(mbar)) : "memory")
#define MBARRIER_WAIT_PARITY(mbar, parity) do { \
    uint32_t _m = (uint32_t)(mbar); uint32_t _p = (uint32_t)(parity); uint32_t _d; \
    asm volatile("{\n\t.reg .pred p;\n\t" \
        "mbarrier.try_wait.parity.acquire.cta.shared::cta.b64 p, [%1], %2;\n\t" \
        "selp.b32 %0, 1, 0, p;\n\t}" : "=r"(_d) : "r"(_m), "r"(_p) : "memory"); \
    if (!_d) { \
        asm volatile("{\n\t.reg .pred P1;\n\t" \
            "WL_%=:\n\t" \
            "mbarrier.try_wait.parity.acquire.cta.shared::cta.b64 P1, [%0], %1, 0x989680;\n\t" \
            "@P1 bra.uni WD_%=;\n\t" \
            "bra.uni WL_%=;\n\t" \
            "WD_%=:\n\t}" :: "r"(_m), "r"(_p) : "memory"); \
    } } while (0)

#define FENCE_PROXY_ASYNC()    asm volatile("fence.proxy.async.shared::cta;" ::: "memory")

#if USE_TCGEN05
#define TCGEN05_ALLOC(smem_result_addr, nCols) \
    asm volatile("tcgen05.alloc.cta_group::1.sync.aligned.shared::cta.b32 [%0], %1;" \
                 :: "r"((uint32_t)(smem_result_addr)), "r"((uint32_t)(nCols)) : "memory")
#define TCGEN05_DEALLOC(tmem_addr, nCols) \
    asm volatile("tcgen05.dealloc.cta_group::1.sync.aligned.b32 %0, %1;" \
                 :: "r"(tmem_addr), "r"((uint32_t)(nCols)))
#define TCGEN05_RELINQ() \
    asm volatile("tcgen05.relinquish_alloc_permit.cta_group::1.sync.aligned;")
#define TCGEN05_COMMIT(mbar) \
    asm volatile("tcgen05.commit.cta_group::1.mbarrier::arrive::one.shared::cluster.b64 [%0];" \
                 :: "r"((uint32_t)(mbar)) : "memory")
#define TCGEN05_FENCE_AFTER()  asm volatile("tcgen05.fence::after_thread_sync;" ::: "memory")
#define TCGEN05_FENCE_BEFORE() asm volatile("tcgen05.fence::before_thread_sync;" ::: "memory")
#define TCGEN05_WAIT_LD()      asm volatile("tcgen05.wait::ld.sync.aligned;" ::: "memory")

#define TCGEN05_LD_32X32B_X16(r, tmem_addr) \
    asm volatile("tcgen05.ld.sync.aligned.32x32b.x16.b32 " \
        "{%0, %1, %2, %3, %4, %5, %6, %7, %8, %9, %10, %11, %12, %13, %14, %15}, [%16];" \
        : "=r"((r)[0]),  "=r"((r)[1]),  "=r"((r)[2]),  "=r"((r)[3]), \
          "=r"((r)[4]),  "=r"((r)[5]),  "=r"((r)[6]),  "=r"((r)[7]), \
          "=r"((r)[8]),  "=r"((r)[9]),  "=r"((r)[10]), "=r"((r)[11]), \
          "=r"((r)[12]), "=r"((r)[13]), "=r"((r)[14]), "=r"((r)[15]) \
        : "r"(tmem_addr))

#define TCGEN05_LD_32X32B_X32(r, tmem_addr) \
    asm volatile("tcgen05.ld.sync.aligned.32x32b.x32.b32 " \
        "{%0, %1, %2, %3, %4, %5, %6, %7, %8, %9, %10, %11, %12, %13, %14, %15, " \
        " %16, %17, %18, %19, %20, %21, %22, %23, %24, %25, %26, %27, %28, %29, %30, %31}, [%32];" \
        : "=r"((r)[0]),  "=r"((r)[1]),  "=r"((r)[2]),  "=r"((r)[3]), \
          "=r"((r)[4]),  "=r"((r)[5]),  "=r"((r)[6]),  "=r"((r)[7]), \
          "=r"((r)[8]),  "=r"((r)[9]),  "=r"((r)[10]), "=r"((r)[11]), \
          "=r"((r)[12]), "=r"((r)[13]), "=r"((r)[14]), "=r"((r)[15]), \
          "=r"((r)[16]), "=r"((r)[17]), "=r"((r)[18]), "=r"((r)[19]), \
          "=r"((r)[20]), "=r"((r)[21]), "=r"((r)[22]), "=r"((r)[23]), \
          "=r"((r)[24]), "=r"((r)[25]), "=r"((r)[26]), "=r"((r)[27]), \
          "=r"((r)[28]), "=r"((r)[29]), "=r"((r)[30]), "=r"((r)[31]) \
        : "r"(tmem_addr))

// SS-form tf32 MMA, cta_group::1. fp32 data in SMEM; HW rounds to tf32.
__device__ __forceinline__ void mma_tf32_ss(uint32_t d_tmem, uint64_t a_desc, uint64_t b_desc,
                                            uint32_t idesc, bool accum) {
    uint32_t en = accum ? 1u : 0u;
    asm volatile("{\n\t.reg .pred p;\n\tsetp.ne.u32 p, %5, 0;\n\t"
                 "tcgen05.mma.cta_group::1.kind::tf32 [%0], %1, %2, %3, {%4, %4, %4, %4}, p;\n\t}"
                 :: "r"(d_tmem), "l"(a_desc), "l"(b_desc), "r"(idesc), "r"(0u), "r"(en)
                 : "memory");
}
#endif // USE_TCGEN05

// SW128 K-major SMEM descriptor base: layout=SW128(2), version=1, SBO=64, LBO=1
static constexpr uint64_t DESC_BASE_SW128 =
    (uint64_t(2) << 61) | (uint64_t(1) << 46) | (uint64_t(64) << 32) | (uint64_t(1) << 16);

// idesc: D=F32, A=TF32, B=TF32, N=128, M=128, K-major both
#define IDESC_TF32 0x8200910u

// ---------------------------------------------------------------------------
// fast activations
// ---------------------------------------------------------------------------
__device__ __forceinline__ float tanh_fast(float v) {
    float r;
    asm("tanh.approx.f32 %0, %1;" : "=f"(r) : "f"(v));
    return r;
}
__device__ __forceinline__ float sigmoid_fast(float v) {
    return fmaf(tanh_fast(0.5f * v), 0.5f, 0.5f);
}
__device__ __forceinline__ float lstm_h(float iv, float gv, float ov) {
    float c = sigmoid_fast(iv) * tanh_fast(gv);
    return sigmoid_fast(ov) * tanh_fast(c);
}

// byte offset (incl. SW128 swizzle), K-major blocked-atom, 128-row block
__device__ __forceinline__ uint32_t kmaj_off(int row, int col) {
    uint32_t b = (uint32_t)((row >> 3) + (col >> 5) * 16) * 1024u
               + (uint32_t)(row & 7) * 128u + (uint32_t)(col & 31) * 4u;
    return b ^ ((b >> 3) & 0x70);
}

// ---- shared memory layout (bytes, from 1024-aligned base) -----------------
#define OFF_TMEMPTR 0
#define OFF_MBAR    8
#define OFF_B1      16
#define OFF_W2      528
#define OFF_PART    1040                      // 1024 f
#define OFF_F       6144                      // 2 x 16 KB
#define OFF_WIHB    38912                     // 3 x 16 KB
#define OFF_W1      88064                     // 64 KB
#define OFF_H       153600                    // 64 KB -> 219136
#define SMEM_BYTES  (219136 + 1024)

__global__ __launch_bounds__(NTH, 1)
void ps_lstm_kernel(
    const float* __restrict__ x,   const float* __restrict__ x1,  const float* __restrict__ x2,
    const float* __restrict__ z1,  const float* __restrict__ z2,
    const float* __restrict__ x1E, const float* __restrict__ x2E,
    const float* __restrict__ z1E, const float* __restrict__ z2E,
    const float* __restrict__ muB, const float* __restrict__ lb,  const float* __restrict__ ub,
    const float* __restrict__ W_ih, const float* __restrict__ b_ih, const float* __restrict__ b_hh,
    const float* __restrict__ W1,  const float* __restrict__ b1,
    const float* __restrict__ W2,  const float* __restrict__ b2,
    float* __restrict__ out)
{
    extern __shared__ unsigned char smraw[];
    const uint32_t rawa = smem_u32(smraw);
    const uint32_t base = (rawa + 1023u) & ~1023u;
    unsigned char* smb = smraw + (base - rawa);

    float* sb1   = (float*)(smb + OFF_B1);
    float* sW2   = (float*)(smb + OFF_W2);
    float* sPart = (float*)(smb + OFF_PART);

    const int tid  = threadIdx.x;
    const int warp = tid >> 5, lane = tid & 31;
    const int r256 = tid & 255, half = tid >> 8;
    const int rr   = r256 & 127;
    const uint32_t fb = (uint32_t)OFF_F + (uint32_t)(r256 >> 7) * 16384u;
    const float b2v = b2[0];

    // ---- one-time preload: W_ih^T (+bias col 12) & W1, K-major SW128 ------
    for (int j = tid; j < 384; j += NTH) {
        int row = (j < 128) ? j : j + 128;
        const float* wr = W_ih + row * 15;
        uint32_t blk = (uint32_t)(j >> 7) * 16384u + (uint32_t)OFF_WIHB;
        int jr = j & 127;
        *(float*)(smb + blk + kmaj_off(jr, 0))  = wr[0] + wr[5];
        *(float*)(smb + blk + kmaj_off(jr, 1))  = wr[1];
        *(float*)(smb + blk + kmaj_off(jr, 2))  = wr[2];
        *(float*)(smb + blk + kmaj_off(jr, 3))  = wr[3] + wr[6];
        *(float*)(smb + blk + kmaj_off(jr, 4))  = wr[4] + wr[7];
        #pragma unroll
        for (int k = 5; k < 12; ++k)
            *(float*)(smb + blk + kmaj_off(jr, k)) = wr[k + 3];
        *(float*)(smb + blk + kmaj_off(jr, 12)) = b_ih[row] + b_hh[row];
        *(float*)(smb + blk + kmaj_off(jr, 13)) = 0.0f;
        *(float*)(smb + blk + kmaj_off(jr, 14)) = 0.0f;
        *(float*)(smb + blk + kmaj_off(jr, 15)) = 0.0f;
    }
    for (int i = tid; i < 4096; i += NTH) {
        int r = i >> 5, c4 = (i & 31) * 4;
        float4 v = *(const float4*)(W1 + r * 128 + c4);
        *(float4*)(smb + OFF_W1 + kmaj_off(r, c4)) = v;
    }
    if (tid < 128) { sb1[tid] = b1[tid]; sW2[tid] = W2[tid]; }

#if USE_TCGEN05
    if (warp == 0) { TCGEN05_ALLOC(base + OFF_TMEMPTR, 512); TCGEN05_RELINQ(); }
    if (tid == 0)  { MBARRIER_INIT(base + OFF_MBAR, 1); }
#endif

    const int STR = gridDim.x;
    int tile = blockIdx.x;
    if (tile >= NTILES) return;    // (never with grid<=NTILES)

    // ---- Stage-C register carries ----------------------------------------
    float c_xv = 0.f, c_lb = 0.f, c_ub = 0.f;
    float c_z1m = 0.f, c_z2m = 0.f, c_iD1 = 0.f, c_iD2 = 0.f;

    // ---- prologue: load + store F + carries for first tile ----------------
    {
        const int row = tile * TILE + r256;
        const float mu = muB[tile >> 3];
        float a1 = x1[row], a2 = x2[row], v1 = z1[row], v2 = z2[row];
        float xv = x[row];
        float z1m = (v1 + mu <= 0.0f) ? 0.0f : v1;
        float z2m = (v2 + mu <= 0.0f) ? 0.0f : v2;
        if (half == 0) {
            c_xv = xv; c_lb = lb[row]; c_ub = ub[row];
            *(float4*)(smb + fb + kmaj_off(rr, 0)) = make_float4(xv, a1, a2, z1m);
            *(float4*)(smb + fb + kmaj_off(rr, 4)) = make_float4(z2m, x1E[row], x2E[row], z1E[row]);
        } else {
            float iD1 = fminf(fmaxf(__fdividef(z1m + mu, a1 + mu + 1e-12f), 0.0f), 100.0f);
            float iD2 = fminf(fmaxf(__fdividef(z2m + mu, a2 + mu + 1e-12f), 0.0f), 100.0f);
            c_xv = xv; c_z1m = z1m; c_z2m = z2m; c_iD1 = iD1; c_iD2 = iD2;
            *(float4*)(smb + fb + kmaj_off(rr, 8))  = make_float4(z2E[row], mu, iD1, iD2);
            *(float4*)(smb + fb + kmaj_off(rr, 12)) = make_float4(1.0f, 0.0f, 0.0f, 0.0f);
        }
    }

#if USE_TCGEN05
    uint32_t tmem;
    {
        FENCE_PROXY_ASYNC(); __syncthreads();
        asm volatile("ld.shared.b32 %0, [%1];" : "=r"(tmem) : "r"(base + OFF_TMEMPTR));
    }
    const uint64_t fdA = DESC_BASE_SW128 | ((uint64_t)((base + OFF_F)          >> 4) & 0x3FFF);
    const uint64_t fdB = DESC_BASE_SW128 | ((uint64_t)((base + OFF_F + 16384u) >> 4) & 0x3FFF);
    const uint64_t wd  = DESC_BASE_SW128 | ((uint64_t)((base + OFF_WIHB)       >> 4) & 0x3FFF);
    const uint64_t hd  = DESC_BASE_SW128 | ((uint64_t)((base + OFF_H)          >> 4) & 0x3FFF);
    const uint64_t w1d = DESC_BASE_SW128 | ((uint64_t)((base + OFF_W1)         >> 4) & 0x3FFF);

    const int sp = warp & 3, qu = warp >> 2;
    const int trow = sp * 32 + lane;
    int ph = 0;

    for (; tile < NTILES; tile += STR) {
        const int next = tile + STR;
        const bool hn = next < NTILES;

        // ---- commit#1: MMA1(A) gates_A -> cols 0..383 ---------------------
        if (warp == 0 && elect_one_pred()) {
            #pragma unroll
            for (int nb = 0; nb < 3; ++nb)
                #pragma unroll
                for (int s = 0; s < 2; ++s)
                    mma_tf32_ss(tmem + nb * 128, fdA + s * 2, wd + nb * 1024u + s * 2,
                                IDESC_TF32, s > 0);
            TCGEN05_COMMIT(base + OFF_MBAR);
        }

        // ---- prefetch next tile's inputs (hidden under c1/c2 waits) -------
        float n_x1 = 0.f, n_x2 = 0.f, n_z1 = 0.f, n_z2 = 0.f, n_xv = 0.f, n_mu = 0.f;
        float n_e1 = 0.f, n_e2 = 0.f, n_e3 = 0.f, n_e4 = 0.f, n_lb = 0.f, n_ub = 0.f;
        if (hn) {
            const int row = next * TILE + r256;
            n_mu = muB[next >> 3];
            n_x1 = x1[row]; n_x2 = x2[row]; n_z1 = z1[row]; n_z2 = z2[row];
            n_xv = x[row];
            if (half == 0) {
                n_e1 = x1E[row]; n_e2 = x2E[row]; n_e3 = z1E[row];
                n_lb = lb[row];  n_ub = ub[row];
            } else {
                n_e4 = z2E[row];
            }
        }

        MBARRIER_WAIT_PARITY(base + OFF_MBAR, ph);
        TCGEN05_FENCE_AFTER();

        // ---- gate-epi(A) -> H ---------------------------------------------
        #pragma unroll
        for (int hh = 0; hh < 2; ++hh) {
            const int c = qu * 32 + hh * 16;
            uint32_t vi[16], vg[16], vo[16];
            TCGEN05_LD_32X32B_X16(vi, tmem + c);
            TCGEN05_LD_32X32B_X16(vg, tmem + 128 + c);
            TCGEN05_LD_32X32B_X16(vo, tmem + 256 + c);
            TCGEN05_WAIT_LD();
            #pragma unroll
            for (int u = 0; u < 4; ++u) {
                float4 hv;
                hv.x = lstm_h(__uint_as_float(vi[4*u+0]), __uint_as_float(vg[4*u+0]), __uint_as_float(vo[4*u+0]));
                hv.y = lstm_h(__uint_as_float(vi[4*u+1]), __uint_as_float(vg[4*u+1]), __uint_as_float(vo[4*u+1]));
                hv.z = lstm_h(__uint_as_float(vi[4*u+2]), __uint_as_float(vg[4*u+2]), __uint_as_float(vo[4*u+2]));
                hv.w = lstm_h(__uint_as_float(vi[4*u+3]), __uint_as_float(vg[4*u+3]), __uint_as_float(vo[4*u+3]));
                *(float4*)(smb + OFF_H + kmaj_off(trow, c + 4 * u)) = hv;
            }
        }
        TCGEN05_FENCE_BEFORE();
        FENCE_PROXY_ASYNC();
        __syncthreads();

        // ---- commit#2: MMA2(A) -> 384..511  +  MMA1(B) -> 0..383 ----------
        if (warp == 0 && elect_one_pred()) {
            #pragma unroll
            for (int s = 0; s < 16; ++s) {
                uint32_t off = (uint32_t)(s >> 2) * 1024u + (uint32_t)(s & 3) * 2u;
                mma_tf32_ss(tmem + 384, hd + off, w1d + off, IDESC_TF32, s > 0);
            }
            #pragma unroll
            for (int nb = 0; nb < 3; ++nb)
                #pragma unroll
                for (int s = 0; s < 2; ++s)
                    mma_tf32_ss(tmem + nb * 128, fdB + s * 2, wd + nb * 1024u + s * 2,
                                IDESC_TF32, s > 0);
            TCGEN05_COMMIT(base + OFF_MBAR);
        }
        MBARRIER_WAIT_PARITY(base + OFF_MBAR, ph ^ 1);
        TCGEN05_FENCE_AFTER();

        // ---- gate-epi(B) -> H ---------------------------------------------
        #pragma unroll
        for (int hh = 0; hh < 2; ++hh) {
            const int c = qu * 32 + hh * 16;
            uint32_t vi[16], vg[16], vo[16];
            TCGEN05_LD_32X32B_X16(vi, tmem + c);
            TCGEN05_LD_32X32B_X16(vg, tmem + 128 + c);
            TCGEN05_LD_32X32B_X16(vo, tmem + 256 + c);
            TCGEN05_WAIT_LD();
            #pragma unroll
            for (int u = 0; u < 4; ++u) {
                float4 hv;
                hv.x = lstm_h(__uint_as_float(vi[4*u+0]), __uint_as_float(vg[4*u+0]), __uint_as_float(vo[4*u+0]));
                hv.y = lstm_h(__uint_as_float(vi[4*u+1]), __uint_as_float(vg[4*u+1]), __uint_as_float(vo[4*u+1]));
                hv.z = lstm_h(__uint_as_float(vi[4*u+2]), __uint_as_float(vg[4*u+2]), __uint_as_float(vo[4*u+2]));
                hv.w = lstm_h(__uint_as_float(vi[4*u+3]), __uint_as_float(vg[4*u+3]), __uint_as_float(vo[4*u+3]));
                *(float4*)(smb + OFF_H + kmaj_off(trow, c + 4 * u)) = hv;
            }
        }
        // ---- head-epi(A) --------------------------------------------------
        {
            const int cb = qu * 32;
            uint32_t d0[32];
            TCGEN05_LD_32X32B_X32(d0, tmem + 384 + cb);
            TCGEN05_WAIT_LD();
            float s = 0.0f;
            #pragma unroll
            for (int r = 0; r < 32; ++r)
                s = fmaf(fmaxf(__uint_as_float(d0[r]) + sb1[cb + r], 0.0f), sW2[cb + r], s);
            sPart[qu * 128 + trow] = s;
        }
        TCGEN05_FENCE_BEFORE();
        FENCE_PROXY_ASYNC();
        __syncthreads();

        // ---- commit#3: MMA2(B) -> 384..511 --------------------------------
        if (warp == 0 && elect_one_pred()) {
            #pragma unroll
            for (int s = 0; s < 16; ++s) {
                uint32_t off = (uint32_t)(s >> 2) * 1024u + (uint32_t)(s & 3) * 2u;
                mma_tf32_ss(tmem + 384, hd + off, w1d + off, IDESC_TF32, s > 0);
            }
            TCGEN05_COMMIT(base + OFF_MBAR);
        }
        MBARRIER_WAIT_PARITY(base + OFF_MBAR, ph);
        TCGEN05_FENCE_AFTER();

        // ---- head-epi(B) --------------------------------------------------
        {
            const int cb = qu * 32;
            uint32_t d0[32];
            TCGEN05_LD_32X32B_X32(d0, tmem + 384 + cb);
            TCGEN05_WAIT_LD();
            float s = 0.0f;
            #pragma unroll
            for (int r = 0; r < 32; ++r)
                s = fmaf(fmaxf(__uint_as_float(d0[r]) + sb1[cb + r], 0.0f), sW2[cb + r], s);
            sPart[512 + qu * 128 + trow] = s;
            TCGEN05_FENCE_BEFORE();
        }
        __syncthreads();

        // ---- Stage C: register-carried, split across halves ---------------
        {
            const int tq = r256 >> 7;
            float psum = sPart[tq * 512 + rr] + sPart[tq * 512 + 128 + rr]
                       + sPart[tq * 512 + 256 + rr] + sPart[tq * 512 + 384 + rr];
            float p  = fabsf(psum + b2v);
            float d  = -p * c_xv;
            float xn = c_xv + d;
            const int bI = tile >> 3;
            const int n  = (tile & 7) * TILE + r256;
            size_t ob = (size_t)bI * (5 * NDIM) + n;
            if (half == 0) {
                out[ob]            = xn;
                out[ob +     NDIM] = xn - c_lb;
                out[ob + 2 * NDIM] = c_ub - xn;
            } else {
                out[ob + 3 * NDIM] = c_z1m - c_iD1 * (d + c_z1m);
                out[ob + 4 * NDIM] = c_z2m - c_iD2 * (-d + c_z2m);
            }
        }

        // ---- store F(next) + rotate carries -------------------------------
        if (hn) {
            float z1m = (n_z1 + n_mu <= 0.0f) ? 0.0f : n_z1;
            float z2m = (n_z2 + n_mu <= 0.0f) ? 0.0f : n_z2;
            if (half == 0) {
                c_xv = n_xv; c_lb = n_lb; c_ub = n_ub;
                *(float4*)(smb + fb + kmaj_off(rr, 0)) = make_float4(n_xv, n_x1, n_x2, z1m);
                *(float4*)(smb + fb + kmaj_off(rr, 4)) = make_float4(z2m, n_e1, n_e2, n_e3);
            } else {
                float iD1 = fminf(fmaxf(__fdividef(z1m + n_mu, n_x1 + n_mu + 1e-12f), 0.0f), 100.0f);
                float iD2 = fminf(fmaxf(__fdividef(z2m + n_mu, n_x2 + n_mu + 1e-12f), 0.0f), 100.0f);
                c_xv = n_xv; c_z1m = z1m; c_z2m = z2m; c_iD1 = iD1; c_iD2 = iD2;
                *(float4*)(smb + fb + kmaj_off(rr, 8))  = make_float4(n_e4, n_mu, iD1, iD2);
                *(float4*)(smb + fb + kmaj_off(rr, 12)) = make_float4(1.0f, 0.0f, 0.0f, 0.0f);
            }
        }
        FENCE_PROXY_ASYNC();
        __syncthreads();
        ph ^= 1;
    }

    if (tid == 0) MBARRIER_INVAL(base + OFF_MBAR);
    if (warp == 0) TCGEN05_DEALLOC(tmem, 512);
#else
    // ---- PTX-pass fallback (compiles only; cubin path runs on GB300) ------
    __syncthreads();
    for (; tile < NTILES; tile += STR) {
        // features already in F for this tile (prologue / end of prev iter)
        __syncthreads();
        for (int t = 0; t < 2; ++t) {
            if (tid < 128) {
                const int r = tid;
                const uint32_t fbl = (uint32_t)OFF_F + (uint32_t)t * 16384u;
                float f[13];
                #pragma unroll
                for (int k = 0; k < 13; ++k)
                    f[k] = *(const float*)(smb + fbl + kmaj_off(r, k));
                for (int j = 0; j < 128; ++j) {
                    float a[3];
                    #pragma unroll
                    for (int gidx = 0; gidx < 3; ++gidx) {
                        uint32_t blk = (uint32_t)gidx * 16384u + (uint32_t)OFF_WIHB;
                        float acc = 0.0f;
                        #pragma unroll
                        for (int k = 0; k < 13; ++k)
                            acc = fmaf(f[k], *(const float*)(smb + blk + kmaj_off(j, k)), acc);
                        a[gidx] = acc;
                    }
                    *(float*)(smb + OFF_H + kmaj_off(r, j)) = lstm_h(a[0], a[1], a[2]);
                }
            }
            __syncthreads();
            if (tid < 128) {
                const int r = tid;
                float s = 0.0f;
                for (int j = 0; j < 128; ++j) {
                    float acc = sb1[j];
                    #pragma unroll 8
                    for (int k4 = 0; k4 < 32; ++k4) {
                        const float4 hv = *(const float4*)(smb + OFF_H  + kmaj_off(r, 4 * k4));
                        const float4 wv = *(const float4*)(smb + OFF_W1 + kmaj_off(j, 4 * k4));
                        acc = fmaf(hv.x, wv.x, fmaf(hv.y, wv.y, fmaf(hv.z, wv.z, fmaf(hv.w, wv.w, acc))));
                    }
                    s = fmaf(fmaxf(acc, 0.0f), sW2[j], s);
                }
                sPart[t * 512 + r] = s;
                sPart[t * 512 + 128 + r] = 0.0f;
                sPart[t * 512 + 256 + r] = 0.0f;
                sPart[t * 512 + 384 + r] = 0.0f;
            }
            __syncthreads();
        }
        // Stage C (register-carried, split by half)
        {
            const int tq = r256 >> 7;
            float psum = sPart[tq * 512 + rr] + sPart[tq * 512 + 128 + rr]
                       + sPart[tq * 512 + 256 + rr] + sPart[tq * 512 + 384 + rr];
            float p  = fabsf(psum + b2v);
            float d  = -p * c_xv;
            float xn = c_xv + d;
            const int bI = tile >> 3;
            const int n  = (tile & 7) * TILE + r256;
            size_t ob = (size_t)bI * (5 * NDIM) + n;
            if (half == 0) {
                out[ob]            = xn;
                out[ob +     NDIM] = xn - c_lb;
                out[ob + 2 * NDIM] = c_ub - xn;
            } else {
                out[ob + 3 * NDIM] = c_z1m - c_iD1 * (d + c_z1m);
                out[ob + 4 * NDIM] = c_z2m - c_iD2 * (-d + c_z2m);
            }
        }
        __syncthreads();
        // features for next tile
        const int next = tile + STR;
        if (next < NTILES) {
            const int row = next * TILE + r256;
            const float mu = muB[next >> 3];
            float a1 = x1[row], a2 = x2[row], v1 = z1[row], v2 = z2[row];
            float xv = x[row];
            float z1m = (v1 + mu <= 0.0f) ? 0.0f : v1;
            float z2m = (v2 + mu <= 0.0f) ? 0.0f : v2;
            if (half == 0) {
                c_xv = xv; c_lb = lb[row]; c_ub = ub[row];
                *(float4*)(smb + fb + kmaj_off(rr, 0)) = make_float4(xv, a1, a2, z1m);
                *(float4*)(smb + fb + kmaj_off(rr, 4)) = make_float4(z2m, x1E[row], x2E[row], z1E[row]);
            } else {
                float iD1 = fminf(fmaxf(__fdividef(z1m + mu, a1 + mu + 1e-12f), 0.0f), 100.0f);
                float iD2 = fminf(fmaxf(__fdividef(z2m + mu, a2 + mu + 1e-12f), 0.0f), 100.0f);
                c_xv = xv; c_z1m = z1m; c_z2m = z2m; c_iD1 = iD1; c_iD2 = iD2;
                *(float4*)(smb + fb + kmaj_off(rr, 8))  = make_float4(z2E[row], mu, iD1, iD2);
                *(float4*)(smb + fb + kmaj_off(rr, 12)) = make_float4(1.0f, 0.0f, 0.0f, 0.0f);
            }
        }
        __syncthreads();
    }
#endif
}

// ---------------------------------------------------------------------------
// metadata order:
//  0 x  1 x1  2 x2  3 z1  4 z2  5 x1E  6 x2E  7 z1E  8 z2E  9 muB  10 lb 11 ub
// 12 has_lb 13 has_ub 14 W_ih 15 W_hh(unused) 16 b_ih 17 b_hh 18 W1 19 b1 20 W2 21 b2
// ---------------------------------------------------------------------------
extern "C" void kernel_launch(void* const* d_in, const int* in_sizes, int n_in,
                              void* d_out, int out_size) {
    (void)in_sizes; (void)n_in; (void)out_size;
    const float* x    = (const float*)d_in[0];
    const float* x1   = (const float*)d_in[1];
    const float* x2   = (const float*)d_in[2];
    const float* z1   = (const float*)d_in[3];
    const float* z2   = (const float*)d_in[4];
    const float* x1E  = (const float*)d_in[5];
    const float* x2E  = (const float*)d_in[6];
    const float* z1E  = (const float*)d_in[7];
    const float* z2E  = (const float*)d_in[8];
    const float* muB  = (const float*)d_in[9];
    const float* lb   = (const float*)d_in[10];
    const float* ub   = (const float*)d_in[11];
    const float* W_ih = (const float*)d_in[14];
    const float* b_ih = (const float*)d_in[16];
    const float* b_hh = (const float*)d_in[17];
    const float* W1   = (const float*)d_in[18];
    const float* b1   = (const float*)d_in[19];
    const float* W2   = (const float*)d_in[20];
    const float* b2   = (const float*)d_in[21];

    cudaFuncSetAttribute(ps_lstm_kernel, cudaFuncAttributeMaxDynamicSharedMemorySize, SMEM_BYTES);

    int dev = 0, nsm = 0;
    cudaGetDevice(&dev);
    cudaDeviceGetAttribute(&nsm, cudaDevAttrMultiProcessorCount, dev);
    if (nsm <= 0) nsm = 148;
    if (nsm > NTILES) nsm = NTILES;

    ps_lstm_kernel<<<nsm, NTH, SMEM_BYTES>>>(
        x, x1, x2, z1, z2, x1E, x2E, z1E, z2E, muB, lb, ub,
        W_ih, b_ih, b_hh, W1, b1, W2, b2, (float*)d_out);
}

// round 16
// speedup vs baseline: 7.6720x; 1.1355x over previous
#include <cuda_runtime.h>
#include <cstdint>

#define NDIM   2048
#define TILE   256
#define NTH    512
#define NTILES 1024

// ---------------------------------------------------------------------------
// tcgen05 is an architecture-SPECIFIC ('a') feature. The harness also compiles
// a plain compute_103 PTX pass where these instructions don't exist, so every
// tcgen05 usage is gated and a plain-FMA fallback covers the PTX pass.
// ---------------------------------------------------------------------------
#if defined(__CUDA_ARCH__) && (defined(__CUDA_ARCH_FEAT_SM103_ALL) || \
    defined(__CUDA_ARCH_FEAT_SM100_ALL) || defined(__CUDA_ARCH_SPECIFIC__))
#define USE_TCGEN05 1
#else
#define USE_TCGEN05 0
#endif

// ---------------------------------------------------------------------------
// PTX helpers
// ---------------------------------------------------------------------------
__device__ __forceinline__ uint32_t elect_one_pred() {
    uint32_t pred;
    asm volatile("{\n\t.reg .pred p;\n\telect.sync _|p, 0xFFFFFFFF;\n\tselp.b32 %0, 1, 0, p;\n\t}"
                 : "=r"(pred));
    return pred;
}
__device__ __forceinline__ uint32_t smem_u32(const void* p) {
    uint32_t a;
    asm("{ .reg .u64 t; cvta.to.shared.u64 t, %1; cvt.u32.u64 %0, t; }" : "=r"(a) : "l"(p));
    return a;
}

#define MBARRIER_INIT(mbar, count) \
    asm volatile("mbarrier.init.shared.b64 [%0], %1;" \
                 :: "r"((uint32_t)(mbar)), "r"((uint32_t)(count)) : "memory")
#define MBARRIER_INVAL(mbar) \
    asm volatile("mbarrier.inval.shared.b64 [%0];" :: "r"((uint32_t)(mbar)) : "memory")
#define MBARRIER_WAIT_PARITY(mbar, parity) do { \
    uint32_t _m = (uint32_t)(mbar); uint32_t _p = (uint32_t)(parity); uint32_t _d; \
    asm volatile("{\n\t.reg .pred p;\n\t" \
        "mbarrier.try_wait.parity.acquire.cta.shared::cta.b64 p, [%1], %2;\n\t" \
        "selp.b32 %0, 1, 0, p;\n\t}" : "=r"(_d) : "r"(_m), "r"(_p) : "memory"); \
    if (!_d) { \
        asm volatile("{\n\t.reg .pred P1;\n\t" \
            "WL_%=:\n\t" \
            "mbarrier.try_wait.parity.acquire.cta.shared::cta.b64 P1, [%0], %1, 0x989680;\n\t" \
            "@P1 bra.uni WD_%=;\n\t" \
            "bra.uni WL_%=;\n\t" \
            "WD_%=:\n\t}" :: "r"(_m), "r"(_p) : "memory"); \
    } } while (0)

#define FENCE_PROXY_ASYNC()    asm volatile("fence.proxy.async.shared::cta;" ::: "memory")

#if USE_TCGEN05
#define TCGEN05_ALLOC(smem_result_addr, nCols) \
    asm volatile("tcgen05.alloc.cta_group::1.sync.aligned.shared::cta.b32 [%0], %1;" \
                 :: "r"((uint32_t)(smem_result_addr)), "r"((uint32_t)(nCols)) : "memory")
#define TCGEN05_DEALLOC(tmem_addr, nCols) \
    asm volatile("tcgen05.dealloc.cta_group::1.sync.aligned.b32 %0, %1;" \
                 :: "r"(tmem_addr), "r"((uint32_t)(nCols)))
#define TCGEN05_RELINQ() \
    asm volatile("tcgen05.relinquish_alloc_permit.cta_group::1.sync.aligned;")
#define TCGEN05_COMMIT(mbar) \
    asm volatile("tcgen05.commit.cta_group::1.mbarrier::arrive::one.shared::cluster.b64 [%0];" \
                 :: "r"((uint32_t)(mbar)) : "memory")
#define TCGEN05_FENCE_AFTER()  asm volatile("tcgen05.fence::after_thread_sync;" ::: "memory")
#define TCGEN05_FENCE_BEFORE() asm volatile("tcgen05.fence::before_thread_sync;" ::: "memory")
#define TCGEN05_WAIT_LD()      asm volatile("tcgen05.wait::ld.sync.aligned;" ::: "memory")

#define TCGEN05_LD_32X32B_X16(r, tmem_addr) \
    asm volatile("tcgen05.ld.sync.aligned.32x32b.x16.b32 " \
        "{%0, %1, %2, %3, %4, %5, %6, %7, %8, %9, %10, %11, %12, %13, %14, %15}, [%16];" \
        : "=r"((r)[0]),  "=r"((r)[1]),  "=r"((r)[2]),  "=r"((r)[3]), \
          "=r"((r)[4]),  "=r"((r)[5]),  "=r"((r)[6]),  "=r"((r)[7]), \
          "=r"((r)[8]),  "=r"((r)[9]),  "=r"((r)[10]), "=r"((r)[11]), \
          "=r"((r)[12]), "=r"((r)[13]), "=r"((r)[14]), "=r"((r)[15]) \
        : "r"(tmem_addr))

#define TCGEN05_LD_32X32B_X32(r, tmem_addr) \
    asm volatile("tcgen05.ld.sync.aligned.32x32b.x32.b32 " \
        "{%0, %1, %2, %3, %4, %5, %6, %7, %8, %9, %10, %11, %12, %13, %14, %15, " \
        " %16, %17, %18, %19, %20, %21, %22, %23, %24, %25, %26, %27, %28, %29, %30, %31}, [%32];" \
        : "=r"((r)[0]),  "=r"((r)[1]),  "=r"((r)[2]),  "=r"((r)[3]), \
          "=r"((r)[4]),  "=r"((r)[5]),  "=r"((r)[6]),  "=r"((r)[7]), \
          "=r"((r)[8]),  "=r"((r)[9]),  "=r"((r)[10]), "=r"((r)[11]), \
          "=r"((r)[12]), "=r"((r)[13]), "=r"((r)[14]), "=r"((r)[15]), \
          "=r"((r)[16]), "=r"((r)[17]), "=r"((r)[18]), "=r"((r)[19]), \
          "=r"((r)[20]), "=r"((r)[21]), "=r"((r)[22]), "=r"((r)[23]), \
          "=r"((r)[24]), "=r"((r)[25]), "=r"((r)[26]), "=r"((r)[27]), \
          "=r"((r)[28]), "=r"((r)[29]), "=r"((r)[30]), "=r"((r)[31]) \
        : "r"(tmem_addr))

// SS-form tf32 MMA, cta_group::1. fp32 data in SMEM; HW rounds to tf32.
__device__ __forceinline__ void mma_tf32_ss(uint32_t d_tmem, uint64_t a_desc, uint64_t b_desc,
                                            uint32_t idesc, bool accum) {
    uint32_t en = accum ? 1u : 0u;
    asm volatile("{\n\t.reg .pred p;\n\tsetp.ne.u32 p, %5, 0;\n\t"
                 "tcgen05.mma.cta_group::1.kind::tf32 [%0], %1, %2, %3, {%4, %4, %4, %4}, p;\n\t}"
                 :: "r"(d_tmem), "l"(a_desc), "l"(b_desc), "r"(idesc), "r"(0u), "r"(en)
                 : "memory");
}
#endif // USE_TCGEN05

// SW128 K-major SMEM descriptor base: layout=SW128(2), version=1, SBO=64, LBO=1
static constexpr uint64_t DESC_BASE_SW128 =
    (uint64_t(2) << 61) | (uint64_t(1) << 46) | (uint64_t(64) << 32) | (uint64_t(1) << 16);

// idesc: D=F32, A=TF32, B=TF32, N=128, M=128, K-major both
#define IDESC_TF32 0x8200910u

// ---------------------------------------------------------------------------
// activations: tanh.approx (MUFU) for unbounded args; polynomial for the
// final tanh(c) where c = sigmoid(i)*tanh(g) is provably in (-1,1).
// ---------------------------------------------------------------------------
__device__ __forceinline__ float tanh_fast(float v) {
    float r;
    asm("tanh.approx.f32 %0, %1;" : "=f"(r) : "f"(v));
    return r;
}
__device__ __forceinline__ float sigmoid_fast(float v) {
    return fmaf(tanh_fast(0.5f * v), 0.5f, 0.5f);
}
// deg-7 odd polynomial fit of tanh on [-1,1]; max abs err ~1.5e-4
__device__ __forceinline__ float tanh_poly(float y) {
    float y2 = y * y;
    float p = fmaf(y2, -0.0277001f, 0.1204398f);
    p = fmaf(y2, p, -0.3310472f);
    p = fmaf(y2, p, 0.9999017f);
    return y * p;
}
__device__ __forceinline__ float lstm_h(float iv, float gv, float ov) {
    float c = sigmoid_fast(iv) * tanh_fast(gv);     // |c| < 1
    return sigmoid_fast(ov) * tanh_poly(c);         // 3 MUFU + poly
}

// byte offset (incl. SW128 swizzle), K-major blocked-atom, 128-row block
__device__ __forceinline__ uint32_t kmaj_off(int row, int col) {
    uint32_t b = (uint32_t)((row >> 3) + (col >> 5) * 16) * 1024u
               + (uint32_t)(row & 7) * 128u + (uint32_t)(col & 31) * 4u;
    return b ^ ((b >> 3) & 0x70);
}

// ---- shared memory layout (bytes, from 1024-aligned base) -----------------
#define OFF_TMEMPTR 0
#define OFF_MBAR    8
#define OFF_B1      16
#define OFF_W2      528
#define OFF_PART    1040                      // 1024 f
#define OFF_F       6144                      // 2 x 16 KB
#define OFF_WIHB    38912                     // 3 x 16 KB
#define OFF_W1      88064                     // 64 KB
#define OFF_H       153600                    // 64 KB -> 219136
#define SMEM_BYTES  (219136 + 1024)

__global__ __launch_bounds__(NTH, 1)
void ps_lstm_kernel(
    const float* __restrict__ x,   const float* __restrict__ x1,  const float* __restrict__ x2,
    const float* __restrict__ z1,  const float* __restrict__ z2,
    const float* __restrict__ x1E, const float* __restrict__ x2E,
    const float* __restrict__ z1E, const float* __restrict__ z2E,
    const float* __restrict__ muB, const float* __restrict__ lb,  const float* __restrict__ ub,
    const float* __restrict__ W_ih, const float* __restrict__ b_ih, const float* __restrict__ b_hh,
    const float* __restrict__ W1,  const float* __restrict__ b1,
    const float* __restrict__ W2,  const float* __restrict__ b2,
    float* __restrict__ out)
{
    extern __shared__ unsigned char smraw[];
    const uint32_t rawa = smem_u32(smraw);
    const uint32_t base = (rawa + 1023u) & ~1023u;
    unsigned char* smb = smraw + (base - rawa);

    float* sb1   = (float*)(smb + OFF_B1);
    float* sW2   = (float*)(smb + OFF_W2);
    float* sPart = (float*)(smb + OFF_PART);

    const int tid  = threadIdx.x;
    const int warp = tid >> 5, lane = tid & 31;
    const int r256 = tid & 255, half = tid >> 8;
    const int rr   = r256 & 127;
    const uint32_t fb = (uint32_t)OFF_F + (uint32_t)(r256 >> 7) * 16384u;
    const float b2v = b2[0];

    // ---- one-time preload: W_ih^T (+bias col 12) & W1, K-major SW128 ------
    for (int j = tid; j < 384; j += NTH) {
        int row = (j < 128) ? j : j + 128;
        const float* wr = W_ih + row * 15;
        uint32_t blk = (uint32_t)(j >> 7) * 16384u + (uint32_t)OFF_WIHB;
        int jr = j & 127;
        *(float*)(smb + blk + kmaj_off(jr, 0))  = wr[0] + wr[5];
        *(float*)(smb + blk + kmaj_off(jr, 1))  = wr[1];
        *(float*)(smb + blk + kmaj_off(jr, 2))  = wr[2];
        *(float*)(smb + blk + kmaj_off(jr, 3))  = wr[3] + wr[6];
        *(float*)(smb + blk + kmaj_off(jr, 4))  = wr[4] + wr[7];
        #pragma unroll
        for (int k = 5; k < 12; ++k)
            *(float*)(smb + blk + kmaj_off(jr, k)) = wr[k + 3];
        *(float*)(smb + blk + kmaj_off(jr, 12)) = b_ih[row] + b_hh[row];
        *(float*)(smb + blk + kmaj_off(jr, 13)) = 0.0f;
        *(float*)(smb + blk + kmaj_off(jr, 14)) = 0.0f;
        *(float*)(smb + blk + kmaj_off(jr, 15)) = 0.0f;
    }
    for (int i = tid; i < 4096; i += NTH) {
        int r = i >> 5, c4 = (i & 31) * 4;
        float4 v = *(const float4*)(W1 + r * 128 + c4);
        *(float4*)(smb + OFF_W1 + kmaj_off(r, c4)) = v;
    }
    if (tid < 128) { sb1[tid] = b1[tid]; sW2[tid] = W2[tid]; }

#if USE_TCGEN05
    if (warp == 0) { TCGEN05_ALLOC(base + OFF_TMEMPTR, 512); TCGEN05_RELINQ(); }
    if (tid == 0)  { MBARRIER_INIT(base + OFF_MBAR, 1); }
#endif

    const int STR = gridDim.x;
    int tile = blockIdx.x;
    if (tile >= NTILES) return;

    // ---- Stage-C register carries ----------------------------------------
    float c_xv = 0.f, c_lb = 0.f, c_ub = 0.f;
    float c_z1m = 0.f, c_z2m = 0.f, c_iD1 = 0.f, c_iD2 = 0.f;

    // ---- prologue: F(t0) + carries ----------------------------------------
    {
        const int row = tile * TILE + r256;
        const float mu = muB[tile >> 3];
        float a1 = x1[row], a2 = x2[row], v1 = z1[row], v2 = z2[row];
        float xv = x[row];
        float z1m = (v1 + mu <= 0.0f) ? 0.0f : v1;
        float z2m = (v2 + mu <= 0.0f) ? 0.0f : v2;
        if (half == 0) {
            c_xv = xv; c_lb = lb[row]; c_ub = ub[row];
            *(float4*)(smb + fb + kmaj_off(rr, 0)) = make_float4(xv, a1, a2, z1m);
            *(float4*)(smb + fb + kmaj_off(rr, 4)) = make_float4(z2m, x1E[row], x2E[row], z1E[row]);
        } else {
            float iD1 = fminf(fmaxf(__fdividef(z1m + mu, a1 + mu + 1e-12f), 0.0f), 100.0f);
            float iD2 = fminf(fmaxf(__fdividef(z2m + mu, a2 + mu + 1e-12f), 0.0f), 100.0f);
            c_xv = xv; c_z1m = z1m; c_z2m = z2m; c_iD1 = iD1; c_iD2 = iD2;
            *(float4*)(smb + fb + kmaj_off(rr, 8))  = make_float4(z2E[row], mu, iD1, iD2);
            *(float4*)(smb + fb + kmaj_off(rr, 12)) = make_float4(1.0f, 0.0f, 0.0f, 0.0f);
        }
    }

#if USE_TCGEN05
    uint32_t tmem;
    FENCE_PROXY_ASYNC(); __syncthreads();
    asm volatile("ld.shared.b32 %0, [%1];" : "=r"(tmem) : "r"(base + OFF_TMEMPTR));

    const uint64_t fdA = DESC_BASE_SW128 | ((uint64_t)((base + OFF_F)          >> 4) & 0x3FFF);
    const uint64_t fdB = DESC_BASE_SW128 | ((uint64_t)((base + OFF_F + 16384u) >> 4) & 0x3FFF);
    const uint64_t wd  = DESC_BASE_SW128 | ((uint64_t)((base + OFF_WIHB)       >> 4) & 0x3FFF);
    const uint64_t hd  = DESC_BASE_SW128 | ((uint64_t)((base + OFF_H)          >> 4) & 0x3FFF);
    const uint64_t w1d = DESC_BASE_SW128 | ((uint64_t)((base + OFF_W1)         >> 4) & 0x3FFF);

    const int sp = warp & 3, qu = warp >> 2;
    const int trow = sp * 32 + lane;

    // ---- prologue commit: MMA1(A_t0) -> gate cols 0..383 ------------------
    if (warp == 0 && elect_one_pred()) {
        #pragma unroll
        for (int nb = 0; nb < 3; ++nb)
            #pragma unroll
            for (int s = 0; s < 2; ++s)
                mma_tf32_ss(tmem + nb * 128, fdA + s * 2, wd + nb * 1024u + s * 2,
                            IDESC_TF32, s > 0);
        TCGEN05_COMMIT(base + OFF_MBAR);
    }
    MBARRIER_WAIT_PARITY(base + OFF_MBAR, 0);
    TCGEN05_FENCE_AFTER();
    // gate-epi(A_t0) -> H
    #pragma unroll
    for (int hh = 0; hh < 2; ++hh) {
        const int c = qu * 32 + hh * 16;
        uint32_t vi[16], vg[16], vo[16];
        TCGEN05_LD_32X32B_X16(vi, tmem + c);
        TCGEN05_LD_32X32B_X16(vg, tmem + 128 + c);
        TCGEN05_LD_32X32B_X16(vo, tmem + 256 + c);
        TCGEN05_WAIT_LD();
        #pragma unroll
        for (int u = 0; u < 4; ++u) {
            float4 hv;
            hv.x = lstm_h(__uint_as_float(vi[4*u+0]), __uint_as_float(vg[4*u+0]), __uint_as_float(vo[4*u+0]));
            hv.y = lstm_h(__uint_as_float(vi[4*u+1]), __uint_as_float(vg[4*u+1]), __uint_as_float(vo[4*u+1]));
            hv.z = lstm_h(__uint_as_float(vi[4*u+2]), __uint_as_float(vg[4*u+2]), __uint_as_float(vo[4*u+2]));
            hv.w = lstm_h(__uint_as_float(vi[4*u+3]), __uint_as_float(vg[4*u+3]), __uint_as_float(vo[4*u+3]));
            *(float4*)(smb + OFF_H + kmaj_off(trow, c + 4 * u)) = hv;
        }
    }
    TCGEN05_FENCE_BEFORE();
    FENCE_PROXY_ASYNC();
    __syncthreads();

    // ---- steady-state: 2 commits per tile ---------------------------------
    // wait parities: prologue 0, then C1 -> 1, C2 -> 0, repeating each tile.
    for (; tile < NTILES; tile += STR) {
        const int next = tile + STR;
        const bool hn = next < NTILES;

        // ---- commit C1: MMA2(A) -> 384..511  +  MMA1(B) -> 0..383 ---------
        if (warp == 0 && elect_one_pred()) {
            #pragma unroll
            for (int s = 0; s < 16; ++s) {
                uint32_t off = (uint32_t)(s >> 2) * 1024u + (uint32_t)(s & 3) * 2u;
                mma_tf32_ss(tmem + 384, hd + off, w1d + off, IDESC_TF32, s > 0);
            }
            #pragma unroll
            for (int nb = 0; nb < 3; ++nb)
                #pragma unroll
                for (int s = 0; s < 2; ++s)
                    mma_tf32_ss(tmem + nb * 128, fdB + s * 2, wd + nb * 1024u + s * 2,
                                IDESC_TF32, s > 0);
            TCGEN05_COMMIT(base + OFF_MBAR);
        }

        // ---- prefetch next tile's inputs (hidden under C1 wait) -----------
        float n_x1 = 0.f, n_x2 = 0.f, n_z1 = 0.f, n_z2 = 0.f, n_xv = 0.f, n_mu = 0.f;
        float n_e1 = 0.f, n_e2 = 0.f, n_e3 = 0.f, n_e4 = 0.f, n_lb = 0.f, n_ub = 0.f;
        if (hn) {
            const int row = next * TILE + r256;
            n_mu = muB[next >> 3];
            n_x1 = x1[row]; n_x2 = x2[row]; n_z1 = z1[row]; n_z2 = z2[row];
            n_xv = x[row];
            if (half == 0) {
                n_e1 = x1E[row]; n_e2 = x2E[row]; n_e3 = z1E[row];
                n_lb = lb[row];  n_ub = ub[row];
            } else {
                n_e4 = z2E[row];
            }
        }
        float n_z1m = 0.f, n_z2m = 0.f, n_iD1 = 0.f, n_iD2 = 0.f;

        MBARRIER_WAIT_PARITY(base + OFF_MBAR, 1);
        TCGEN05_FENCE_AFTER();

        // ---- gate-epi(B) -> H  (H free: MMA2(A) done) ---------------------
        #pragma unroll
        for (int hh = 0; hh < 2; ++hh) {
            const int c = qu * 32 + hh * 16;
            uint32_t vi[16], vg[16], vo[16];
            TCGEN05_LD_32X32B_X16(vi, tmem + c);
            TCGEN05_LD_32X32B_X16(vg, tmem + 128 + c);
            TCGEN05_LD_32X32B_X16(vo, tmem + 256 + c);
            TCGEN05_WAIT_LD();
            #pragma unroll
            for (int u = 0; u < 4; ++u) {
                float4 hv;
                hv.x = lstm_h(__uint_as_float(vi[4*u+0]), __uint_as_float(vg[4*u+0]), __uint_as_float(vo[4*u+0]));
                hv.y = lstm_h(__uint_as_float(vi[4*u+1]), __uint_as_float(vg[4*u+1]), __uint_as_float(vo[4*u+1]));
                hv.z = lstm_h(__uint_as_float(vi[4*u+2]), __uint_as_float(vg[4*u+2]), __uint_as_float(vo[4*u+2]));
                hv.w = lstm_h(__uint_as_float(vi[4*u+3]), __uint_as_float(vg[4*u+3]), __uint_as_float(vo[4*u+3]));
                *(float4*)(smb + OFF_H + kmaj_off(trow, c + 4 * u)) = hv;
            }
        }
        // ---- head-epi(A) --------------------------------------------------
        {
            const int cb = qu * 32;
            uint32_t d0[32];
            TCGEN05_LD_32X32B_X32(d0, tmem + 384 + cb);
            TCGEN05_WAIT_LD();
            float s = 0.0f;
            #pragma unroll
            for (int r = 0; r < 32; ++r)
                s = fmaf(fmaxf(__uint_as_float(d0[r]) + sb1[cb + r], 0.0f), sW2[cb + r], s);
            sPart[qu * 128 + trow] = s;
        }
        // ---- store F(next)  (F free: MMA1(B) done) ------------------------
        if (hn) {
            n_z1m = (n_z1 + n_mu <= 0.0f) ? 0.0f : n_z1;
            n_z2m = (n_z2 + n_mu <= 0.0f) ? 0.0f : n_z2;
            if (half == 0) {
                *(float4*)(smb + fb + kmaj_off(rr, 0)) = make_float4(n_xv, n_x1, n_x2, n_z1m);
                *(float4*)(smb + fb + kmaj_off(rr, 4)) = make_float4(n_z2m, n_e1, n_e2, n_e3);
            } else {
                n_iD1 = fminf(fmaxf(__fdividef(n_z1m + n_mu, n_x1 + n_mu + 1e-12f), 0.0f), 100.0f);
                n_iD2 = fminf(fmaxf(__fdividef(n_z2m + n_mu, n_x2 + n_mu + 1e-12f), 0.0f), 100.0f);
                *(float4*)(smb + fb + kmaj_off(rr, 8))  = make_float4(n_e4, n_mu, n_iD1, n_iD2);
                *(float4*)(smb + fb + kmaj_off(rr, 12)) = make_float4(1.0f, 0.0f, 0.0f, 0.0f);
            }
        }
        TCGEN05_FENCE_BEFORE();
        FENCE_PROXY_ASYNC();
        __syncthreads();

        // ---- commit C2: MMA2(B) -> 384..511  + (hn) MMA1(A_next) ----------
        if (warp == 0 && elect_one_pred()) {
            #pragma unroll
            for (int s = 0; s < 16; ++s) {
                uint32_t off = (uint32_t)(s >> 2) * 1024u + (uint32_t)(s & 3) * 2u;
                mma_tf32_ss(tmem + 384, hd + off, w1d + off, IDESC_TF32, s > 0);
            }
            if (hn) {
                #pragma unroll
                for (int nb = 0; nb < 3; ++nb)
                    #pragma unroll
                    for (int s = 0; s < 2; ++s)
                        mma_tf32_ss(tmem + nb * 128, fdA + s * 2, wd + nb * 1024u + s * 2,
                                    IDESC_TF32, s > 0);
            }
            TCGEN05_COMMIT(base + OFF_MBAR);
        }
        MBARRIER_WAIT_PARITY(base + OFF_MBAR, 0);
        TCGEN05_FENCE_AFTER();

        // ---- head-epi(B) --------------------------------------------------
        {
            const int cb = qu * 32;
            uint32_t d0[32];
            TCGEN05_LD_32X32B_X32(d0, tmem + 384 + cb);
            TCGEN05_WAIT_LD();
            float s = 0.0f;
            #pragma unroll
            for (int r = 0; r < 32; ++r)
                s = fmaf(fmaxf(__uint_as_float(d0[r]) + sb1[cb + r], 0.0f), sW2[cb + r], s);
            sPart[512 + qu * 128 + trow] = s;
        }
        // ---- gate-epi(A_next) -> H  (H free: MMA2(B) done) ----------------
        if (hn) {
            #pragma unroll
            for (int hh = 0; hh < 2; ++hh) {
                const int c = qu * 32 + hh * 16;
                uint32_t vi[16], vg[16], vo[16];
                TCGEN05_LD_32X32B_X16(vi, tmem + c);
                TCGEN05_LD_32X32B_X16(vg, tmem + 128 + c);
                TCGEN05_LD_32X32B_X16(vo, tmem + 256 + c);
                TCGEN05_WAIT_LD();
                #pragma unroll
                for (int u = 0; u < 4; ++u) {
                    float4 hv;
                    hv.x = lstm_h(__uint_as_float(vi[4*u+0]), __uint_as_float(vg[4*u+0]), __uint_as_float(vo[4*u+0]));
                    hv.y = lstm_h(__uint_as_float(vi[4*u+1]), __uint_as_float(vg[4*u+1]), __uint_as_float(vo[4*u+1]));
                    hv.z = lstm_h(__uint_as_float(vi[4*u+2]), __uint_as_float(vg[4*u+2]), __uint_as_float(vo[4*u+2]));
                    hv.w = lstm_h(__uint_as_float(vi[4*u+3]), __uint_as_float(vg[4*u+3]), __uint_as_float(vo[4*u+3]));
                    *(float4*)(smb + OFF_H + kmaj_off(trow, c + 4 * u)) = hv;
                }
            }
        }
        TCGEN05_FENCE_BEFORE();
        FENCE_PROXY_ASYNC();
        __syncthreads();   // sPart + H visible before Stage C / next C1

        // ---- Stage C(tile): register-carried, split across halves ---------
        {
            const int tq = r256 >> 7;
            float psum = sPart[tq * 512 + rr] + sPart[tq * 512 + 128 + rr]
                       + sPart[tq * 512 + 256 + rr] + sPart[tq * 512 + 384 + rr];
            float p  = fabsf(psum + b2v);
            float d  = -p * c_xv;
            float xn = c_xv + d;
            const int bI = tile >> 3;
            const int n  = (tile & 7) * TILE + r256;
            size_t ob = (size_t)bI * (5 * NDIM) + n;
            if (half == 0) {
                out[ob]            = xn;
                out[ob +     NDIM] = xn - c_lb;
                out[ob + 2 * NDIM] = c_ub - xn;
            } else {
                out[ob + 3 * NDIM] = c_z1m - c_iD1 * (d + c_z1m);
                out[ob + 4 * NDIM] = c_z2m - c_iD2 * (-d + c_z2m);
            }
        }
        // rotate carries
        c_xv = n_xv; c_lb = n_lb; c_ub = n_ub;
        c_z1m = n_z1m; c_z2m = n_z2m; c_iD1 = n_iD1; c_iD2 = n_iD2;
    }

    if (tid == 0) MBARRIER_INVAL(base + OFF_MBAR);
    if (warp == 0) TCGEN05_DEALLOC(tmem, 512);
#else
    // ---- PTX-pass fallback (compiles only; cubin path runs on GB300) ------
    __syncthreads();
    for (; tile < NTILES; tile += STR) {
        __syncthreads();
        for (int t = 0; t < 2; ++t) {
            if (tid < 128) {
                const int r = tid;
                const uint32_t fbl = (uint32_t)OFF_F + (uint32_t)t * 16384u;
                float f[13];
                #pragma unroll
                for (int k = 0; k < 13; ++k)
                    f[k] = *(const float*)(smb + fbl + kmaj_off(r, k));
                for (int j = 0; j < 128; ++j) {
                    float a[3];
                    #pragma unroll
                    for (int gidx = 0; gidx < 3; ++gidx) {
                        uint32_t blk = (uint32_t)gidx * 16384u + (uint32_t)OFF_WIHB;
                        float acc = 0.0f;
                        #pragma unroll
                        for (int k = 0; k < 13; ++k)
                            acc = fmaf(f[k], *(const float*)(smb + blk + kmaj_off(j, k)), acc);
                        a[gidx] = acc;
                    }
                    *(float*)(smb + OFF_H + kmaj_off(r, j)) = lstm_h(a[0], a[1], a[2]);
                }
            }
            __syncthreads();
            if (tid < 128) {
                const int r = tid;
                float s = 0.0f;
                for (int j = 0; j < 128; ++j) {
                    float acc = sb1[j];
                    #pragma unroll 8
                    for (int k4 = 0; k4 < 32; ++k4) {
                        const float4 hv = *(const float4*)(smb + OFF_H  + kmaj_off(r, 4 * k4));
                        const float4 wv = *(const float4*)(smb + OFF_W1 + kmaj_off(j, 4 * k4));
                        acc = fmaf(hv.x, wv.x, fmaf(hv.y, wv.y, fmaf(hv.z, wv.z, fmaf(hv.w, wv.w, acc))));
                    }
                    s = fmaf(fmaxf(acc, 0.0f), sW2[j], s);
                }
                sPart[t * 512 + r] = s;
                sPart[t * 512 + 128 + r] = 0.0f;
                sPart[t * 512 + 256 + r] = 0.0f;
                sPart[t * 512 + 384 + r] = 0.0f;
            }
            __syncthreads();
        }
        {
            const int tq = r256 >> 7;
            float psum = sPart[tq * 512 + rr] + sPart[tq * 512 + 128 + rr]
                       + sPart[tq * 512 + 256 + rr] + sPart[tq * 512 + 384 + rr];
            float p  = fabsf(psum + b2v);
            float d  = -p * c_xv;
            float xn = c_xv + d;
            const int bI = tile >> 3;
            const int n  = (tile & 7) * TILE + r256;
            size_t ob = (size_t)bI * (5 * NDIM) + n;
            if (half == 0) {
                out[ob]            = xn;
                out[ob +     NDIM] = xn - c_lb;
                out[ob + 2 * NDIM] = c_ub - xn;
            } else {
                out[ob + 3 * NDIM] = c_z1m - c_iD1 * (d + c_z1m);
                out[ob + 4 * NDIM] = c_z2m - c_iD2 * (-d + c_z2m);
            }
        }
        __syncthreads();
        const int next = tile + STR;
        if (next < NTILES) {
            const int row = next * TILE + r256;
            const float mu = muB[next >> 3];
            float a1 = x1[row], a2 = x2[row], v1 = z1[row], v2 = z2[row];
            float xv = x[row];
            float z1m = (v1 + mu <= 0.0f) ? 0.0f : v1;
            float z2m = (v2 + mu <= 0.0f) ? 0.0f : v2;
            if (half == 0) {
                c_xv = xv; c_lb = lb[row]; c_ub = ub[row];
                *(float4*)(smb + fb + kmaj_off(rr, 0)) = make_float4(xv, a1, a2, z1m);
                *(float4*)(smb + fb + kmaj_off(rr, 4)) = make_float4(z2m, x1E[row], x2E[row], z1E[row]);
            } else {
                float iD1 = fminf(fmaxf(__fdividef(z1m + mu, a1 + mu + 1e-12f), 0.0f), 100.0f);
                float iD2 = fminf(fmaxf(__fdividef(z2m + mu, a2 + mu + 1e-12f), 0.0f), 100.0f);
                c_xv = xv; c_z1m = z1m; c_z2m = z2m; c_iD1 = iD1; c_iD2 = iD2;
                *(float4*)(smb + fb + kmaj_off(rr, 8))  = make_float4(z2E[row], mu, iD1, iD2);
                *(float4*)(smb + fb + kmaj_off(rr, 12)) = make_float4(1.0f, 0.0f, 0.0f, 0.0f);
            }
        }
        __syncthreads();
    }
#endif
}

// ---------------------------------------------------------------------------
// metadata order:
//  0 x  1 x1  2 x2  3 z1  4 z2  5 x1E  6 x2E  7 z1E  8 z2E  9 muB  10 lb 11 ub
// 12 has_lb 13 has_ub 14 W_ih 15 W_hh(unused) 16 b_ih 17 b_hh 18 W1 19 b1 20 W2 21 b2
// ---------------------------------------------------------------------------
extern "C" void kernel_launch(void* const* d_in, const int* in_sizes, int n_in,
                              void* d_out, int out_size) {
    (void)in_sizes; (void)n_in; (void)out_size;
    const float* x    = (const float*)d_in[0];
    const float* x1   = (const float*)d_in[1];
    const float* x2   = (const float*)d_in[2];
    const float* z1   = (const float*)d_in[3];
    const float* z2   = (const float*)d_in[4];
    const float* x1E  = (const float*)d_in[5];
    const float* x2E  = (const float*)d_in[6];
    const float* z1E  = (const float*)d_in[7];
    const float* z2E  = (const float*)d_in[8];
    const float* muB  = (const float*)d_in[9];
    const float* lb   = (const float*)d_in[10];
    const float* ub   = (const float*)d_in[11];
    const float* W_ih = (const float*)d_in[14];
    const float* b_ih = (const float*)d_in[16];
    const float* b_hh = (const float*)d_in[17];
    const float* W1   = (const float*)d_in[18];
    const float* b1   = (const float*)d_in[19];
    const float* W2   = (const float*)d_in[20];
    const float* b2   = (const float*)d_in[21];

    cudaFuncSetAttribute(ps_lstm_kernel, cudaFuncAttributeMaxDynamicSharedMemorySize, SMEM_BYTES);

    int dev = 0, nsm = 0;
    cudaGetDevice(&dev);
    cudaDeviceGetAttribute(&nsm, cudaDevAttrMultiProcessorCount, dev);
    if (nsm <= 0) nsm = 148;
    if (nsm > NTILES) nsm = NTILES;

    ps_lstm_kernel<<<nsm, NTH, SMEM_BYTES>>>(
        x, x1, x2, z1, z2, x1E, x2E, z1E, z2E, muB, lb, ub,
        W_ih, b_ih, b_hh, W1, b1, W2, b2, (float*)d_out);
}

// round 17
// speedup vs baseline: 7.7061x; 1.0044x over previous
#include <cuda_runtime.h>
#include <cstdint>

#define NDIM   2048
#define TILE   256
#define NTH    512
#define NTILES 1024

// ---------------------------------------------------------------------------
// tcgen05 is an architecture-SPECIFIC ('a') feature. The harness also compiles
// a plain compute_103 PTX pass where these instructions don't exist, so every
// tcgen05 usage is gated and a plain-FMA fallback covers the PTX pass.
// ---------------------------------------------------------------------------
#if defined(__CUDA_ARCH__) && (defined(__CUDA_ARCH_FEAT_SM103_ALL) || \
    defined(__CUDA_ARCH_FEAT_SM100_ALL) || defined(__CUDA_ARCH_SPECIFIC__))
#define USE_TCGEN05 1
#else
#define USE_TCGEN05 0
#endif

// ---------------------------------------------------------------------------
// PTX helpers
// ---------------------------------------------------------------------------
__device__ __forceinline__ uint32_t elect_one_pred() {
    uint32_t pred;
    asm volatile("{\n\t.reg .pred p;\n\telect.sync _|p, 0xFFFFFFFF;\n\tselp.b32 %0, 1, 0, p;\n\t}"
                 : "=r"(pred));
    return pred;
}
__device__ __forceinline__ uint32_t smem_u32(const void* p) {
    uint32_t a;
    asm("{ .reg .u64 t; cvta.to.shared.u64 t, %1; cvt.u32.u64 %0, t; }" : "=r"(a) : "l"(p));
    return a;
}

#define MBARRIER_INIT(mbar, count) \
    asm volatile("mbarrier.init.shared.b64 [%0], %1;" \
                 :: "r"((uint32_t)(mbar)), "r"((uint32_t)(count)) : "memory")
#define MBARRIER_INVAL(mbar) \
    asm volatile("mbarrier.inval.shared.b64 [%0];" :: "r"((uint32_t)(mbar)) : "memory")
#define MBARRIER_WAIT_PARITY(mbar, parity) do { \
    uint32_t _m = (uint32_t)(mbar); uint32_t _p = (uint32_t)(parity); uint32_t _d; \
    asm volatile("{\n\t.reg .pred p;\n\t" \
        "mbarrier.try_wait.parity.acquire.cta.shared::cta.b64 p, [%1], %2;\n\t" \
        "selp.b32 %0, 1, 0, p;\n\t}" : "=r"(_d) : "r"(_m), "r"(_p) : "memory"); \
    if (!_d) { \
        asm volatile("{\n\t.reg .pred P1;\n\t" \
            "WL_%=:\n\t" \
            "mbarrier.try_wait.parity.acquire.cta.shared::cta.b64 P1, [%0], %1, 0x989680;\n\t" \
            "@P1 bra.uni WD_%=;\n\t" \
            "bra.uni WL_%=;\n\t" \
            "WD_%=:\n\t}" :: "r"(_m), "r"(_p) : "memory"); \
    } } while (0)

#define FENCE_PROXY_ASYNC()    asm volatile("fence.proxy.async.shared::cta;" ::: "memory")

#if USE_TCGEN05
#define TCGEN05_ALLOC(smem_result_addr, nCols) \
    asm volatile("tcgen05.alloc.cta_group::1.sync.aligned.shared::cta.b32 [%0], %1;" \
                 :: "r"((uint32_t)(smem_result_addr)), "r"((uint32_t)(nCols)) : "memory")
#define TCGEN05_DEALLOC(tmem_addr, nCols) \
    asm volatile("tcgen05.dealloc.cta_group::1.sync.aligned.b32 %0, %1;" \
                 :: "r"(tmem_addr), "r"((uint32_t)(nCols)))
#define TCGEN05_RELINQ() \
    asm volatile("tcgen05.relinquish_alloc_permit.cta_group::1.sync.aligned;")
#define TCGEN05_COMMIT(mbar) \
    asm volatile("tcgen05.commit.cta_group::1.mbarrier::arrive::one.shared::cluster.b64 [%0];" \
                 :: "r"((uint32_t)(mbar)) : "memory")
#define TCGEN05_FENCE_AFTER()  asm volatile("tcgen05.fence::after_thread_sync;" ::: "memory")
#define TCGEN05_FENCE_BEFORE() asm volatile("tcgen05.fence::before_thread_sync;" ::: "memory")
#define TCGEN05_WAIT_LD()      asm volatile("tcgen05.wait::ld.sync.aligned;" ::: "memory")

#define TCGEN05_LD_32X32B_X16(r, tmem_addr) \
    asm volatile("tcgen05.ld.sync.aligned.32x32b.x16.b32 " \
        "{%0, %1, %2, %3, %4, %5, %6, %7, %8, %9, %10, %11, %12, %13, %14, %15}, [%16];" \
        : "=r"((r)[0]),  "=r"((r)[1]),  "=r"((r)[2]),  "=r"((r)[3]), \
          "=r"((r)[4]),  "=r"((r)[5]),  "=r"((r)[6]),  "=r"((r)[7]), \
          "=r"((r)[8]),  "=r"((r)[9]),  "=r"((r)[10]), "=r"((r)[11]), \
          "=r"((r)[12]), "=r"((r)[13]), "=r"((r)[14]), "=r"((r)[15]) \
        : "r"(tmem_addr))

#define TCGEN05_LD_32X32B_X32(r, tmem_addr) \
    asm volatile("tcgen05.ld.sync.aligned.32x32b.x32.b32 " \
        "{%0, %1, %2, %3, %4, %5, %6, %7, %8, %9, %10, %11, %12, %13, %14, %15, " \
        " %16, %17, %18, %19, %20, %21, %22, %23, %24, %25, %26, %27, %28, %29, %30, %31}, [%32];" \
        : "=r"((r)[0]),  "=r"((r)[1]),  "=r"((r)[2]),  "=r"((r)[3]), \
          "=r"((r)[4]),  "=r"((r)[5]),  "=r"((r)[6]),  "=r"((r)[7]), \
          "=r"((r)[8]),  "=r"((r)[9]),  "=r"((r)[10]), "=r"((r)[11]), \
          "=r"((r)[12]), "=r"((r)[13]), "=r"((r)[14]), "=r"((r)[15]), \
          "=r"((r)[16]), "=r"((r)[17]), "=r"((r)[18]), "=r"((r)[19]), \
          "=r"((r)[20]), "=r"((r)[21]), "=r"((r)[22]), "=r"((r)[23]), \
          "=r"((r)[24]), "=r"((r)[25]), "=r"((r)[26]), "=r"((r)[27]), \
          "=r"((r)[28]), "=r"((r)[29]), "=r"((r)[30]), "=r"((r)[31]) \
        : "r"(tmem_addr))

// SS-form tf32 MMA, cta_group::1. fp32 data in SMEM; HW rounds to tf32.
__device__ __forceinline__ void mma_tf32_ss(uint32_t d_tmem, uint64_t a_desc, uint64_t b_desc,
                                            uint32_t idesc, bool accum) {
    uint32_t en = accum ? 1u : 0u;
    asm volatile("{\n\t.reg .pred p;\n\tsetp.ne.u32 p, %5, 0;\n\t"
                 "tcgen05.mma.cta_group::1.kind::tf32 [%0], %1, %2, %3, {%4, %4, %4, %4}, p;\n\t}"
                 :: "r"(d_tmem), "l"(a_desc), "l"(b_desc), "r"(idesc), "r"(0u), "r"(en)
                 : "memory");
}
#endif // USE_TCGEN05

// SW128 K-major SMEM descriptor base: layout=SW128(2), version=1, SBO=64, LBO=1
static constexpr uint64_t DESC_BASE_SW128 =
    (uint64_t(2) << 61) | (uint64_t(1) << 46) | (uint64_t(64) << 32) | (uint64_t(1) << 16);

// idesc: D=F32, A=TF32, B=TF32, N=128, M=128, K-major both
#define IDESC_TF32 0x8200910u

// ---------------------------------------------------------------------------
// activations: tanh.approx (MUFU) for unbounded args; polynomial for the
// final tanh(c) where c = sigmoid(i)*tanh(g) is provably in (-1,1).
// ---------------------------------------------------------------------------
__device__ __forceinline__ float tanh_fast(float v) {
    float r;
    asm("tanh.approx.f32 %0, %1;" : "=f"(r) : "f"(v));
    return r;
}
__device__ __forceinline__ float sigmoid_fast(float v) {
    return fmaf(tanh_fast(0.5f * v), 0.5f, 0.5f);
}
// deg-7 odd polynomial fit of tanh on [-1,1]; max abs err ~1.5e-4
__device__ __forceinline__ float tanh_poly(float y) {
    float y2 = y * y;
    float p = fmaf(y2, -0.0277001f, 0.1204398f);
    p = fmaf(y2, p, -0.3310472f);
    p = fmaf(y2, p, 0.9999017f);
    return y * p;
}
__device__ __forceinline__ float lstm_h(float iv, float gv, float ov) {
    float c = sigmoid_fast(iv) * tanh_fast(gv);     // |c| < 1
    return sigmoid_fast(ov) * tanh_poly(c);         // 3 MUFU + poly
}

// byte offset (incl. SW128 swizzle), K-major blocked-atom, 128-row block
__device__ __forceinline__ uint32_t kmaj_off(int row, int col) {
    uint32_t b = (uint32_t)((row >> 3) + (col >> 5) * 16) * 1024u
               + (uint32_t)(row & 7) * 128u + (uint32_t)(col & 31) * 4u;
    return b ^ ((b >> 3) & 0x70);
}

// ---- shared memory layout (bytes, from 1024-aligned base) -----------------
#define OFF_TMEMPTR 0
#define OFF_MBAR    8
#define OFF_B1      16
#define OFF_W2      528
#define OFF_PART    1040                      // 1024 f
#define OFF_F       6144                      // 2 x 16 KB
#define OFF_WIHB    38912                     // 3 x 16 KB
#define OFF_W1      88064                     // 64 KB
#define OFF_H       153600                    // 64 KB -> 219136
#define SMEM_BYTES  (219136 + 1024)

__global__ __launch_bounds__(NTH, 1)
void ps_lstm_kernel(
    const float* __restrict__ x,   const float* __restrict__ x1,  const float* __restrict__ x2,
    const float* __restrict__ z1,  const float* __restrict__ z2,
    const float* __restrict__ x1E, const float* __restrict__ x2E,
    const float* __restrict__ z1E, const float* __restrict__ z2E,
    const float* __restrict__ muB, const float* __restrict__ lb,  const float* __restrict__ ub,
    const float* __restrict__ W_ih, const float* __restrict__ b_ih, const float* __restrict__ b_hh,
    const float* __restrict__ W1,  const float* __restrict__ b1,
    const float* __restrict__ W2,  const float* __restrict__ b2,
    float* __restrict__ out)
{
    extern __shared__ unsigned char smraw[];
    const uint32_t rawa = smem_u32(smraw);
    const uint32_t base = (rawa + 1023u) & ~1023u;
    unsigned char* smb = smraw + (base - rawa);

    float* sb1   = (float*)(smb + OFF_B1);
    float* sW2   = (float*)(smb + OFF_W2);
    float* sPart = (float*)(smb + OFF_PART);

    const int tid  = threadIdx.x;
    const int warp = tid >> 5, lane = tid & 31;
    const int r256 = tid & 255, half = tid >> 8;
    const int rr   = r256 & 127;
    const bool rowA = (r256 < 128);            // row-block A vs B
    const uint32_t fb = (uint32_t)OFF_F + (uint32_t)(r256 >> 7) * 16384u;
    const float b2v = b2[0];

    // ---- one-time preload: W_ih^T (+bias col 12) & W1, K-major SW128 ------
    for (int j = tid; j < 384; j += NTH) {
        int row = (j < 128) ? j : j + 128;
        const float* wr = W_ih + row * 15;
        uint32_t blk = (uint32_t)(j >> 7) * 16384u + (uint32_t)OFF_WIHB;
        int jr = j & 127;
        *(float*)(smb + blk + kmaj_off(jr, 0))  = wr[0] + wr[5];
        *(float*)(smb + blk + kmaj_off(jr, 1))  = wr[1];
        *(float*)(smb + blk + kmaj_off(jr, 2))  = wr[2];
        *(float*)(smb + blk + kmaj_off(jr, 3))  = wr[3] + wr[6];
        *(float*)(smb + blk + kmaj_off(jr, 4))  = wr[4] + wr[7];
        #pragma unroll
        for (int k = 5; k < 12; ++k)
            *(float*)(smb + blk + kmaj_off(jr, k)) = wr[k + 3];
        *(float*)(smb + blk + kmaj_off(jr, 12)) = b_ih[row] + b_hh[row];
        *(float*)(smb + blk + kmaj_off(jr, 13)) = 0.0f;
        *(float*)(smb + blk + kmaj_off(jr, 14)) = 0.0f;
        *(float*)(smb + blk + kmaj_off(jr, 15)) = 0.0f;
    }
    for (int i = tid; i < 4096; i += NTH) {
        int r = i >> 5, c4 = (i & 31) * 4;
        float4 v = *(const float4*)(W1 + r * 128 + c4);
        *(float4*)(smb + OFF_W1 + kmaj_off(r, c4)) = v;
    }
    if (tid < 128) { sb1[tid] = b1[tid]; sW2[tid] = W2[tid]; }

#if USE_TCGEN05
    if (warp == 0) { TCGEN05_ALLOC(base + OFF_TMEMPTR, 512); TCGEN05_RELINQ(); }
    if (tid == 0)  { MBARRIER_INIT(base + OFF_MBAR, 1); }
#endif

    const int STR = gridDim.x;
    int tile = blockIdx.x;
    if (tile >= NTILES) return;

    // ---- Stage-C register carries (current + deferred copies) -------------
    float c_xv = 0.f, c_lb = 0.f, c_ub = 0.f;
    float c_z1m = 0.f, c_z2m = 0.f, c_iD1 = 0.f, c_iD2 = 0.f;
    float p_xv = 0.f, p_lb = 0.f, p_ub = 0.f;
    float p_z1m = 0.f, p_z2m = 0.f, p_iD1 = 0.f, p_iD2 = 0.f;
    int tile_prev = -1;

    // ---- prologue: F(t0) + carries ----------------------------------------
    {
        const int row = tile * TILE + r256;
        const float mu = muB[tile >> 3];
        float a1 = x1[row], a2 = x2[row], v1 = z1[row], v2 = z2[row];
        float xv = x[row];
        float z1m = (v1 + mu <= 0.0f) ? 0.0f : v1;
        float z2m = (v2 + mu <= 0.0f) ? 0.0f : v2;
        if (half == 0) {
            c_xv = xv; c_lb = lb[row]; c_ub = ub[row];
            *(float4*)(smb + fb + kmaj_off(rr, 0)) = make_float4(xv, a1, a2, z1m);
            *(float4*)(smb + fb + kmaj_off(rr, 4)) = make_float4(z2m, x1E[row], x2E[row], z1E[row]);
        } else {
            float iD1 = fminf(fmaxf(__fdividef(z1m + mu, a1 + mu + 1e-12f), 0.0f), 100.0f);
            float iD2 = fminf(fmaxf(__fdividef(z2m + mu, a2 + mu + 1e-12f), 0.0f), 100.0f);
            c_xv = xv; c_z1m = z1m; c_z2m = z2m; c_iD1 = iD1; c_iD2 = iD2;
            *(float4*)(smb + fb + kmaj_off(rr, 8))  = make_float4(z2E[row], mu, iD1, iD2);
            *(float4*)(smb + fb + kmaj_off(rr, 12)) = make_float4(1.0f, 0.0f, 0.0f, 0.0f);
        }
    }

#if USE_TCGEN05
    uint32_t tmem;
    FENCE_PROXY_ASYNC(); __syncthreads();
    asm volatile("ld.shared.b32 %0, [%1];" : "=r"(tmem) : "r"(base + OFF_TMEMPTR));

    const uint64_t fdA = DESC_BASE_SW128 | ((uint64_t)((base + OFF_F)          >> 4) & 0x3FFF);
    const uint64_t fdB = DESC_BASE_SW128 | ((uint64_t)((base + OFF_F + 16384u) >> 4) & 0x3FFF);
    const uint64_t wd  = DESC_BASE_SW128 | ((uint64_t)((base + OFF_WIHB)       >> 4) & 0x3FFF);
    const uint64_t hd  = DESC_BASE_SW128 | ((uint64_t)((base + OFF_H)          >> 4) & 0x3FFF);
    const uint64_t w1d = DESC_BASE_SW128 | ((uint64_t)((base + OFF_W1)         >> 4) & 0x3FFF);

    const int sp = warp & 3, qu = warp >> 2;
    const int trow = sp * 32 + lane;

    // ---- prologue commit: MMA1(A_t0) -> gate cols 0..383 ------------------
    if (warp == 0 && elect_one_pred()) {
        #pragma unroll
        for (int nb = 0; nb < 3; ++nb)
            #pragma unroll
            for (int s = 0; s < 2; ++s)
                mma_tf32_ss(tmem + nb * 128, fdA + s * 2, wd + nb * 1024u + s * 2,
                            IDESC_TF32, s > 0);
        TCGEN05_COMMIT(base + OFF_MBAR);
    }
    MBARRIER_WAIT_PARITY(base + OFF_MBAR, 0);
    TCGEN05_FENCE_AFTER();
    // gate-epi(A_t0) -> H
    #pragma unroll
    for (int hh = 0; hh < 2; ++hh) {
        const int c = qu * 32 + hh * 16;
        uint32_t vi[16], vg[16], vo[16];
        TCGEN05_LD_32X32B_X16(vi, tmem + c);
        TCGEN05_LD_32X32B_X16(vg, tmem + 128 + c);
        TCGEN05_LD_32X32B_X16(vo, tmem + 256 + c);
        TCGEN05_WAIT_LD();
        #pragma unroll
        for (int u = 0; u < 4; ++u) {
            float4 hv;
            hv.x = lstm_h(__uint_as_float(vi[4*u+0]), __uint_as_float(vg[4*u+0]), __uint_as_float(vo[4*u+0]));
            hv.y = lstm_h(__uint_as_float(vi[4*u+1]), __uint_as_float(vg[4*u+1]), __uint_as_float(vo[4*u+1]));
            hv.z = lstm_h(__uint_as_float(vi[4*u+2]), __uint_as_float(vg[4*u+2]), __uint_as_float(vo[4*u+2]));
            hv.w = lstm_h(__uint_as_float(vi[4*u+3]), __uint_as_float(vg[4*u+3]), __uint_as_float(vo[4*u+3]));
            *(float4*)(smb + OFF_H + kmaj_off(trow, c + 4 * u)) = hv;
        }
    }
    TCGEN05_FENCE_BEFORE();
    FENCE_PROXY_ASYNC();
    __syncthreads();

    // ---- steady-state: 2 commits per tile; Stage C split fills both waits -
    for (; tile < NTILES; tile += STR) {
        const int next = tile + STR;
        const bool hn = next < NTILES;

        // ---- commit C1: MMA2(A) -> 384..511  +  MMA1(B) -> 0..383 ---------
        if (warp == 0 && elect_one_pred()) {
            #pragma unroll
            for (int s = 0; s < 16; ++s) {
                uint32_t off = (uint32_t)(s >> 2) * 1024u + (uint32_t)(s & 3) * 2u;
                mma_tf32_ss(tmem + 384, hd + off, w1d + off, IDESC_TF32, s > 0);
            }
            #pragma unroll
            for (int nb = 0; nb < 3; ++nb)
                #pragma unroll
                for (int s = 0; s < 2; ++s)
                    mma_tf32_ss(tmem + nb * 128, fdB + s * 2, wd + nb * 1024u + s * 2,
                                IDESC_TF32, s > 0);
            TCGEN05_COMMIT(base + OFF_MBAR);
        }

        // ---- deferred Stage C: B-rows of previous tile (fills C1 wait) ----
        if (tile_prev >= 0 && !rowA) {
            float psum = sPart[512 + rr] + sPart[512 + 128 + rr]
                       + sPart[512 + 256 + rr] + sPart[512 + 384 + rr];
            float p  = fabsf(psum + b2v);
            float d  = -p * p_xv;
            float xn = p_xv + d;
            const int bI = tile_prev >> 3;
            const int n  = (tile_prev & 7) * TILE + r256;
            size_t ob = (size_t)bI * (5 * NDIM) + n;
            if (half == 0) {
                out[ob]            = xn;
                out[ob +     NDIM] = xn - p_lb;
                out[ob + 2 * NDIM] = p_ub - xn;
            } else {
                out[ob + 3 * NDIM] = p_z1m - p_iD1 * (d + p_z1m);
                out[ob + 4 * NDIM] = p_z2m - p_iD2 * (-d + p_z2m);
            }
        }

        // ---- prefetch next tile's inputs (fills rest of C1 wait) ----------
        float n_x1 = 0.f, n_x2 = 0.f, n_z1 = 0.f, n_z2 = 0.f, n_xv = 0.f, n_mu = 0.f;
        float n_e1 = 0.f, n_e2 = 0.f, n_e3 = 0.f, n_e4 = 0.f, n_lb = 0.f, n_ub = 0.f;
        if (hn) {
            const int row = next * TILE + r256;
            n_mu = muB[next >> 3];
            n_x1 = x1[row]; n_x2 = x2[row]; n_z1 = z1[row]; n_z2 = z2[row];
            n_xv = x[row];
            if (half == 0) {
                n_e1 = x1E[row]; n_e2 = x2E[row]; n_e3 = z1E[row];
                n_lb = lb[row];  n_ub = ub[row];
            } else {
                n_e4 = z2E[row];
            }
        }
        float n_z1m = 0.f, n_z2m = 0.f, n_iD1 = 0.f, n_iD2 = 0.f;

        MBARRIER_WAIT_PARITY(base + OFF_MBAR, 1);
        TCGEN05_FENCE_AFTER();

        // ---- gate-epi(B) -> H  (H free: MMA2(A) done) ---------------------
        #pragma unroll
        for (int hh = 0; hh < 2; ++hh) {
            const int c = qu * 32 + hh * 16;
            uint32_t vi[16], vg[16], vo[16];
            TCGEN05_LD_32X32B_X16(vi, tmem + c);
            TCGEN05_LD_32X32B_X16(vg, tmem + 128 + c);
            TCGEN05_LD_32X32B_X16(vo, tmem + 256 + c);
            TCGEN05_WAIT_LD();
            #pragma unroll
            for (int u = 0; u < 4; ++u) {
                float4 hv;
                hv.x = lstm_h(__uint_as_float(vi[4*u+0]), __uint_as_float(vg[4*u+0]), __uint_as_float(vo[4*u+0]));
                hv.y = lstm_h(__uint_as_float(vi[4*u+1]), __uint_as_float(vg[4*u+1]), __uint_as_float(vo[4*u+1]));
                hv.z = lstm_h(__uint_as_float(vi[4*u+2]), __uint_as_float(vg[4*u+2]), __uint_as_float(vo[4*u+2]));
                hv.w = lstm_h(__uint_as_float(vi[4*u+3]), __uint_as_float(vg[4*u+3]), __uint_as_float(vo[4*u+3]));
                *(float4*)(smb + OFF_H + kmaj_off(trow, c + 4 * u)) = hv;
            }
        }
        // ---- head-epi(A) -> sPart[0..511] ---------------------------------
        {
            const int cb = qu * 32;
            uint32_t d0[32];
            TCGEN05_LD_32X32B_X32(d0, tmem + 384 + cb);
            TCGEN05_WAIT_LD();
            float s = 0.0f;
            #pragma unroll
            for (int r = 0; r < 32; ++r)
                s = fmaf(fmaxf(__uint_as_float(d0[r]) + sb1[cb + r], 0.0f), sW2[cb + r], s);
            sPart[qu * 128 + trow] = s;
        }
        // ---- store F(next)  (F free: MMA1(B) done) ------------------------
        if (hn) {
            n_z1m = (n_z1 + n_mu <= 0.0f) ? 0.0f : n_z1;
            n_z2m = (n_z2 + n_mu <= 0.0f) ? 0.0f : n_z2;
            if (half == 0) {
                *(float4*)(smb + fb + kmaj_off(rr, 0)) = make_float4(n_xv, n_x1, n_x2, n_z1m);
                *(float4*)(smb + fb + kmaj_off(rr, 4)) = make_float4(n_z2m, n_e1, n_e2, n_e3);
            } else {
                n_iD1 = fminf(fmaxf(__fdividef(n_z1m + n_mu, n_x1 + n_mu + 1e-12f), 0.0f), 100.0f);
                n_iD2 = fminf(fmaxf(__fdividef(n_z2m + n_mu, n_x2 + n_mu + 1e-12f), 0.0f), 100.0f);
                *(float4*)(smb + fb + kmaj_off(rr, 8))  = make_float4(n_e4, n_mu, n_iD1, n_iD2);
                *(float4*)(smb + fb + kmaj_off(rr, 12)) = make_float4(1.0f, 0.0f, 0.0f, 0.0f);
            }
        }
        TCGEN05_FENCE_BEFORE();
        FENCE_PROXY_ASYNC();
        __syncthreads();

        // ---- commit C2: MMA2(B) -> 384..511  + (hn) MMA1(A_next) ----------
        if (warp == 0 && elect_one_pred()) {
            #pragma unroll
            for (int s = 0; s < 16; ++s) {
                uint32_t off = (uint32_t)(s >> 2) * 1024u + (uint32_t)(s & 3) * 2u;
                mma_tf32_ss(tmem + 384, hd + off, w1d + off, IDESC_TF32, s > 0);
            }
            if (hn) {
                #pragma unroll
                for (int nb = 0; nb < 3; ++nb)
                    #pragma unroll
                    for (int s = 0; s < 2; ++s)
                        mma_tf32_ss(tmem + nb * 128, fdA + s * 2, wd + nb * 1024u + s * 2,
                                    IDESC_TF32, s > 0);
            }
            TCGEN05_COMMIT(base + OFF_MBAR);
        }

        // ---- Stage C: A-rows of current tile (fills C2 wait) --------------
        if (rowA) {
            float psum = sPart[rr] + sPart[128 + rr] + sPart[256 + rr] + sPart[384 + rr];
            float p  = fabsf(psum + b2v);
            float d  = -p * c_xv;
            float xn = c_xv + d;
            const int bI = tile >> 3;
            const int n  = (tile & 7) * TILE + r256;
            size_t ob = (size_t)bI * (5 * NDIM) + n;
            if (half == 0) {
                out[ob]            = xn;
                out[ob +     NDIM] = xn - c_lb;
                out[ob + 2 * NDIM] = c_ub - xn;
            } else {
                out[ob + 3 * NDIM] = c_z1m - c_iD1 * (d + c_z1m);
                out[ob + 4 * NDIM] = c_z2m - c_iD2 * (-d + c_z2m);
            }
        }

        MBARRIER_WAIT_PARITY(base + OFF_MBAR, 0);
        TCGEN05_FENCE_AFTER();

        // ---- head-epi(B) -> sPart[512..1023] ------------------------------
        {
            const int cb = qu * 32;
            uint32_t d0[32];
            TCGEN05_LD_32X32B_X32(d0, tmem + 384 + cb);
            TCGEN05_WAIT_LD();
            float s = 0.0f;
            #pragma unroll
            for (int r = 0; r < 32; ++r)
                s = fmaf(fmaxf(__uint_as_float(d0[r]) + sb1[cb + r], 0.0f), sW2[cb + r], s);
            sPart[512 + qu * 128 + trow] = s;
        }
        // ---- gate-epi(A_next) -> H  (H free: MMA2(B) done) ----------------
        if (hn) {
            #pragma unroll
            for (int hh = 0; hh < 2; ++hh) {
                const int c = qu * 32 + hh * 16;
                uint32_t vi[16], vg[16], vo[16];
                TCGEN05_LD_32X32B_X16(vi, tmem + c);
                TCGEN05_LD_32X32B_X16(vg, tmem + 128 + c);
                TCGEN05_LD_32X32B_X16(vo, tmem + 256 + c);
                TCGEN05_WAIT_LD();
                #pragma unroll
                for (int u = 0; u < 4; ++u) {
                    float4 hv;
                    hv.x = lstm_h(__uint_as_float(vi[4*u+0]), __uint_as_float(vg[4*u+0]), __uint_as_float(vo[4*u+0]));
                    hv.y = lstm_h(__uint_as_float(vi[4*u+1]), __uint_as_float(vg[4*u+1]), __uint_as_float(vo[4*u+1]));
                    hv.z = lstm_h(__uint_as_float(vi[4*u+2]), __uint_as_float(vg[4*u+2]), __uint_as_float(vo[4*u+2]));
                    hv.w = lstm_h(__uint_as_float(vi[4*u+3]), __uint_as_float(vg[4*u+3]), __uint_as_float(vo[4*u+3]));
                    *(float4*)(smb + OFF_H + kmaj_off(trow, c + 4 * u)) = hv;
                }
            }
        }
        TCGEN05_FENCE_BEFORE();
        FENCE_PROXY_ASYNC();
        __syncthreads();   // sPart(B) + H(A_next) visible before next iter

        // ---- rotate carries: current -> deferred, next -> current ---------
        tile_prev = tile;
        p_xv = c_xv; p_lb = c_lb; p_ub = c_ub;
        p_z1m = c_z1m; p_z2m = c_z2m; p_iD1 = c_iD1; p_iD2 = c_iD2;
        c_xv = n_xv; c_lb = n_lb; c_ub = n_ub;
        c_z1m = n_z1m; c_z2m = n_z2m; c_iD1 = n_iD1; c_iD2 = n_iD2;
    }

    // ---- flush: deferred B-rows Stage C of the last tile ------------------
    if (tile_prev >= 0 && !rowA) {
        float psum = sPart[512 + rr] + sPart[512 + 128 + rr]
                   + sPart[512 + 256 + rr] + sPart[512 + 384 + rr];
        float p  = fabsf(psum + b2v);
        float d  = -p * p_xv;
        float xn = p_xv + d;
        const int bI = tile_prev >> 3;
        const int n  = (tile_prev & 7) * TILE + r256;
        size_t ob = (size_t)bI * (5 * NDIM) + n;
        if (half == 0) {
            out[ob]            = xn;
            out[ob +     NDIM] = xn - p_lb;
            out[ob + 2 * NDIM] = p_ub - xn;
        } else {
            out[ob + 3 * NDIM] = p_z1m - p_iD1 * (d + p_z1m);
            out[ob + 4 * NDIM] = p_z2m - p_iD2 * (-d + p_z2m);
        }
    }

    if (tid == 0) MBARRIER_INVAL(base + OFF_MBAR);
    if (warp == 0) TCGEN05_DEALLOC(tmem, 512);
#else
    // ---- PTX-pass fallback (compiles only; cubin path runs on GB300) ------
    __syncthreads();
    for (; tile < NTILES; tile += STR) {
        __syncthreads();
        for (int t = 0; t < 2; ++t) {
            if (tid < 128) {
                const int r = tid;
                const uint32_t fbl = (uint32_t)OFF_F + (uint32_t)t * 16384u;
                float f[13];
                #pragma unroll
                for (int k = 0; k < 13; ++k)
                    f[k] = *(const float*)(smb + fbl + kmaj_off(r, k));
                for (int j = 0; j < 128; ++j) {
                    float a[3];
                    #pragma unroll
                    for (int gidx = 0; gidx < 3; ++gidx) {
                        uint32_t blk = (uint32_t)gidx * 16384u + (uint32_t)OFF_WIHB;
                        float acc = 0.0f;
                        #pragma unroll
                        for (int k = 0; k < 13; ++k)
                            acc = fmaf(f[k], *(const float*)(smb + blk + kmaj_off(j, k)), acc);
                        a[gidx] = acc;
                    }
                    *(float*)(smb + OFF_H + kmaj_off(r, j)) = lstm_h(a[0], a[1], a[2]);
                }
            }
            __syncthreads();
            if (tid < 128) {
                const int r = tid;
                float s = 0.0f;
                for (int j = 0; j < 128; ++j) {
                    float acc = sb1[j];
                    #pragma unroll 8
                    for (int k4 = 0; k4 < 32; ++k4) {
                        const float4 hv = *(const float4*)(smb + OFF_H  + kmaj_off(r, 4 * k4));
                        const float4 wv = *(const float4*)(smb + OFF_W1 + kmaj_off(j, 4 * k4));
                        acc = fmaf(hv.x, wv.x, fmaf(hv.y, wv.y, fmaf(hv.z, wv.z, fmaf(hv.w, wv.w, acc))));
                    }
                    s = fmaf(fmaxf(acc, 0.0f), sW2[j], s);
                }
                sPart[t * 512 + r] = s;
                sPart[t * 512 + 128 + r] = 0.0f;
                sPart[t * 512 + 256 + r] = 0.0f;
                sPart[t * 512 + 384 + r] = 0.0f;
            }
            __syncthreads();
        }
        {
            const int tq = r256 >> 7;
            float psum = sPart[tq * 512 + rr] + sPart[tq * 512 + 128 + rr]
                       + sPart[tq * 512 + 256 + rr] + sPart[tq * 512 + 384 + rr];
            float p  = fabsf(psum + b2v);
            float d  = -p * c_xv;
            float xn = c_xv + d;
            const int bI = tile >> 3;
            const int n  = (tile & 7) * TILE + r256;
            size_t ob = (size_t)bI * (5 * NDIM) + n;
            if (half == 0) {
                out[ob]            = xn;
                out[ob +     NDIM] = xn - c_lb;
                out[ob + 2 * NDIM] = c_ub - xn;
            } else {
                out[ob + 3 * NDIM] = c_z1m - c_iD1 * (d + c_z1m);
                out[ob + 4 * NDIM] = c_z2m - c_iD2 * (-d + c_z2m);
            }
        }
        __syncthreads();
        const int next = tile + STR;
        if (next < NTILES) {
            const int row = next * TILE + r256;
            const float mu = muB[next >> 3];
            float a1 = x1[row], a2 = x2[row], v1 = z1[row], v2 = z2[row];
            float xv = x[row];
            float z1m = (v1 + mu <= 0.0f) ? 0.0f : v1;
            float z2m = (v2 + mu <= 0.0f) ? 0.0f : v2;
            if (half == 0) {
                c_xv = xv; c_lb = lb[row]; c_ub = ub[row];
                *(float4*)(smb + fb + kmaj_off(rr, 0)) = make_float4(xv, a1, a2, z1m);
                *(float4*)(smb + fb + kmaj_off(rr, 4)) = make_float4(z2m, x1E[row], x2E[row], z1E[row]);
            } else {
                float iD1 = fminf(fmaxf(__fdividef(z1m + mu, a1 + mu + 1e-12f), 0.0f), 100.0f);
                float iD2 = fminf(fmaxf(__fdividef(z2m + mu, a2 + mu + 1e-12f), 0.0f), 100.0f);
                c_xv = xv; c_z1m = z1m; c_z2m = z2m; c_iD1 = iD1; c_iD2 = iD2;
                *(float4*)(smb + fb + kmaj_off(rr, 8))  = make_float4(z2E[row], mu, iD1, iD2);
                *(float4*)(smb + fb + kmaj_off(rr, 12)) = make_float4(1.0f, 0.0f, 0.0f, 0.0f);
            }
        }
        __syncthreads();
    }
#endif
}

// ---------------------------------------------------------------------------
// metadata order:
//  0 x  1 x1  2 x2  3 z1  4 z2  5 x1E  6 x2E  7 z1E  8 z2E  9 muB  10 lb 11 ub
// 12 has_lb 13 has_ub 14 W_ih 15 W_hh(unused) 16 b_ih 17 b_hh 18 W1 19 b1 20 W2 21 b2
// ---------------------------------------------------------------------------
extern "C" void kernel_launch(void* const* d_in, const int* in_sizes, int n_in,
                              void* d_out, int out_size) {
    (void)in_sizes; (void)n_in; (void)out_size;
    const float* x    = (const float*)d_in[0];
    const float* x1   = (const float*)d_in[1];
    const float* x2   = (const float*)d_in[2];
    const float* z1   = (const float*)d_in[3];
    const float* z2   = (const float*)d_in[4];
    const float* x1E  = (const float*)d_in[5];
    const float* x2E  = (const float*)d_in[6];
    const float* z1E  = (const float*)d_in[7];
    const float* z2E  = (const float*)d_in[8];
    const float* muB  = (const float*)d_in[9];
    const float* lb   = (const float*)d_in[10];
    const float* ub   = (const float*)d_in[11];
    const float* W_ih = (const float*)d_in[14];
    const float* b_ih = (const float*)d_in[16];
    const float* b_hh = (const float*)d_in[17];
    const float* W1   = (const float*)d_in[18];
    const float* b1   = (const float*)d_in[19];
    const float* W2   = (const float*)d_in[20];
    const float* b2   = (const float*)d_in[21];

    cudaFuncSetAttribute(ps_lstm_kernel, cudaFuncAttributeMaxDynamicSharedMemorySize, SMEM_BYTES);

    int dev = 0, nsm = 0;
    cudaGetDevice(&dev);
    cudaDeviceGetAttribute(&nsm, cudaDevAttrMultiProcessorCount, dev);
    if (nsm <= 0) nsm = 148;
    if (nsm > NTILES) nsm = NTILES;

    ps_lstm_kernel<<<nsm, NTH, SMEM_BYTES>>>(
        x, x1, x2, z1, z2, x1E, x2E, z1E, z2E, muB, lb, ub,
        W_ih, b_ih, b_hh, W1, b1, W2, b2, (float*)d_out);
}